// round 1
// baseline (speedup 1.0000x reference)
#include <cuda_runtime.h>
#include <math_constants.h>

// Problem constants (fixed by reference)
#define Bv 4
#define Sv 2048
#define Ev 1024
#define Hv 16
#define HDv 64
#define NKB (Sv / 64)        // 32 key blocks of 64
#define ATT_SCALE 0.125f     // 1/sqrt(64)

// Scratch (static device memory — allocation-free per harness rules)
__device__ float g_Q[(size_t)Bv * Sv * Ev];
__device__ float g_K[(size_t)Bv * Sv * Ev];
__device__ float g_V[(size_t)Bv * Sv * Ev];
__device__ float g_O[(size_t)Bv * Sv * Ev];

// ---------------------------------------------------------------------------
// GEMM: C[M,N] = A[M,K] * W[N,K]^T (+ bias), fp32 SIMT.
// 128x128 tile, BK=16, 256 threads, 8x8 micro-tile.
// ---------------------------------------------------------------------------
__global__ __launch_bounds__(256, 2)
void gemm_nt_kernel(const float* __restrict__ A, const float* __restrict__ W,
                    const float* __restrict__ bias, float* __restrict__ C,
                    int M, int N, int K)
{
    __shared__ float As[16][132];
    __shared__ float Ws[16][132];

    const int tid = threadIdx.x;
    const int tx = tid & 15;       // 0..15 -> output cols
    const int ty = tid >> 4;       // 0..15 -> output rows
    const int m0 = blockIdx.y << 7;
    const int n0 = blockIdx.x << 7;

    const int lrow = tid >> 2;          // 0..63
    const int lk   = (tid & 3) << 2;    // 0,4,8,12

    float acc[8][8];
#pragma unroll
    for (int i = 0; i < 8; ++i)
#pragma unroll
        for (int j = 0; j < 8; ++j) acc[i][j] = 0.f;

    for (int k0 = 0; k0 < K; k0 += 16) {
#pragma unroll
        for (int hh = 0; hh < 2; ++hh) {
            int row = lrow + (hh << 6);
            float4 av = *reinterpret_cast<const float4*>(
                &A[(size_t)(m0 + row) * K + k0 + lk]);
            As[lk + 0][row] = av.x; As[lk + 1][row] = av.y;
            As[lk + 2][row] = av.z; As[lk + 3][row] = av.w;
            float4 wv = *reinterpret_cast<const float4*>(
                &W[(size_t)(n0 + row) * K + k0 + lk]);
            Ws[lk + 0][row] = wv.x; Ws[lk + 1][row] = wv.y;
            Ws[lk + 2][row] = wv.z; Ws[lk + 3][row] = wv.w;
        }
        __syncthreads();
#pragma unroll
        for (int kk = 0; kk < 16; ++kk) {
            float a[8], b[8];
#pragma unroll
            for (int i = 0; i < 8; ++i) a[i] = As[kk][ty * 8 + i];
#pragma unroll
            for (int j = 0; j < 8; ++j) b[j] = Ws[kk][tx * 8 + j];
#pragma unroll
            for (int i = 0; i < 8; ++i)
#pragma unroll
                for (int j = 0; j < 8; ++j)
                    acc[i][j] = fmaf(a[i], b[j], acc[i][j]);
        }
        __syncthreads();
    }

#pragma unroll
    for (int i = 0; i < 8; ++i) {
        const int m = m0 + ty * 8 + i;
        float* cp = &C[(size_t)m * N + n0 + tx * 8];
#pragma unroll
        for (int j = 0; j < 8; ++j) {
            float v = acc[i][j];
            if (bias) v += bias[n0 + tx * 8 + j];
            cp[j] = v;
        }
    }
}

// ---------------------------------------------------------------------------
// Flash attention (reproducing the reference's buggy l update):
//   per key block: m_new = max(m, rowmax); corr = exp(m - m_new)
//   P = exp(S*scale - m_new); cs = rowsum(P)
//   l = cs*corr + cs            <-- BUG preserved (no accumulation of l)
//   acc = acc*corr + P @ V
// final: O = acc / l
//
// One block handles 128 query rows of one (b,h). 256 threads.
// ---------------------------------------------------------------------------
__global__ __launch_bounds__(256, 2)
void attn_kernel(const float* __restrict__ Q, const float* __restrict__ K,
                 const float* __restrict__ V, float* __restrict__ O)
{
    extern __shared__ float sm[];
    float* Qs = sm;                      // [128][65]
    float* Ks = Qs + 128 * 65;           // [64][65]
    float* Vs = Ks + 64 * 65;            // [64][65]
    float* Ps = Vs + 64 * 65;            // [128][65]
    float* ms = Ps + 128 * 65;           // [128]
    float* ls = ms + 128;                // [128]
    float* cs = ls + 128;                // [128]

    const int tid = threadIdx.x;
    const int b  = blockIdx.x >> 4;
    const int h  = blockIdx.x & 15;
    const int q0 = blockIdx.y << 7;

    const float* Qb = Q + ((size_t)b * Sv + q0) * Ev + h * HDv;
    const float* Kb = K + (size_t)b * Sv * Ev + h * HDv;
    const float* Vb = V + (size_t)b * Sv * Ev + h * HDv;

    // Load 128x64 Q tile (coalesced float4 along head dim)
    for (int i = tid; i < 128 * 16; i += 256) {
        const int row = i >> 4;
        const int d   = (i & 15) << 2;
        float4 v = *reinterpret_cast<const float4*>(&Qb[(size_t)row * Ev + d]);
        Qs[row * 65 + d + 0] = v.x; Qs[row * 65 + d + 1] = v.y;
        Qs[row * 65 + d + 2] = v.z; Qs[row * 65 + d + 3] = v.w;
    }
    if (tid < 128) ms[tid] = -CUDART_INF_F;

    const int tx = tid & 15;     // 0..15
    const int ty = tid >> 4;     // 0..15
    const int r0 = ty << 3;      // 8 query rows per thread
    const int c0 = tx << 2;      // 4 cols per thread (keys / head dims)

    float acc[8][4];
#pragma unroll
    for (int i = 0; i < 8; ++i)
#pragma unroll
        for (int j = 0; j < 4; ++j) acc[i][j] = 0.f;

    for (int kb = 0; kb < NKB; ++kb) {
        const float* Kp = Kb + (size_t)(kb * 64) * Ev;
        const float* Vp = Vb + (size_t)(kb * 64) * Ev;

        // Load 64x64 K and V tiles
        for (int i = tid; i < 64 * 16; i += 256) {
            const int row = i >> 4;
            const int d   = (i & 15) << 2;
            float4 kv = *reinterpret_cast<const float4*>(&Kp[(size_t)row * Ev + d]);
            Ks[row * 65 + d + 0] = kv.x; Ks[row * 65 + d + 1] = kv.y;
            Ks[row * 65 + d + 2] = kv.z; Ks[row * 65 + d + 3] = kv.w;
            float4 vv = *reinterpret_cast<const float4*>(&Vp[(size_t)row * Ev + d]);
            Vs[row * 65 + d + 0] = vv.x; Vs[row * 65 + d + 1] = vv.y;
            Vs[row * 65 + d + 2] = vv.z; Vs[row * 65 + d + 3] = vv.w;
        }
        __syncthreads();   // K/V (and, first iter, Q + ms) visible

        // Scores: S[128][64] = Q_tile @ K_blk^T, 8x4 micro per thread
        float s[8][4];
#pragma unroll
        for (int i = 0; i < 8; ++i)
#pragma unroll
            for (int j = 0; j < 4; ++j) s[i][j] = 0.f;

#pragma unroll 16
        for (int kk = 0; kk < 64; ++kk) {
            float qv[8], kv[4];
#pragma unroll
            for (int i = 0; i < 8; ++i) qv[i] = Qs[(r0 + i) * 65 + kk];
#pragma unroll
            for (int j = 0; j < 4; ++j) kv[j] = Ks[(c0 + j) * 65 + kk];
#pragma unroll
            for (int i = 0; i < 8; ++i)
#pragma unroll
                for (int j = 0; j < 4; ++j)
                    s[i][j] = fmaf(qv[i], kv[j], s[i][j]);
        }
#pragma unroll
        for (int i = 0; i < 8; ++i)
#pragma unroll
            for (int j = 0; j < 4; ++j)
                Ps[(r0 + i) * 65 + c0 + j] = s[i][j] * ATT_SCALE;
        __syncthreads();

        // Row-wise online softmax bookkeeping (one thread per query row)
        if (tid < 128) {
            float mx = -CUDART_INF_F;
#pragma unroll 8
            for (int k = 0; k < 64; ++k) mx = fmaxf(mx, Ps[tid * 65 + k]);
            const float mo = ms[tid];
            const float mn = fmaxf(mo, mx);
            const float co = __expf(mo - mn);
            float sum = 0.f;
#pragma unroll 8
            for (int k = 0; k < 64; ++k) {
                float e = __expf(Ps[tid * 65 + k] - mn);
                Ps[tid * 65 + k] = e;
                sum += e;
            }
            ls[tid] = sum * co + sum;   // BUG preserved from reference
            ms[tid] = mn;
            cs[tid] = co;
        }
        __syncthreads();

        // acc = acc*corr + P @ V_blk
        float cr[8];
#pragma unroll
        for (int i = 0; i < 8; ++i) cr[i] = cs[r0 + i];
#pragma unroll
        for (int i = 0; i < 8; ++i)
#pragma unroll
            for (int j = 0; j < 4; ++j) acc[i][j] *= cr[i];

#pragma unroll 16
        for (int kk = 0; kk < 64; ++kk) {
            float p[8], vv[4];
#pragma unroll
            for (int i = 0; i < 8; ++i) p[i] = Ps[(r0 + i) * 65 + kk];
#pragma unroll
            for (int j = 0; j < 4; ++j) vv[j] = Vs[kk * 65 + c0 + j];
#pragma unroll
            for (int i = 0; i < 8; ++i)
#pragma unroll
                for (int j = 0; j < 4; ++j)
                    acc[i][j] = fmaf(p[i], vv[j], acc[i][j]);
        }
        __syncthreads();   // protect Ks/Vs/Ps before next iteration
    }

    // O = acc / l  (merge heads: [B,S,E] layout)
    float* Ob = O + ((size_t)b * Sv + q0) * Ev + h * HDv;
#pragma unroll
    for (int i = 0; i < 8; ++i) {
        const float inv = 1.f / ls[r0 + i];
#pragma unroll
        for (int j = 0; j < 4; ++j)
            Ob[(size_t)(r0 + i) * Ev + c0 + j] = acc[i][j] * inv;
    }
}

// ---------------------------------------------------------------------------
extern "C" void kernel_launch(void* const* d_in, const int* in_sizes, int n_in,
                              void* d_out, int out_size)
{
    const float* x  = (const float*)d_in[0];
    const float* qw = (const float*)d_in[1];
    const float* kw = (const float*)d_in[2];
    const float* vw = (const float*)d_in[3];
    const float* ow = (const float*)d_in[4];
    const float* ob = (const float*)d_in[5];
    float* out = (float*)d_out;

    float *Qg, *Kg, *Vg, *Og;
    cudaGetSymbolAddress((void**)&Qg, g_Q);
    cudaGetSymbolAddress((void**)&Kg, g_K);
    cudaGetSymbolAddress((void**)&Vg, g_V);
    cudaGetSymbolAddress((void**)&Og, g_O);

    const int M = Bv * Sv;   // 8192
    const dim3 gblk(256);
    const dim3 ggrid(Ev / 128, M / 128);   // (8, 64)

    gemm_nt_kernel<<<ggrid, gblk>>>(x, qw, nullptr, Qg, M, Ev, Ev);
    gemm_nt_kernel<<<ggrid, gblk>>>(x, kw, nullptr, Kg, M, Ev, Ev);
    gemm_nt_kernel<<<ggrid, gblk>>>(x, vw, nullptr, Vg, M, Ev, Ev);

    const size_t smem = (size_t)(128 * 65 + 64 * 65 + 64 * 65 + 128 * 65 + 3 * 128)
                        * sizeof(float);   // ~99 KB
    cudaFuncSetAttribute(attn_kernel,
                         cudaFuncAttributeMaxDynamicSharedMemorySize, (int)smem);
    attn_kernel<<<dim3(Bv * Hv, Sv / 128), 256, smem>>>(Qg, Kg, Vg, Og);

    gemm_nt_kernel<<<ggrid, gblk>>>(Og, ow, ob, out, M, Ev, Ev);
}

// round 2
// speedup vs baseline: 1.0422x; 1.0422x over previous
#include <cuda_runtime.h>
#include <math_constants.h>

// Problem constants (fixed by reference)
#define Bv 4
#define Sv 2048
#define Ev 1024
#define Hv 16
#define HDv 64
#define NKB (Sv / 64)
#define ATT_SCALE 0.125f

typedef unsigned long long u64;

// ---- packed f32x2 helpers (sm_103a FFMA2 path, only reachable via PTX) ----
__device__ __forceinline__ u64 pack2(float lo, float hi) {
    u64 r; asm("mov.b64 %0, {%1, %2};" : "=l"(r) : "f"(lo), "f"(hi)); return r;
}
__device__ __forceinline__ u64 pack_dup(float v) {
    u64 r; asm("mov.b64 %0, {%1, %2};" : "=l"(r) : "f"(v), "f"(v)); return r;
}
__device__ __forceinline__ void unpack2(u64 p, float& lo, float& hi) {
    asm("mov.b64 {%0, %1}, %2;" : "=f"(lo), "=f"(hi) : "l"(p));
}
__device__ __forceinline__ void ffma2(u64& d, u64 a, u64 b) {
    asm("fma.rn.f32x2 %0, %1, %2, %3;" : "=l"(d) : "l"(a), "l"(b), "l"(d));
}
__device__ __forceinline__ u64 fmul2(u64 a, u64 b) {
    u64 r; asm("mul.rn.f32x2 %0, %1, %2;" : "=l"(r) : "l"(a), "l"(b)); return r;
}

// Scratch (static device memory — allocation-free per harness rules)
__device__ float g_Q[(size_t)Bv * Sv * Ev];
__device__ float g_K[(size_t)Bv * Sv * Ev];
__device__ float g_V[(size_t)Bv * Sv * Ev];
__device__ float g_O[(size_t)Bv * Sv * Ev];

// ---------------------------------------------------------------------------
// GEMM: C[M,N] = A[M,K] * W[N,K]^T (+ bias), fp32, FFMA2 inner product.
// 128x128 tile, BK=16, 256 threads, 8x8 micro-tile (as 8x4 packed pairs).
// ---------------------------------------------------------------------------
__global__ __launch_bounds__(256, 2)
void gemm_nt_kernel(const float* __restrict__ A, const float* __restrict__ W,
                    const float* __restrict__ bias, float* __restrict__ C,
                    int M, int N, int K)
{
    __shared__ __align__(16) float As[16][132];
    __shared__ __align__(16) float Ws[16][132];

    const int tid = threadIdx.x;
    const int tx = tid & 15;
    const int ty = tid >> 4;
    const int m0 = blockIdx.y << 7;
    const int n0 = blockIdx.x << 7;

    const int lrow = tid >> 2;
    const int lk   = (tid & 3) << 2;

    u64 acc2[8][4];
#pragma unroll
    for (int i = 0; i < 8; ++i)
#pragma unroll
        for (int j = 0; j < 4; ++j) acc2[i][j] = 0ull;

    for (int k0 = 0; k0 < K; k0 += 16) {
#pragma unroll
        for (int hh = 0; hh < 2; ++hh) {
            int row = lrow + (hh << 6);
            float4 av = *reinterpret_cast<const float4*>(
                &A[(size_t)(m0 + row) * K + k0 + lk]);
            As[lk + 0][row] = av.x; As[lk + 1][row] = av.y;
            As[lk + 2][row] = av.z; As[lk + 3][row] = av.w;
            float4 wv = *reinterpret_cast<const float4*>(
                &W[(size_t)(n0 + row) * K + k0 + lk]);
            Ws[lk + 0][row] = wv.x; Ws[lk + 1][row] = wv.y;
            Ws[lk + 2][row] = wv.z; Ws[lk + 3][row] = wv.w;
        }
        __syncthreads();
#pragma unroll
        for (int kk = 0; kk < 16; ++kk) {
            const u64* wp = reinterpret_cast<const u64*>(&Ws[kk][tx * 8]);
            u64 b2[4];
#pragma unroll
            for (int j = 0; j < 4; ++j) b2[j] = wp[j];
#pragma unroll
            for (int i = 0; i < 8; ++i) {
                u64 a2 = pack_dup(As[kk][ty * 8 + i]);
#pragma unroll
                for (int j = 0; j < 4; ++j) ffma2(acc2[i][j], a2, b2[j]);
            }
        }
        __syncthreads();
    }

#pragma unroll
    for (int i = 0; i < 8; ++i) {
        const int m = m0 + ty * 8 + i;
        float* cp = &C[(size_t)m * N + n0 + tx * 8];
#pragma unroll
        for (int j = 0; j < 4; ++j) {
            float lo, hi;
            unpack2(acc2[i][j], lo, hi);
            if (bias) { lo += bias[n0 + tx * 8 + 2 * j]; hi += bias[n0 + tx * 8 + 2 * j + 1]; }
            cp[2 * j]     = lo;
            cp[2 * j + 1] = hi;
        }
    }
}

// ---------------------------------------------------------------------------
// Flash attention (reference's buggy l update preserved), FFMA2 inner loops.
// Layouts: Qt[d][qrow] (pairs along qrow), Ks[key][d], Vs[key][d],
//          Pt[key][qrow] (pairs along qrow).
// One block = 128 query rows of one (b,h). 256 threads, 8x4 micro as 4x4 pairs.
// ---------------------------------------------------------------------------
#define QT_PAD 130
#define PT_PAD 130
#define KV_PAD 65

__global__ __launch_bounds__(256, 2)
void attn_kernel(const float* __restrict__ Q, const float* __restrict__ K,
                 const float* __restrict__ V, float* __restrict__ O)
{
    extern __shared__ float sm[];
    float* Qt = sm;                         // [64][130]
    float* Ks = Qt + 64 * QT_PAD;           // [64][65]
    float* Vs = Ks + 64 * KV_PAD;           // [64][65]
    float* Pt = Vs + 64 * KV_PAD;           // [64][130]
    float* ms = Pt + 64 * PT_PAD;           // [128]
    float* ls = ms + 128;                   // [128]
    float* cs = ls + 128;                   // [128]

    const int tid = threadIdx.x;
    const int b  = blockIdx.x >> 4;
    const int h  = blockIdx.x & 15;
    const int q0 = blockIdx.y << 7;

    const float* Qb = Q + ((size_t)b * Sv + q0) * Ev + h * HDv;
    const float* Kb = K + (size_t)b * Sv * Ev + h * HDv;
    const float* Vb = V + (size_t)b * Sv * Ev + h * HDv;

    // Load 128x64 Q tile transposed: Qt[d][row]
    for (int i = tid; i < 128 * 16; i += 256) {
        const int row = i >> 4;
        const int d   = (i & 15) << 2;
        float4 v = *reinterpret_cast<const float4*>(&Qb[(size_t)row * Ev + d]);
        Qt[(d + 0) * QT_PAD + row] = v.x;
        Qt[(d + 1) * QT_PAD + row] = v.y;
        Qt[(d + 2) * QT_PAD + row] = v.z;
        Qt[(d + 3) * QT_PAD + row] = v.w;
    }
    if (tid < 128) ms[tid] = -CUDART_INF_F;

    const int tx = tid & 15;     // key/headdim cols
    const int ty = tid >> 4;     // query row group
    const int r0 = ty << 3;      // 8 query rows per thread (4 pairs)
    const int c0 = tx << 2;      // 4 cols per thread

    u64 acc2[4][4];
#pragma unroll
    for (int i = 0; i < 4; ++i)
#pragma unroll
        for (int j = 0; j < 4; ++j) acc2[i][j] = 0ull;

    const u64 scale2 = pack_dup(ATT_SCALE);

    for (int kb = 0; kb < NKB; ++kb) {
        const float* Kp = Kb + (size_t)(kb * 64) * Ev;
        const float* Vp = Vb + (size_t)(kb * 64) * Ev;

        for (int i = tid; i < 64 * 16; i += 256) {
            const int row = i >> 4;
            const int d   = (i & 15) << 2;
            float4 kv = *reinterpret_cast<const float4*>(&Kp[(size_t)row * Ev + d]);
            Ks[row * KV_PAD + d + 0] = kv.x; Ks[row * KV_PAD + d + 1] = kv.y;
            Ks[row * KV_PAD + d + 2] = kv.z; Ks[row * KV_PAD + d + 3] = kv.w;
            float4 vv = *reinterpret_cast<const float4*>(&Vp[(size_t)row * Ev + d]);
            Vs[row * KV_PAD + d + 0] = vv.x; Vs[row * KV_PAD + d + 1] = vv.y;
            Vs[row * KV_PAD + d + 2] = vv.z; Vs[row * KV_PAD + d + 3] = vv.w;
        }
        __syncthreads();

        // Scores: S[q][k] = sum_d Qt[d][q] * Ks[k][d]; pairs packed along q.
        u64 s2[4][4];
#pragma unroll
        for (int i = 0; i < 4; ++i)
#pragma unroll
            for (int j = 0; j < 4; ++j) s2[i][j] = 0ull;

#pragma unroll 8
        for (int kk = 0; kk < 64; ++kk) {
            const u64* qp = reinterpret_cast<const u64*>(&Qt[kk * QT_PAD + r0]);
            u64 q2[4];
#pragma unroll
            for (int i = 0; i < 4; ++i) q2[i] = qp[i];
            u64 k2[4];
#pragma unroll
            for (int j = 0; j < 4; ++j) k2[j] = pack_dup(Ks[(c0 + j) * KV_PAD + kk]);
#pragma unroll
            for (int i = 0; i < 4; ++i)
#pragma unroll
                for (int j = 0; j < 4; ++j)
                    ffma2(s2[i][j], q2[i], k2[j]);
        }
        // Store scaled scores transposed: Pt[key][qrow], pairs contiguous.
#pragma unroll
        for (int j = 0; j < 4; ++j)
#pragma unroll
            for (int i = 0; i < 4; ++i)
                *reinterpret_cast<u64*>(&Pt[(c0 + j) * PT_PAD + r0 + 2 * i]) =
                    fmul2(s2[i][j], scale2);
        __syncthreads();

        // Row-wise online softmax (thread tid handles query row tid)
        if (tid < 128) {
            float mx = -CUDART_INF_F;
#pragma unroll 8
            for (int k = 0; k < 64; ++k) mx = fmaxf(mx, Pt[k * PT_PAD + tid]);
            const float mo = ms[tid];
            const float mn = fmaxf(mo, mx);
            const float co = __expf(mo - mn);
            float sum = 0.f;
#pragma unroll 8
            for (int k = 0; k < 64; ++k) {
                float e = __expf(Pt[k * PT_PAD + tid] - mn);
                Pt[k * PT_PAD + tid] = e;
                sum += e;
            }
            ls[tid] = sum * co + sum;   // BUG preserved from reference
            ms[tid] = mn;
            cs[tid] = co;
        }
        __syncthreads();

        // acc = acc*corr + P @ V ; pairs packed along query rows.
#pragma unroll
        for (int i = 0; i < 4; ++i) {
            const u64 cr2 = pack2(cs[r0 + 2 * i], cs[r0 + 2 * i + 1]);
#pragma unroll
            for (int j = 0; j < 4; ++j) acc2[i][j] = fmul2(acc2[i][j], cr2);
        }

#pragma unroll 8
        for (int kk = 0; kk < 64; ++kk) {
            const u64* pp = reinterpret_cast<const u64*>(&Pt[kk * PT_PAD + r0]);
            u64 p2[4];
#pragma unroll
            for (int i = 0; i < 4; ++i) p2[i] = pp[i];
            u64 v2[4];
#pragma unroll
            for (int j = 0; j < 4; ++j) v2[j] = pack_dup(Vs[kk * KV_PAD + c0 + j]);
#pragma unroll
            for (int i = 0; i < 4; ++i)
#pragma unroll
                for (int j = 0; j < 4; ++j)
                    ffma2(acc2[i][j], p2[i], v2[j]);
        }
        __syncthreads();
    }

    // O = acc / l
    float* Ob = O + ((size_t)b * Sv + q0) * Ev + h * HDv;
#pragma unroll
    for (int i = 0; i < 4; ++i) {
        const float inv_lo = 1.f / ls[r0 + 2 * i];
        const float inv_hi = 1.f / ls[r0 + 2 * i + 1];
#pragma unroll
        for (int j = 0; j < 4; ++j) {
            float lo, hi;
            unpack2(acc2[i][j], lo, hi);
            Ob[(size_t)(r0 + 2 * i) * Ev + c0 + j]     = lo * inv_lo;
            Ob[(size_t)(r0 + 2 * i + 1) * Ev + c0 + j] = hi * inv_hi;
        }
    }
}

// ---------------------------------------------------------------------------
extern "C" void kernel_launch(void* const* d_in, const int* in_sizes, int n_in,
                              void* d_out, int out_size)
{
    const float* x  = (const float*)d_in[0];
    const float* qw = (const float*)d_in[1];
    const float* kw = (const float*)d_in[2];
    const float* vw = (const float*)d_in[3];
    const float* ow = (const float*)d_in[4];
    const float* ob = (const float*)d_in[5];
    float* out = (float*)d_out;

    float *Qg, *Kg, *Vg, *Og;
    cudaGetSymbolAddress((void**)&Qg, g_Q);
    cudaGetSymbolAddress((void**)&Kg, g_K);
    cudaGetSymbolAddress((void**)&Vg, g_V);
    cudaGetSymbolAddress((void**)&Og, g_O);

    const int M = Bv * Sv;   // 8192
    const dim3 gblk(256);
    const dim3 ggrid(Ev / 128, M / 128);

    gemm_nt_kernel<<<ggrid, gblk>>>(x, qw, nullptr, Qg, M, Ev, Ev);
    gemm_nt_kernel<<<ggrid, gblk>>>(x, kw, nullptr, Kg, M, Ev, Ev);
    gemm_nt_kernel<<<ggrid, gblk>>>(x, vw, nullptr, Vg, M, Ev, Ev);

    const size_t smem = (size_t)(64 * QT_PAD + 64 * KV_PAD + 64 * KV_PAD
                                 + 64 * PT_PAD + 3 * 128) * sizeof(float);
    cudaFuncSetAttribute(attn_kernel,
                         cudaFuncAttributeMaxDynamicSharedMemorySize, (int)smem);
    attn_kernel<<<dim3(Bv * Hv, Sv / 128), 256, smem>>>(Qg, Kg, Vg, Og);

    gemm_nt_kernel<<<ggrid, gblk>>>(Og, ow, ob, out, M, Ev, Ev);
}

// round 4
// speedup vs baseline: 1.5172x; 1.4557x over previous
#include <cuda_runtime.h>
#include <cuda_bf16.h>
#include <math_constants.h>
#include <cstdint>

// Problem constants
#define Bv 4
#define Sv 2048
#define Ev 1024
#define Hv 16
#define HDv 64
#define NKB (Sv / 64)
#define ATT_SCALE 0.125f

typedef unsigned long long u64;

// ========================= PTX helpers =====================================
__device__ __forceinline__ uint32_t smem_u32(const void* p) {
    uint32_t a;
    asm("{ .reg .u64 t; cvta.to.shared.u64 t, %1; cvt.u32.u64 %0, t; }"
        : "=r"(a) : "l"(p));
    return a;
}
#define CP_ASYNC16(sa, ga) \
    asm volatile("cp.async.cg.shared.global [%0], [%1], 16;" :: "r"(sa), "l"(ga))
#define CP_COMMIT()  asm volatile("cp.async.commit_group;" ::: "memory")
#define CP_WAIT(n)   asm volatile("cp.async.wait_group %0;" :: "n"(n) : "memory")

__device__ __forceinline__ void ldsm4(uint32_t addr, uint32_t r[4]) {
    asm volatile("ldmatrix.sync.aligned.m8n8.x4.shared.b16 {%0,%1,%2,%3}, [%4];"
                 : "=r"(r[0]), "=r"(r[1]), "=r"(r[2]), "=r"(r[3]) : "r"(addr));
}
__device__ __forceinline__ void mma16816(float c[4], const uint32_t a[4],
                                         const uint32_t b[2]) {
    asm volatile(
        "mma.sync.aligned.m16n8k16.row.col.f32.bf16.bf16.f32 "
        "{%0,%1,%2,%3}, {%4,%5,%6,%7}, {%8,%9}, {%0,%1,%2,%3};"
        : "+f"(c[0]), "+f"(c[1]), "+f"(c[2]), "+f"(c[3])
        : "r"(a[0]), "r"(a[1]), "r"(a[2]), "r"(a[3]), "r"(b[0]), "r"(b[1]));
}

// ---- packed f32x2 helpers (attention kernel) ----
__device__ __forceinline__ u64 pack2(float lo, float hi) {
    u64 r; asm("mov.b64 %0, {%1, %2};" : "=l"(r) : "f"(lo), "f"(hi)); return r;
}
__device__ __forceinline__ u64 pack_dup(float v) {
    u64 r; asm("mov.b64 %0, {%1, %2};" : "=l"(r) : "f"(v), "f"(v)); return r;
}
__device__ __forceinline__ void unpack2(u64 p, float& lo, float& hi) {
    asm("mov.b64 {%0, %1}, %2;" : "=f"(lo), "=f"(hi) : "l"(p));
}
__device__ __forceinline__ void ffma2(u64& d, u64 a, u64 b) {
    asm("fma.rn.f32x2 %0, %1, %2, %3;" : "=l"(d) : "l"(a), "l"(b), "l"(d));
}
__device__ __forceinline__ u64 fmul2(u64 a, u64 b) {
    u64 r; asm("mul.rn.f32x2 %0, %1, %2;" : "=l"(r) : "l"(a), "l"(b)); return r;
}

// ========================= static device scratch ===========================
__device__ float g_Q[(size_t)Bv * Sv * Ev];
__device__ float g_K[(size_t)Bv * Sv * Ev];
__device__ float g_V[(size_t)Bv * Sv * Ev];
__device__ float g_O[(size_t)Bv * Sv * Ev];
__device__ __nv_bfloat16 g_xh[(size_t)Bv * Sv * Ev];
__device__ __nv_bfloat16 g_xl[(size_t)Bv * Sv * Ev];
__device__ __nv_bfloat16 g_oh[(size_t)Bv * Sv * Ev];
__device__ __nv_bfloat16 g_ol[(size_t)Bv * Sv * Ev];
__device__ __nv_bfloat16 g_wh[4][(size_t)Ev * Ev];
__device__ __nv_bfloat16 g_wl[4][(size_t)Ev * Ev];

// ========================= split fp32 -> bf16 hi/lo ========================
__global__ void split_kernel(const float* __restrict__ src,
                             __nv_bfloat16* __restrict__ hi,
                             __nv_bfloat16* __restrict__ lo, int n4)
{
    int i = blockIdx.x * blockDim.x + threadIdx.x;
    if (i >= n4) return;
    float4 v = reinterpret_cast<const float4*>(src)[i];
    float a[4] = {v.x, v.y, v.z, v.w};
    __nv_bfloat16 h[4], l[4];
#pragma unroll
    for (int j = 0; j < 4; ++j) {
        h[j] = __float2bfloat16(a[j]);
        l[j] = __float2bfloat16(a[j] - __bfloat162float(h[j]));
    }
    __nv_bfloat162* hp = reinterpret_cast<__nv_bfloat162*>(hi) + 2 * i;
    __nv_bfloat162* lp = reinterpret_cast<__nv_bfloat162*>(lo) + 2 * i;
    hp[0] = __halves2bfloat162(h[0], h[1]);
    hp[1] = __halves2bfloat162(h[2], h[3]);
    lp[0] = __halves2bfloat162(l[0], l[1]);
    lp[1] = __halves2bfloat162(l[2], l[3]);
}

// ========================= mma.sync GEMM ===================================
// C[M,N] = (Ah+Al)[M,K] * (Bh+Bl)[N,K]^T (+bias), bf16 3-product split,
// fp32 accumulators. 128x128 tile, 8 warps (32x64 each), K-chunk 32,
// double-buffered cp.async. Padded smem rows (80B) -> conflict-free ldmatrix.
#define BK 32
#define ROWB 80
#define TILE_BYTES (128 * ROWB)          // 10240
#define STAGE_BYTES (4 * TILE_BYTES)     // 40960
#define GEMM_SMEM (2 * STAGE_BYTES)      // 81920
#define NCH (Ev / BK)                    // 32

__device__ __forceinline__ void load_stage(
    uint32_t sbase, int stage, int kc,
    const __nv_bfloat16* Ah, const __nv_bfloat16* Al,
    const __nv_bfloat16* Bh, const __nv_bfloat16* Bl,
    int m0, int n0, int tid)
{
    const uint32_t st = sbase + stage * STAGE_BYTES;
    const __nv_bfloat16* srcs[4] = {Ah, Al, Bh, Bl};
    const int row0[4] = {m0, m0, n0, n0};
#pragma unroll
    for (int t = 0; t < 4; ++t) {
#pragma unroll
        for (int p = 0; p < 2; ++p) {
            const int i = p * 256 + tid;          // 0..511
            const int r = i >> 2;
            const int c = i & 3;
            const __nv_bfloat16* g =
                srcs[t] + (size_t)(row0[t] + r) * Ev + kc * BK + c * 8;
            CP_ASYNC16(st + t * TILE_BYTES + r * ROWB + c * 16, g);
        }
    }
}

__global__ __launch_bounds__(256, 1)
void gemm_mma_kernel(const __nv_bfloat16* __restrict__ Ah,
                     const __nv_bfloat16* __restrict__ Al,
                     const __nv_bfloat16* __restrict__ Bh,
                     const __nv_bfloat16* __restrict__ Bl,
                     const float* __restrict__ bias, float* __restrict__ C)
{
    extern __shared__ __align__(128) char smem[];
    const uint32_t sb = smem_u32(smem);
    const int tid = threadIdx.x;
    const int wid = tid >> 5, lane = tid & 31;
    const int warp_m = wid & 3, warp_n = wid >> 2;
    const int m0 = blockIdx.y << 7;
    const int n0 = blockIdx.x << 7;

    float acc[2][8][4];
#pragma unroll
    for (int mt = 0; mt < 2; ++mt)
#pragma unroll
        for (int nt = 0; nt < 8; ++nt)
#pragma unroll
            for (int q = 0; q < 4; ++q) acc[mt][nt][q] = 0.f;

    load_stage(sb, 0, 0, Ah, Al, Bh, Bl, m0, n0, tid);
    CP_COMMIT();

    // fragment address components (constant across chunks)
    const int arow = warp_m * 32 + (lane & 15);
    const uint32_t acol16 = (uint32_t)((lane >> 4) << 4);        // 0 or 16
    const int nrow = warp_n * 64 + (((lane >> 4) & 1) << 3) + (lane & 7);
    const uint32_t bcol16 = (uint32_t)(((lane >> 3) & 1) << 4);  // 0 or 16

    for (int c = 0; c < NCH; ++c) {
        const int s = c & 1;
        if (c + 1 < NCH) {
            load_stage(sb, s ^ 1, c + 1, Ah, Al, Bh, Bl, m0, n0, tid);
            CP_COMMIT();
            CP_WAIT(1);
        } else {
            CP_WAIT(0);
        }
        __syncthreads();

        const uint32_t stAh = sb + s * STAGE_BYTES;
        const uint32_t stAl = stAh + TILE_BYTES;
        const uint32_t stBh = stAh + 2 * TILE_BYTES;
        const uint32_t stBl = stAh + 3 * TILE_BYTES;

#pragma unroll
        for (int ks = 0; ks < 2; ++ks) {
            const uint32_t kofs = ks * 32;
            uint32_t a[2][4], a2[2][4], b[4][4];

            // A-hi fragments (2 m16 tiles)
            ldsm4(stAh + (uint32_t)arow * ROWB + kofs + acol16, a[0]);
            ldsm4(stAh + (uint32_t)(arow + 16) * ROWB + kofs + acol16, a[1]);
            // B-hi fragments (8 n8 tiles as 4 pairs)
#pragma unroll
            for (int p = 0; p < 4; ++p)
                ldsm4(stBh + (uint32_t)(nrow + p * 16) * ROWB + kofs + bcol16, b[p]);

            // Ah * Bh
#pragma unroll
            for (int mt = 0; mt < 2; ++mt)
#pragma unroll
                for (int nt = 0; nt < 8; ++nt)
                    mma16816(acc[mt][nt], a[mt], &b[nt >> 1][(nt & 1) * 2]);

            // Al * Bh
            ldsm4(stAl + (uint32_t)arow * ROWB + kofs + acol16, a2[0]);
            ldsm4(stAl + (uint32_t)(arow + 16) * ROWB + kofs + acol16, a2[1]);
#pragma unroll
            for (int mt = 0; mt < 2; ++mt)
#pragma unroll
                for (int nt = 0; nt < 8; ++nt)
                    mma16816(acc[mt][nt], a2[mt], &b[nt >> 1][(nt & 1) * 2]);

            // Ah * Bl (reuse b regs)
#pragma unroll
            for (int p = 0; p < 4; ++p)
                ldsm4(stBl + (uint32_t)(nrow + p * 16) * ROWB + kofs + bcol16, b[p]);
#pragma unroll
            for (int mt = 0; mt < 2; ++mt)
#pragma unroll
                for (int nt = 0; nt < 8; ++nt)
                    mma16816(acc[mt][nt], a[mt], &b[nt >> 1][(nt & 1) * 2]);
        }
        __syncthreads();
    }

    // epilogue: thread t owns (m = base + mt*16 + t/4 [+8], n = nt*8 + (t%4)*2)
    const int tr = lane >> 2;
    const int tc = (lane & 3) * 2;
    const int mb = m0 + warp_m * 32;
    const int nb = n0 + warp_n * 64;
#pragma unroll
    for (int mt = 0; mt < 2; ++mt) {
#pragma unroll
        for (int nt = 0; nt < 8; ++nt) {
            const int col = nb + nt * 8 + tc;
            float b0 = 0.f, b1 = 0.f;
            if (bias) { b0 = bias[col]; b1 = bias[col + 1]; }
            float2 v0 = {acc[mt][nt][0] + b0, acc[mt][nt][1] + b1};
            float2 v1 = {acc[mt][nt][2] + b0, acc[mt][nt][3] + b1};
            *reinterpret_cast<float2*>(
                &C[(size_t)(mb + mt * 16 + tr) * Ev + col]) = v0;
            *reinterpret_cast<float2*>(
                &C[(size_t)(mb + mt * 16 + tr + 8) * Ev + col]) = v1;
        }
    }
}

// ========================= flash attention (round-2 FFMA2) =================
#define QT_PAD 130
#define PT_PAD 130
#define KV_PAD 65

__global__ __launch_bounds__(256, 2)
void attn_kernel(const float* __restrict__ Q, const float* __restrict__ K,
                 const float* __restrict__ V, float* __restrict__ O)
{
    extern __shared__ float sm[];
    float* Qt = sm;                         // [64][130]
    float* Ks = Qt + 64 * QT_PAD;           // [64][65]
    float* Vs = Ks + 64 * KV_PAD;           // [64][65]
    float* Pt = Vs + 64 * KV_PAD;           // [64][130]
    float* ms = Pt + 64 * PT_PAD;
    float* ls = ms + 128;
    float* cs = ls + 128;

    const int tid = threadIdx.x;
    const int b  = blockIdx.x >> 4;
    const int h  = blockIdx.x & 15;
    const int q0 = blockIdx.y << 7;

    const float* Qb = Q + ((size_t)b * Sv + q0) * Ev + h * HDv;
    const float* Kb = K + (size_t)b * Sv * Ev + h * HDv;
    const float* Vb = V + (size_t)b * Sv * Ev + h * HDv;

    for (int i = tid; i < 128 * 16; i += 256) {
        const int row = i >> 4;
        const int d   = (i & 15) << 2;
        float4 v = *reinterpret_cast<const float4*>(&Qb[(size_t)row * Ev + d]);
        Qt[(d + 0) * QT_PAD + row] = v.x;
        Qt[(d + 1) * QT_PAD + row] = v.y;
        Qt[(d + 2) * QT_PAD + row] = v.z;
        Qt[(d + 3) * QT_PAD + row] = v.w;
    }
    if (tid < 128) ms[tid] = -CUDART_INF_F;

    const int tx = tid & 15;
    const int ty = tid >> 4;
    const int r0 = ty << 3;
    const int c0 = tx << 2;

    u64 acc2[4][4];
#pragma unroll
    for (int i = 0; i < 4; ++i)
#pragma unroll
        for (int j = 0; j < 4; ++j) acc2[i][j] = 0ull;

    const u64 scale2 = pack_dup(ATT_SCALE);

    for (int kb = 0; kb < NKB; ++kb) {
        const float* Kp = Kb + (size_t)(kb * 64) * Ev;
        const float* Vp = Vb + (size_t)(kb * 64) * Ev;

        for (int i = tid; i < 64 * 16; i += 256) {
            const int row = i >> 4;
            const int d   = (i & 15) << 2;
            float4 kv = *reinterpret_cast<const float4*>(&Kp[(size_t)row * Ev + d]);
            Ks[row * KV_PAD + d + 0] = kv.x; Ks[row * KV_PAD + d + 1] = kv.y;
            Ks[row * KV_PAD + d + 2] = kv.z; Ks[row * KV_PAD + d + 3] = kv.w;
            float4 vv = *reinterpret_cast<const float4*>(&Vp[(size_t)row * Ev + d]);
            Vs[row * KV_PAD + d + 0] = vv.x; Vs[row * KV_PAD + d + 1] = vv.y;
            Vs[row * KV_PAD + d + 2] = vv.z; Vs[row * KV_PAD + d + 3] = vv.w;
        }
        __syncthreads();

        u64 s2[4][4];
#pragma unroll
        for (int i = 0; i < 4; ++i)
#pragma unroll
            for (int j = 0; j < 4; ++j) s2[i][j] = 0ull;

#pragma unroll 8
        for (int kk = 0; kk < 64; ++kk) {
            const u64* qp = reinterpret_cast<const u64*>(&Qt[kk * QT_PAD + r0]);
            u64 q2[4];
#pragma unroll
            for (int i = 0; i < 4; ++i) q2[i] = qp[i];
            u64 k2[4];
#pragma unroll
            for (int j = 0; j < 4; ++j) k2[j] = pack_dup(Ks[(c0 + j) * KV_PAD + kk]);
#pragma unroll
            for (int i = 0; i < 4; ++i)
#pragma unroll
                for (int j = 0; j < 4; ++j)
                    ffma2(s2[i][j], q2[i], k2[j]);
        }
#pragma unroll
        for (int j = 0; j < 4; ++j)
#pragma unroll
            for (int i = 0; i < 4; ++i)
                *reinterpret_cast<u64*>(&Pt[(c0 + j) * PT_PAD + r0 + 2 * i]) =
                    fmul2(s2[i][j], scale2);
        __syncthreads();

        if (tid < 128) {
            float mx = -CUDART_INF_F;
#pragma unroll 8
            for (int k = 0; k < 64; ++k) mx = fmaxf(mx, Pt[k * PT_PAD + tid]);
            const float mo = ms[tid];
            const float mn = fmaxf(mo, mx);
            const float co = __expf(mo - mn);
            float sum = 0.f;
#pragma unroll 8
            for (int k = 0; k < 64; ++k) {
                float e = __expf(Pt[k * PT_PAD + tid] - mn);
                Pt[k * PT_PAD + tid] = e;
                sum += e;
            }
            ls[tid] = sum * co + sum;   // BUG preserved from reference
            ms[tid] = mn;
            cs[tid] = co;
        }
        __syncthreads();

#pragma unroll
        for (int i = 0; i < 4; ++i) {
            const u64 cr2 = pack2(cs[r0 + 2 * i], cs[r0 + 2 * i + 1]);
#pragma unroll
            for (int j = 0; j < 4; ++j) acc2[i][j] = fmul2(acc2[i][j], cr2);
        }

#pragma unroll 8
        for (int kk = 0; kk < 64; ++kk) {
            const u64* pp = reinterpret_cast<const u64*>(&Pt[kk * PT_PAD + r0]);
            u64 p2[4];
#pragma unroll
            for (int i = 0; i < 4; ++i) p2[i] = pp[i];
            u64 v2[4];
#pragma unroll
            for (int j = 0; j < 4; ++j) v2[j] = pack_dup(Vs[kk * KV_PAD + c0 + j]);
#pragma unroll
            for (int i = 0; i < 4; ++i)
#pragma unroll
                for (int j = 0; j < 4; ++j)
                    ffma2(acc2[i][j], p2[i], v2[j]);
        }
        __syncthreads();
    }

    float* Ob = O + ((size_t)b * Sv + q0) * Ev + h * HDv;
#pragma unroll
    for (int i = 0; i < 4; ++i) {
        const float inv_lo = 1.f / ls[r0 + 2 * i];
        const float inv_hi = 1.f / ls[r0 + 2 * i + 1];
#pragma unroll
        for (int j = 0; j < 4; ++j) {
            float lo, hi;
            unpack2(acc2[i][j], lo, hi);
            Ob[(size_t)(r0 + 2 * i) * Ev + c0 + j]     = lo * inv_lo;
            Ob[(size_t)(r0 + 2 * i + 1) * Ev + c0 + j] = hi * inv_hi;
        }
    }
}

// ========================= launch ==========================================
extern "C" void kernel_launch(void* const* d_in, const int* in_sizes, int n_in,
                              void* d_out, int out_size)
{
    const float* x  = (const float*)d_in[0];
    const float* ws[4] = {(const float*)d_in[1], (const float*)d_in[2],
                          (const float*)d_in[3], (const float*)d_in[4]};
    const float* ob = (const float*)d_in[5];
    float* out = (float*)d_out;

    float *Qg, *Kg, *Vg, *Og;
    __nv_bfloat16 *xh, *xl, *oh, *ol, *wh, *wl;
    cudaGetSymbolAddress((void**)&Qg, g_Q);
    cudaGetSymbolAddress((void**)&Kg, g_K);
    cudaGetSymbolAddress((void**)&Vg, g_V);
    cudaGetSymbolAddress((void**)&Og, g_O);
    cudaGetSymbolAddress((void**)&xh, g_xh);
    cudaGetSymbolAddress((void**)&xl, g_xl);
    cudaGetSymbolAddress((void**)&oh, g_oh);
    cudaGetSymbolAddress((void**)&ol, g_ol);
    cudaGetSymbolAddress((void**)&wh, g_wh);
    cudaGetSymbolAddress((void**)&wl, g_wl);

    const int M = Bv * Sv;               // 8192
    const int nX4 = M * Ev / 4;
    const int nW4 = Ev * Ev / 4;

    split_kernel<<<nX4 / 256, 256>>>(x, xh, xl, nX4);
    for (int i = 0; i < 4; ++i)
        split_kernel<<<nW4 / 256, 256>>>(ws[i], wh + (size_t)i * Ev * Ev,
                                         wl + (size_t)i * Ev * Ev, nW4);

    cudaFuncSetAttribute(gemm_mma_kernel,
                         cudaFuncAttributeMaxDynamicSharedMemorySize, GEMM_SMEM);
    const dim3 ggrid(Ev / 128, M / 128);  // (8, 64)

    gemm_mma_kernel<<<ggrid, 256, GEMM_SMEM>>>(xh, xl, wh + 0 * (size_t)Ev * Ev,
                                               wl + 0 * (size_t)Ev * Ev, nullptr, Qg);
    gemm_mma_kernel<<<ggrid, 256, GEMM_SMEM>>>(xh, xl, wh + 1 * (size_t)Ev * Ev,
                                               wl + 1 * (size_t)Ev * Ev, nullptr, Kg);
    gemm_mma_kernel<<<ggrid, 256, GEMM_SMEM>>>(xh, xl, wh + 2 * (size_t)Ev * Ev,
                                               wl + 2 * (size_t)Ev * Ev, nullptr, Vg);

    const size_t asmem = (size_t)(64 * QT_PAD + 64 * KV_PAD + 64 * KV_PAD
                                  + 64 * PT_PAD + 3 * 128) * sizeof(float);
    cudaFuncSetAttribute(attn_kernel,
                         cudaFuncAttributeMaxDynamicSharedMemorySize, (int)asmem);
    attn_kernel<<<dim3(Bv * Hv, Sv / 128), 256, asmem>>>(Qg, Kg, Vg, Og);

    split_kernel<<<nX4 / 256, 256>>>(Og, oh, ol, nX4);
    gemm_mma_kernel<<<ggrid, 256, GEMM_SMEM>>>(oh, ol, wh + 3 * (size_t)Ev * Ev,
                                               wl + 3 * (size_t)Ev * Ev, ob, out);
}

// round 6
// speedup vs baseline: 3.5425x; 2.3349x over previous
#include <cuda_runtime.h>
#include <cuda_bf16.h>
#include <cuda_fp16.h>
#include <math_constants.h>
#include <cstdint>

// Problem constants
#define Bv 4
#define Sv 2048
#define Ev 1024
#define Hv 16
#define HDv 64
#define NKB (Sv / 64)
#define ATT_SCALE 0.125f

// ========================= PTX helpers =====================================
__device__ __forceinline__ uint32_t smem_u32(const void* p) {
    uint32_t a;
    asm("{ .reg .u64 t; cvta.to.shared.u64 t, %1; cvt.u32.u64 %0, t; }"
        : "=r"(a) : "l"(p));
    return a;
}
#define CP_ASYNC16(sa, ga) \
    asm volatile("cp.async.cg.shared.global [%0], [%1], 16;" :: "r"(sa), "l"(ga))
#define CP_COMMIT()  asm volatile("cp.async.commit_group;" ::: "memory")
#define CP_WAIT(n)   asm volatile("cp.async.wait_group %0;" :: "n"(n) : "memory")

__device__ __forceinline__ void ldsm4(uint32_t addr, uint32_t r[4]) {
    asm volatile("ldmatrix.sync.aligned.m8n8.x4.shared.b16 {%0,%1,%2,%3}, [%4];"
                 : "=r"(r[0]), "=r"(r[1]), "=r"(r[2]), "=r"(r[3]) : "r"(addr));
}
__device__ __forceinline__ void ldsm4t(uint32_t addr, uint32_t r[4]) {
    asm volatile("ldmatrix.sync.aligned.m8n8.x4.trans.shared.b16 {%0,%1,%2,%3}, [%4];"
                 : "=r"(r[0]), "=r"(r[1]), "=r"(r[2]), "=r"(r[3]) : "r"(addr));
}
// bf16 mma (GEMMs)
__device__ __forceinline__ void mma_bf(float c[4], const uint32_t a[4],
                                       const uint32_t b[2]) {
    asm volatile(
        "mma.sync.aligned.m16n8k16.row.col.f32.bf16.bf16.f32 "
        "{%0,%1,%2,%3}, {%4,%5,%6,%7}, {%8,%9}, {%0,%1,%2,%3};"
        : "+f"(c[0]), "+f"(c[1]), "+f"(c[2]), "+f"(c[3])
        : "r"(a[0]), "r"(a[1]), "r"(a[2]), "r"(a[3]), "r"(b[0]), "r"(b[1]));
}
// fp16 mma (attention)
__device__ __forceinline__ void mma_fp(float c[4], const uint32_t a[4],
                                       const uint32_t b[2]) {
    asm volatile(
        "mma.sync.aligned.m16n8k16.row.col.f32.f16.f16.f32 "
        "{%0,%1,%2,%3}, {%4,%5,%6,%7}, {%8,%9}, {%0,%1,%2,%3};"
        : "+f"(c[0]), "+f"(c[1]), "+f"(c[2]), "+f"(c[3])
        : "r"(a[0]), "r"(a[1]), "r"(a[2]), "r"(a[3]), "r"(b[0]), "r"(b[1]));
}
// pack two floats -> fp16x2 in a u32 register
__device__ __forceinline__ uint32_t f2_to_h2u(float lo, float hi) {
    uint32_t r;
    asm("cvt.rn.f16x2.f32 %0, %1, %2;" : "=r"(r) : "f"(hi), "f"(lo));
    return r;
}

// ========================= static device scratch ===========================
__device__ float        g_O [(size_t)Bv * Sv * Ev];
__device__ __half       g_Qh[(size_t)Bv * Sv * Ev];
__device__ __half       g_Kh[(size_t)Bv * Sv * Ev];
__device__ __half       g_Vh[(size_t)Bv * Sv * Ev];
__device__ __nv_bfloat16 g_xh[(size_t)Bv * Sv * Ev];
__device__ __nv_bfloat16 g_xl[(size_t)Bv * Sv * Ev];
__device__ __nv_bfloat16 g_oh[(size_t)Bv * Sv * Ev];
__device__ __nv_bfloat16 g_ol[(size_t)Bv * Sv * Ev];
__device__ __nv_bfloat16 g_wh[4][(size_t)Ev * Ev];
__device__ __nv_bfloat16 g_wl[4][(size_t)Ev * Ev];

// ========================= split fp32 -> bf16 hi/lo ========================
__global__ void split_kernel(const float* __restrict__ src,
                             __nv_bfloat16* __restrict__ hi,
                             __nv_bfloat16* __restrict__ lo, int n4)
{
    int i = blockIdx.x * blockDim.x + threadIdx.x;
    if (i >= n4) return;
    float4 v = reinterpret_cast<const float4*>(src)[i];
    float a[4] = {v.x, v.y, v.z, v.w};
    __nv_bfloat16 h[4], l[4];
#pragma unroll
    for (int j = 0; j < 4; ++j) {
        h[j] = __float2bfloat16(a[j]);
        l[j] = __float2bfloat16(a[j] - __bfloat162float(h[j]));
    }
    __nv_bfloat162* hp = reinterpret_cast<__nv_bfloat162*>(hi) + 2 * i;
    __nv_bfloat162* lp = reinterpret_cast<__nv_bfloat162*>(lo) + 2 * i;
    hp[0] = __halves2bfloat162(h[0], h[1]);
    hp[1] = __halves2bfloat162(h[2], h[3]);
    lp[0] = __halves2bfloat162(l[0], l[1]);
    lp[1] = __halves2bfloat162(l[2], l[3]);
}

// ========================= mma.sync GEMM (bf16 3-product split) ============
// C = (Ah+Al)(Bh+Bl)^T (+bias). Output: fp32 (Ch==null) or fp16*premul.
#define BK 32
#define ROWB 80
#define TILE_BYTES (128 * ROWB)
#define STAGE_BYTES (4 * TILE_BYTES)
#define GEMM_SMEM (2 * STAGE_BYTES)
#define NCH (Ev / BK)

__device__ __forceinline__ void load_stage(
    uint32_t sbase, int stage, int kc,
    const __nv_bfloat16* Ah, const __nv_bfloat16* Al,
    const __nv_bfloat16* Bh, const __nv_bfloat16* Bl,
    int m0, int n0, int tid)
{
    const uint32_t st = sbase + stage * STAGE_BYTES;
    const __nv_bfloat16* srcs[4] = {Ah, Al, Bh, Bl};
    const int row0[4] = {m0, m0, n0, n0};
#pragma unroll
    for (int t = 0; t < 4; ++t) {
#pragma unroll
        for (int p = 0; p < 2; ++p) {
            const int i = p * 256 + tid;
            const int r = i >> 2;
            const int c = i & 3;
            const __nv_bfloat16* g =
                srcs[t] + (size_t)(row0[t] + r) * Ev + kc * BK + c * 8;
            CP_ASYNC16(st + t * TILE_BYTES + r * ROWB + c * 16, g);
        }
    }
}

__global__ __launch_bounds__(256, 1)
void gemm_mma_kernel(const __nv_bfloat16* __restrict__ Ah,
                     const __nv_bfloat16* __restrict__ Al,
                     const __nv_bfloat16* __restrict__ Bh,
                     const __nv_bfloat16* __restrict__ Bl,
                     const float* __restrict__ bias,
                     float* __restrict__ C, __half* __restrict__ Ch,
                     float premul)
{
    extern __shared__ __align__(128) char smem[];
    const uint32_t sb = smem_u32(smem);
    const int tid = threadIdx.x;
    const int wid = tid >> 5, lane = tid & 31;
    const int warp_m = wid & 3, warp_n = wid >> 2;
    const int m0 = blockIdx.y << 7;
    const int n0 = blockIdx.x << 7;

    float acc[2][8][4];
#pragma unroll
    for (int mt = 0; mt < 2; ++mt)
#pragma unroll
        for (int nt = 0; nt < 8; ++nt)
#pragma unroll
            for (int q = 0; q < 4; ++q) acc[mt][nt][q] = 0.f;

    load_stage(sb, 0, 0, Ah, Al, Bh, Bl, m0, n0, tid);
    CP_COMMIT();

    const int arow = warp_m * 32 + (lane & 15);
    const uint32_t acol16 = (uint32_t)((lane >> 4) << 4);
    const int nrow = warp_n * 64 + (((lane >> 4) & 1) << 3) + (lane & 7);
    const uint32_t bcol16 = (uint32_t)(((lane >> 3) & 1) << 4);

    for (int c = 0; c < NCH; ++c) {
        const int s = c & 1;
        if (c + 1 < NCH) {
            load_stage(sb, s ^ 1, c + 1, Ah, Al, Bh, Bl, m0, n0, tid);
            CP_COMMIT();
            CP_WAIT(1);
        } else {
            CP_WAIT(0);
        }
        __syncthreads();

        const uint32_t stAh = sb + s * STAGE_BYTES;
        const uint32_t stAl = stAh + TILE_BYTES;
        const uint32_t stBh = stAh + 2 * TILE_BYTES;
        const uint32_t stBl = stAh + 3 * TILE_BYTES;

#pragma unroll
        for (int ks = 0; ks < 2; ++ks) {
            const uint32_t kofs = ks * 32;
            uint32_t a[2][4], a2[2][4], b[4][4];

            ldsm4(stAh + (uint32_t)arow * ROWB + kofs + acol16, a[0]);
            ldsm4(stAh + (uint32_t)(arow + 16) * ROWB + kofs + acol16, a[1]);
#pragma unroll
            for (int p = 0; p < 4; ++p)
                ldsm4(stBh + (uint32_t)(nrow + p * 16) * ROWB + kofs + bcol16, b[p]);
#pragma unroll
            for (int mt = 0; mt < 2; ++mt)
#pragma unroll
                for (int nt = 0; nt < 8; ++nt)
                    mma_bf(acc[mt][nt], a[mt], &b[nt >> 1][(nt & 1) * 2]);

            ldsm4(stAl + (uint32_t)arow * ROWB + kofs + acol16, a2[0]);
            ldsm4(stAl + (uint32_t)(arow + 16) * ROWB + kofs + acol16, a2[1]);
#pragma unroll
            for (int mt = 0; mt < 2; ++mt)
#pragma unroll
                for (int nt = 0; nt < 8; ++nt)
                    mma_bf(acc[mt][nt], a2[mt], &b[nt >> 1][(nt & 1) * 2]);

#pragma unroll
            for (int p = 0; p < 4; ++p)
                ldsm4(stBl + (uint32_t)(nrow + p * 16) * ROWB + kofs + bcol16, b[p]);
#pragma unroll
            for (int mt = 0; mt < 2; ++mt)
#pragma unroll
                for (int nt = 0; nt < 8; ++nt)
                    mma_bf(acc[mt][nt], a[mt], &b[nt >> 1][(nt & 1) * 2]);
        }
        __syncthreads();
    }

    const int tr = lane >> 2;
    const int tc = (lane & 3) * 2;
    const int mb = m0 + warp_m * 32;
    const int nb = n0 + warp_n * 64;
#pragma unroll
    for (int mt = 0; mt < 2; ++mt) {
#pragma unroll
        for (int nt = 0; nt < 8; ++nt) {
            const int col = nb + nt * 8 + tc;
            const size_t r0 = (size_t)(mb + mt * 16 + tr) * Ev + col;
            const size_t r1 = (size_t)(mb + mt * 16 + tr + 8) * Ev + col;
            if (Ch) {
                uint32_t p0 = f2_to_h2u(acc[mt][nt][0] * premul, acc[mt][nt][1] * premul);
                uint32_t p1 = f2_to_h2u(acc[mt][nt][2] * premul, acc[mt][nt][3] * premul);
                *reinterpret_cast<uint32_t*>(&Ch[r0]) = p0;
                *reinterpret_cast<uint32_t*>(&Ch[r1]) = p1;
            } else {
                float b0 = 0.f, b1 = 0.f;
                if (bias) { b0 = bias[col]; b1 = bias[col + 1]; }
                float2 v0 = {acc[mt][nt][0] + b0, acc[mt][nt][1] + b1};
                float2 v1 = {acc[mt][nt][2] + b0, acc[mt][nt][3] + b1};
                *reinterpret_cast<float2*>(&C[r0]) = v0;
                *reinterpret_cast<float2*>(&C[r1]) = v1;
            }
        }
    }
}

// ========================= tensor-core flash attention =====================
// fp16 single-product. Q pre-scaled by 0.125 (exact). Buggy l preserved.
// CTA: 128 q-rows of one (b,h); 8 warps x 16 rows. K/V double-buffered.
#define AROW 72                    // halves per smem row (144 B)
#define ATT_SMEM ((128 + 2*64 + 2*64) * AROW * 2)   // 55296 B

__global__ __launch_bounds__(256, 2)
void attn_tc_kernel(const __half* __restrict__ Q, const __half* __restrict__ K,
                    const __half* __restrict__ V, float* __restrict__ O)
{
    extern __shared__ __align__(128) char smem[];
    const uint32_t sb = smem_u32(smem);
    const uint32_t sQ = sb;
    const uint32_t sK = sQ + 128 * AROW * 2;   // 2 stages of [64][AROW]
    const uint32_t sV = sK + 2 * 64 * AROW * 2;

    const int tid = threadIdx.x;
    const int w = tid >> 5, lane = tid & 31;
    const int b  = blockIdx.x >> 4;
    const int h  = blockIdx.x & 15;
    const int q0 = blockIdx.y << 7;

    const __half* Qg = Q + ((size_t)b * Sv + q0) * Ev + h * HDv;
    const __half* Kg = K + (size_t)b * Sv * Ev + h * HDv;
    const __half* Vg = V + (size_t)b * Sv * Ev + h * HDv;

    // Q: 128 rows x 8 chunks (16B)
    for (int i = tid; i < 1024; i += 256) {
        const int r = i >> 3, c = i & 7;
        CP_ASYNC16(sQ + r * 144 + c * 16, Qg + (size_t)r * Ev + c * 8);
    }
    // K/V block 0 -> stage 0
    for (int i = tid; i < 512; i += 256) {
        const int r = i >> 3, c = i & 7;
        CP_ASYNC16(sK + r * 144 + c * 16, Kg + (size_t)r * Ev + c * 8);
        CP_ASYNC16(sV + r * 144 + c * 16, Vg + (size_t)r * Ev + c * 8);
    }
    CP_COMMIT();

    float acc[8][4];
#pragma unroll
    for (int j = 0; j < 8; ++j)
#pragma unroll
        for (int q = 0; q < 4; ++q) acc[j][q] = 0.f;
    float m0 = -CUDART_INF_F, m1 = -CUDART_INF_F;
    float l0 = 0.f, l1 = 0.f;

    uint32_t aQ[4][4];
    bool qLoaded = false;

    // fragment address components
    const uint32_t q_addr0 = sQ + (uint32_t)(16 * w + (lane & 15)) * 144
                                + ((lane >> 4) << 4);
    const int kq = lane & 7;            // row-within-8 for B-frag loads
    const int kg16 = (lane >> 4) << 3;  // +8 row group
    const int kg8  = ((lane >> 3) & 1) << 3;

    for (int kb = 0; kb < NKB; ++kb) {
        const int st = kb & 1;
        if (kb + 1 < NKB) {
            const int sn = st ^ 1;
            const __half* Kp = Kg + (size_t)((kb + 1) * 64) * Ev;
            const __half* Vp = Vg + (size_t)((kb + 1) * 64) * Ev;
            for (int i = tid; i < 512; i += 256) {
                const int r = i >> 3, c = i & 7;
                CP_ASYNC16(sK + (sn * 64 + r) * 144 + c * 16, Kp + (size_t)r * Ev + c * 8);
                CP_ASYNC16(sV + (sn * 64 + r) * 144 + c * 16, Vp + (size_t)r * Ev + c * 8);
            }
            CP_COMMIT();
            CP_WAIT(1);
        } else {
            CP_WAIT(0);
        }
        __syncthreads();

        if (!qLoaded) {   // Q resident after first wait
#pragma unroll
            for (int s = 0; s < 4; ++s) ldsm4(q_addr0 + s * 32, aQ[s]);
            qLoaded = true;
        }

        const uint32_t sKst = sK + (uint32_t)st * 64 * 144;
        const uint32_t sVst = sV + (uint32_t)st * 64 * 144;

        // ---- scores: S[16][64] = Qw @ K^T ----
        float sc[8][4];
#pragma unroll
        for (int j = 0; j < 8; ++j)
#pragma unroll
            for (int q = 0; q < 4; ++q) sc[j][q] = 0.f;

#pragma unroll
        for (int p = 0; p < 4; ++p) {       // key 16-groups
#pragma unroll
            for (int s = 0; s < 4; ++s) {   // d 16-steps
                uint32_t kf[4];
                ldsm4(sKst + (uint32_t)(16 * p + kg16 + kq) * 144
                           + (uint32_t)(16 * s + kg8) * 2, kf);
                mma_fp(sc[2 * p],     aQ[s], &kf[0]);
                mma_fp(sc[2 * p + 1], aQ[s], &kf[2]);
            }
        }

        // ---- online softmax (buggy l preserved) ----
        float mx0 = -CUDART_INF_F, mx1 = -CUDART_INF_F;
#pragma unroll
        for (int j = 0; j < 8; ++j) {
            mx0 = fmaxf(mx0, fmaxf(sc[j][0], sc[j][1]));
            mx1 = fmaxf(mx1, fmaxf(sc[j][2], sc[j][3]));
        }
        mx0 = fmaxf(mx0, __shfl_xor_sync(0xffffffffu, mx0, 1));
        mx0 = fmaxf(mx0, __shfl_xor_sync(0xffffffffu, mx0, 2));
        mx1 = fmaxf(mx1, __shfl_xor_sync(0xffffffffu, mx1, 1));
        mx1 = fmaxf(mx1, __shfl_xor_sync(0xffffffffu, mx1, 2));

        const float mn0 = fmaxf(m0, mx0);
        const float mn1 = fmaxf(m1, mx1);
        const float co0 = __expf(m0 - mn0);
        const float co1 = __expf(m1 - mn1);
        m0 = mn0; m1 = mn1;

        float sum0 = 0.f, sum1 = 0.f;
        uint32_t ph01[8], ph23[8];
#pragma unroll
        for (int j = 0; j < 8; ++j) {
            const float p0 = __expf(sc[j][0] - mn0);
            const float p1 = __expf(sc[j][1] - mn0);
            const float p2 = __expf(sc[j][2] - mn1);
            const float p3 = __expf(sc[j][3] - mn1);
            sum0 += p0 + p1; sum1 += p2 + p3;
            ph01[j] = f2_to_h2u(p0, p1);
            ph23[j] = f2_to_h2u(p2, p3);
        }
        sum0 += __shfl_xor_sync(0xffffffffu, sum0, 1);
        sum0 += __shfl_xor_sync(0xffffffffu, sum0, 2);
        sum1 += __shfl_xor_sync(0xffffffffu, sum1, 1);
        sum1 += __shfl_xor_sync(0xffffffffu, sum1, 2);

        l0 = sum0 * co0 + sum0;   // BUG preserved from reference
        l1 = sum1 * co1 + sum1;

#pragma unroll
        for (int j = 0; j < 8; ++j) {
            acc[j][0] *= co0; acc[j][1] *= co0;
            acc[j][2] *= co1; acc[j][3] *= co1;
        }

        // ---- PV: acc += P @ V ----
#pragma unroll
        for (int s = 0; s < 4; ++s) {       // key 16-steps
            const uint32_t aP[4] = {ph01[2 * s], ph23[2 * s],
                                    ph01[2 * s + 1], ph23[2 * s + 1]};
#pragma unroll
            for (int dp = 0; dp < 4; ++dp) {  // d 16-pairs
                uint32_t vf[4];
                ldsm4t(sVst + (uint32_t)(16 * s + kg8 + kq) * 144
                            + (uint32_t)(16 * dp + kg16) * 2, vf);
                mma_fp(acc[2 * dp],     aP, &vf[0]);
                mma_fp(acc[2 * dp + 1], aP, &vf[2]);
            }
        }
        __syncthreads();
    }

    // ---- epilogue: O = acc / l ----
    const float inv0 = 1.f / l0;
    const float inv1 = 1.f / l1;
    const int row0 = q0 + 16 * w + (lane >> 2);
    const int colb = h * HDv + 2 * (lane & 3);
    float* Ob = O + (size_t)b * Sv * Ev;
#pragma unroll
    for (int j = 0; j < 8; ++j) {
        const int col = colb + 8 * j;
        float2 v0 = {acc[j][0] * inv0, acc[j][1] * inv0};
        float2 v1 = {acc[j][2] * inv1, acc[j][3] * inv1};
        *reinterpret_cast<float2*>(&Ob[(size_t)row0 * Ev + col]) = v0;
        *reinterpret_cast<float2*>(&Ob[(size_t)(row0 + 8) * Ev + col]) = v1;
    }
}

// ========================= launch ==========================================
extern "C" void kernel_launch(void* const* d_in, const int* in_sizes, int n_in,
                              void* d_out, int out_size)
{
    const float* x  = (const float*)d_in[0];
    const float* ws[4] = {(const float*)d_in[1], (const float*)d_in[2],
                          (const float*)d_in[3], (const float*)d_in[4]};
    const float* ob = (const float*)d_in[5];
    float* out = (float*)d_out;

    float* Og;
    __half *Qh, *Kh, *Vh;
    __nv_bfloat16 *xh, *xl, *oh, *ol, *wh, *wl;
    cudaGetSymbolAddress((void**)&Og, g_O);
    cudaGetSymbolAddress((void**)&Qh, g_Qh);
    cudaGetSymbolAddress((void**)&Kh, g_Kh);
    cudaGetSymbolAddress((void**)&Vh, g_Vh);
    cudaGetSymbolAddress((void**)&xh, g_xh);
    cudaGetSymbolAddress((void**)&xl, g_xl);
    cudaGetSymbolAddress((void**)&oh, g_oh);
    cudaGetSymbolAddress((void**)&ol, g_ol);
    cudaGetSymbolAddress((void**)&wh, g_wh);
    cudaGetSymbolAddress((void**)&wl, g_wl);

    const int M = Bv * Sv;
    const int nX4 = M * Ev / 4;
    const int nW4 = Ev * Ev / 4;

    split_kernel<<<nX4 / 256, 256>>>(x, xh, xl, nX4);
    for (int i = 0; i < 4; ++i)
        split_kernel<<<nW4 / 256, 256>>>(ws[i], wh + (size_t)i * Ev * Ev,
                                         wl + (size_t)i * Ev * Ev, nW4);

    cudaFuncSetAttribute(gemm_mma_kernel,
                         cudaFuncAttributeMaxDynamicSharedMemorySize, GEMM_SMEM);
    const dim3 ggrid(Ev / 128, M / 128);

    // Q scaled by ATT_SCALE at fp16 conversion (exact power of 2)
    gemm_mma_kernel<<<ggrid, 256, GEMM_SMEM>>>(xh, xl, wh + 0 * (size_t)Ev * Ev,
        wl + 0 * (size_t)Ev * Ev, nullptr, nullptr, Qh, ATT_SCALE);
    gemm_mma_kernel<<<ggrid, 256, GEMM_SMEM>>>(xh, xl, wh + 1 * (size_t)Ev * Ev,
        wl + 1 * (size_t)Ev * Ev, nullptr, nullptr, Kh, 1.0f);
    gemm_mma_kernel<<<ggrid, 256, GEMM_SMEM>>>(xh, xl, wh + 2 * (size_t)Ev * Ev,
        wl + 2 * (size_t)Ev * Ev, nullptr, nullptr, Vh, 1.0f);

    cudaFuncSetAttribute(attn_tc_kernel,
                         cudaFuncAttributeMaxDynamicSharedMemorySize, ATT_SMEM);
    attn_tc_kernel<<<dim3(Bv * Hv, Sv / 128), 256, ATT_SMEM>>>(Qh, Kh, Vh, Og);

    split_kernel<<<nX4 / 256, 256>>>(Og, oh, ol, nX4);
    gemm_mma_kernel<<<ggrid, 256, GEMM_SMEM>>>(oh, ol, wh + 3 * (size_t)Ev * Ev,
        wl + 3 * (size_t)Ev * Ev, ob, out, nullptr, 1.0f);
}

// round 7
// speedup vs baseline: 4.4385x; 1.2529x over previous
#include <cuda_runtime.h>
#include <cuda_fp16.h>
#include <math_constants.h>
#include <cstdint>

// Problem constants
#define Bv 4
#define Sv 2048
#define Ev 1024
#define Hv 16
#define HDv 64
#define NKB (Sv / 64)
#define ATT_SCALE 0.125f

// ========================= PTX helpers =====================================
__device__ __forceinline__ uint32_t smem_u32(const void* p) {
    uint32_t a;
    asm("{ .reg .u64 t; cvta.to.shared.u64 t, %1; cvt.u32.u64 %0, t; }"
        : "=r"(a) : "l"(p));
    return a;
}
#define CP_ASYNC16(sa, ga) \
    asm volatile("cp.async.cg.shared.global [%0], [%1], 16;" :: "r"(sa), "l"(ga))
#define CP_COMMIT()  asm volatile("cp.async.commit_group;" ::: "memory")
#define CP_WAIT(n)   asm volatile("cp.async.wait_group %0;" :: "n"(n) : "memory")

__device__ __forceinline__ void ldsm4(uint32_t addr, uint32_t r[4]) {
    asm volatile("ldmatrix.sync.aligned.m8n8.x4.shared.b16 {%0,%1,%2,%3}, [%4];"
                 : "=r"(r[0]), "=r"(r[1]), "=r"(r[2]), "=r"(r[3]) : "r"(addr));
}
__device__ __forceinline__ void ldsm4t(uint32_t addr, uint32_t r[4]) {
    asm volatile("ldmatrix.sync.aligned.m8n8.x4.trans.shared.b16 {%0,%1,%2,%3}, [%4];"
                 : "=r"(r[0]), "=r"(r[1]), "=r"(r[2]), "=r"(r[3]) : "r"(addr));
}
// fp16 mma, fp32 accum
__device__ __forceinline__ void mma_fp(float c[4], const uint32_t a[4],
                                       const uint32_t b[2]) {
    asm volatile(
        "mma.sync.aligned.m16n8k16.row.col.f32.f16.f16.f32 "
        "{%0,%1,%2,%3}, {%4,%5,%6,%7}, {%8,%9}, {%0,%1,%2,%3};"
        : "+f"(c[0]), "+f"(c[1]), "+f"(c[2]), "+f"(c[3])
        : "r"(a[0]), "r"(a[1]), "r"(a[2]), "r"(a[3]), "r"(b[0]), "r"(b[1]));
}
// pack two floats -> fp16x2 in a u32 register
__device__ __forceinline__ uint32_t f2_to_h2u(float lo, float hi) {
    uint32_t r;
    asm("cvt.rn.f16x2.f32 %0, %1, %2;" : "=r"(r) : "f"(hi), "f"(lo));
    return r;
}

// ========================= static device scratch ===========================
__device__ __half g_Qh[(size_t)Bv * Sv * Ev];
__device__ __half g_Kh[(size_t)Bv * Sv * Ev];
__device__ __half g_Vh[(size_t)Bv * Sv * Ev];
__device__ __half g_xh[(size_t)Bv * Sv * Ev];
__device__ __half g_xl[(size_t)Bv * Sv * Ev];
__device__ __half g_oh[(size_t)Bv * Sv * Ev];
__device__ __half g_ol[(size_t)Bv * Sv * Ev];
__device__ __half g_wf[4][(size_t)Ev * Ev];

// ========================= fp32 -> fp16 hi/lo split ========================
__global__ void split_h_kernel(const float* __restrict__ src,
                               __half* __restrict__ hi,
                               __half* __restrict__ lo, int n4)
{
    int i = blockIdx.x * blockDim.x + threadIdx.x;
    if (i >= n4) return;
    float4 v = reinterpret_cast<const float4*>(src)[i];
    float a[4] = {v.x, v.y, v.z, v.w};
    uint32_t hw[2], lw[2];
#pragma unroll
    for (int j = 0; j < 2; ++j) {
        float x0 = a[2 * j], x1 = a[2 * j + 1];
        __half h0 = __float2half_rn(x0), h1 = __float2half_rn(x1);
        hw[j] = f2_to_h2u(__half2float(h0) * 0.f + (float)__half2float(h0),
                          (float)__half2float(h1));
        lw[j] = f2_to_h2u(x0 - __half2float(h0), x1 - __half2float(h1));
    }
    uint32_t* hp = reinterpret_cast<uint32_t*>(hi) + 2 * i;
    uint32_t* lp = reinterpret_cast<uint32_t*>(lo) + 2 * i;
    hp[0] = hw[0]; hp[1] = hw[1];
    lp[0] = lw[0]; lp[1] = lw[1];
}

// ========================= fp32 -> fp16 convert ============================
__global__ void cvt_h_kernel(const float* __restrict__ src,
                             __half* __restrict__ dst, int n4)
{
    int i = blockIdx.x * blockDim.x + threadIdx.x;
    if (i >= n4) return;
    float4 v = reinterpret_cast<const float4*>(src)[i];
    uint32_t* dp = reinterpret_cast<uint32_t*>(dst) + 2 * i;
    dp[0] = f2_to_h2u(v.x, v.y);
    dp[1] = f2_to_h2u(v.z, v.w);
}

// ========================= mma.sync GEMM (fp16 2-product, A split) =========
// C = (Ah+Al)[M,K] * B[N,K]^T (+bias). Output fp32 (Ch==null) or fp16*premul.
#define BK 32
#define ROWB 80
#define TILE_BYTES (128 * ROWB)
#define STAGE_BYTES (3 * TILE_BYTES)     // Ah, Al, B
#define GEMM_SMEM (2 * STAGE_BYTES)      // 61440
#define NCH (Ev / BK)

__device__ __forceinline__ void load_stage(
    uint32_t sbase, int stage, int kc,
    const __half* Ah, const __half* Al, const __half* B,
    int m0, int n0, int tid)
{
    const uint32_t st = sbase + stage * STAGE_BYTES;
    const __half* srcs[3] = {Ah, Al, B};
    const int row0[3] = {m0, m0, n0};
#pragma unroll
    for (int t = 0; t < 3; ++t) {
#pragma unroll
        for (int p = 0; p < 2; ++p) {
            const int i = p * 256 + tid;
            const int r = i >> 2;
            const int c = i & 3;
            const __half* g =
                srcs[t] + (size_t)(row0[t] + r) * Ev + kc * BK + c * 8;
            CP_ASYNC16(st + t * TILE_BYTES + r * ROWB + c * 16, g);
        }
    }
}

__global__ __launch_bounds__(256, 1)
void gemm_mma_kernel(const __half* __restrict__ Ah,
                     const __half* __restrict__ Al,
                     const __half* __restrict__ B,
                     const float* __restrict__ bias,
                     float* __restrict__ C, __half* __restrict__ Ch,
                     float premul)
{
    extern __shared__ __align__(128) char smem[];
    const uint32_t sb = smem_u32(smem);
    const int tid = threadIdx.x;
    const int wid = tid >> 5, lane = tid & 31;
    const int warp_m = wid & 3, warp_n = wid >> 2;
    const int m0 = blockIdx.y << 7;
    const int n0 = blockIdx.x << 7;

    float acc[2][8][4];
#pragma unroll
    for (int mt = 0; mt < 2; ++mt)
#pragma unroll
        for (int nt = 0; nt < 8; ++nt)
#pragma unroll
            for (int q = 0; q < 4; ++q) acc[mt][nt][q] = 0.f;

    load_stage(sb, 0, 0, Ah, Al, B, m0, n0, tid);
    CP_COMMIT();

    const int arow = warp_m * 32 + (lane & 15);
    const uint32_t acol16 = (uint32_t)((lane >> 4) << 4);
    const int nrow = warp_n * 64 + (((lane >> 4) & 1) << 3) + (lane & 7);
    const uint32_t bcol16 = (uint32_t)(((lane >> 3) & 1) << 4);

    for (int c = 0; c < NCH; ++c) {
        const int s = c & 1;
        if (c + 1 < NCH) {
            load_stage(sb, s ^ 1, c + 1, Ah, Al, B, m0, n0, tid);
            CP_COMMIT();
            CP_WAIT(1);
        } else {
            CP_WAIT(0);
        }
        __syncthreads();

        const uint32_t stAh = sb + s * STAGE_BYTES;
        const uint32_t stAl = stAh + TILE_BYTES;
        const uint32_t stB  = stAh + 2 * TILE_BYTES;

#pragma unroll
        for (int ks = 0; ks < 2; ++ks) {
            const uint32_t kofs = ks * 32;
            uint32_t a[2][4], a2[2][4], b[4][4];

#pragma unroll
            for (int p = 0; p < 4; ++p)
                ldsm4(stB + (uint32_t)(nrow + p * 16) * ROWB + kofs + bcol16, b[p]);
            ldsm4(stAh + (uint32_t)arow * ROWB + kofs + acol16, a[0]);
            ldsm4(stAh + (uint32_t)(arow + 16) * ROWB + kofs + acol16, a[1]);
#pragma unroll
            for (int mt = 0; mt < 2; ++mt)
#pragma unroll
                for (int nt = 0; nt < 8; ++nt)
                    mma_fp(acc[mt][nt], a[mt], &b[nt >> 1][(nt & 1) * 2]);

            ldsm4(stAl + (uint32_t)arow * ROWB + kofs + acol16, a2[0]);
            ldsm4(stAl + (uint32_t)(arow + 16) * ROWB + kofs + acol16, a2[1]);
#pragma unroll
            for (int mt = 0; mt < 2; ++mt)
#pragma unroll
                for (int nt = 0; nt < 8; ++nt)
                    mma_fp(acc[mt][nt], a2[mt], &b[nt >> 1][(nt & 1) * 2]);
        }
        __syncthreads();
    }

    const int tr = lane >> 2;
    const int tc = (lane & 3) * 2;
    const int mb = m0 + warp_m * 32;
    const int nb = n0 + warp_n * 64;
#pragma unroll
    for (int mt = 0; mt < 2; ++mt) {
#pragma unroll
        for (int nt = 0; nt < 8; ++nt) {
            const int col = nb + nt * 8 + tc;
            const size_t r0 = (size_t)(mb + mt * 16 + tr) * Ev + col;
            const size_t r1 = (size_t)(mb + mt * 16 + tr + 8) * Ev + col;
            if (Ch) {
                *reinterpret_cast<uint32_t*>(&Ch[r0]) =
                    f2_to_h2u(acc[mt][nt][0] * premul, acc[mt][nt][1] * premul);
                *reinterpret_cast<uint32_t*>(&Ch[r1]) =
                    f2_to_h2u(acc[mt][nt][2] * premul, acc[mt][nt][3] * premul);
            } else {
                float b0 = 0.f, b1 = 0.f;
                if (bias) { b0 = bias[col]; b1 = bias[col + 1]; }
                float2 v0 = {acc[mt][nt][0] + b0, acc[mt][nt][1] + b1};
                float2 v1 = {acc[mt][nt][2] + b0, acc[mt][nt][3] + b1};
                *reinterpret_cast<float2*>(&C[r0]) = v0;
                *reinterpret_cast<float2*>(&C[r1]) = v1;
            }
        }
    }
}

// ========================= tensor-core flash attention =====================
// fp16 single-product. Q pre-scaled by 0.125 (exact). Buggy l preserved.
// Epilogue writes O as fp16 hi/lo split directly (error 2^-22).
#define AROW 72
#define ATT_SMEM ((128 + 2*64 + 2*64) * AROW * 2)   // 55296 B

__global__ __launch_bounds__(256, 2)
void attn_tc_kernel(const __half* __restrict__ Q, const __half* __restrict__ K,
                    const __half* __restrict__ V,
                    __half* __restrict__ Oh, __half* __restrict__ Ol)
{
    extern __shared__ __align__(128) char smem[];
    const uint32_t sb = smem_u32(smem);
    const uint32_t sQ = sb;
    const uint32_t sK = sQ + 128 * AROW * 2;
    const uint32_t sV = sK + 2 * 64 * AROW * 2;

    const int tid = threadIdx.x;
    const int w = tid >> 5, lane = tid & 31;
    const int b  = blockIdx.x >> 4;
    const int h  = blockIdx.x & 15;
    const int q0 = blockIdx.y << 7;

    const __half* Qg = Q + ((size_t)b * Sv + q0) * Ev + h * HDv;
    const __half* Kg = K + (size_t)b * Sv * Ev + h * HDv;
    const __half* Vg = V + (size_t)b * Sv * Ev + h * HDv;

    for (int i = tid; i < 1024; i += 256) {
        const int r = i >> 3, c = i & 7;
        CP_ASYNC16(sQ + r * 144 + c * 16, Qg + (size_t)r * Ev + c * 8);
    }
    for (int i = tid; i < 512; i += 256) {
        const int r = i >> 3, c = i & 7;
        CP_ASYNC16(sK + r * 144 + c * 16, Kg + (size_t)r * Ev + c * 8);
        CP_ASYNC16(sV + r * 144 + c * 16, Vg + (size_t)r * Ev + c * 8);
    }
    CP_COMMIT();

    float acc[8][4];
#pragma unroll
    for (int j = 0; j < 8; ++j)
#pragma unroll
        for (int q = 0; q < 4; ++q) acc[j][q] = 0.f;
    float m0 = -CUDART_INF_F, m1 = -CUDART_INF_F;
    float l0 = 0.f, l1 = 0.f;

    uint32_t aQ[4][4];
    bool qLoaded = false;

    const uint32_t q_addr0 = sQ + (uint32_t)(16 * w + (lane & 15)) * 144
                                + ((lane >> 4) << 4);
    const int kq = lane & 7;
    const int kg16 = (lane >> 4) << 3;
    const int kg8  = ((lane >> 3) & 1) << 3;

    for (int kb = 0; kb < NKB; ++kb) {
        const int st = kb & 1;
        if (kb + 1 < NKB) {
            const int sn = st ^ 1;
            const __half* Kp = Kg + (size_t)((kb + 1) * 64) * Ev;
            const __half* Vp = Vg + (size_t)((kb + 1) * 64) * Ev;
            for (int i = tid; i < 512; i += 256) {
                const int r = i >> 3, c = i & 7;
                CP_ASYNC16(sK + (sn * 64 + r) * 144 + c * 16, Kp + (size_t)r * Ev + c * 8);
                CP_ASYNC16(sV + (sn * 64 + r) * 144 + c * 16, Vp + (size_t)r * Ev + c * 8);
            }
            CP_COMMIT();
            CP_WAIT(1);
        } else {
            CP_WAIT(0);
        }
        __syncthreads();

        if (!qLoaded) {
#pragma unroll
            for (int s = 0; s < 4; ++s) ldsm4(q_addr0 + s * 32, aQ[s]);
            qLoaded = true;
        }

        const uint32_t sKst = sK + (uint32_t)st * 64 * 144;
        const uint32_t sVst = sV + (uint32_t)st * 64 * 144;

        float sc[8][4];
#pragma unroll
        for (int j = 0; j < 8; ++j)
#pragma unroll
            for (int q = 0; q < 4; ++q) sc[j][q] = 0.f;

#pragma unroll
        for (int p = 0; p < 4; ++p) {
#pragma unroll
            for (int s = 0; s < 4; ++s) {
                uint32_t kf[4];
                ldsm4(sKst + (uint32_t)(16 * p + kg16 + kq) * 144
                           + (uint32_t)(16 * s + kg8) * 2, kf);
                mma_fp(sc[2 * p],     aQ[s], &kf[0]);
                mma_fp(sc[2 * p + 1], aQ[s], &kf[2]);
            }
        }

        float mx0 = -CUDART_INF_F, mx1 = -CUDART_INF_F;
#pragma unroll
        for (int j = 0; j < 8; ++j) {
            mx0 = fmaxf(mx0, fmaxf(sc[j][0], sc[j][1]));
            mx1 = fmaxf(mx1, fmaxf(sc[j][2], sc[j][3]));
        }
        mx0 = fmaxf(mx0, __shfl_xor_sync(0xffffffffu, mx0, 1));
        mx0 = fmaxf(mx0, __shfl_xor_sync(0xffffffffu, mx0, 2));
        mx1 = fmaxf(mx1, __shfl_xor_sync(0xffffffffu, mx1, 1));
        mx1 = fmaxf(mx1, __shfl_xor_sync(0xffffffffu, mx1, 2));

        const float mn0 = fmaxf(m0, mx0);
        const float mn1 = fmaxf(m1, mx1);
        const float co0 = __expf(m0 - mn0);
        const float co1 = __expf(m1 - mn1);
        m0 = mn0; m1 = mn1;

        float sum0 = 0.f, sum1 = 0.f;
        uint32_t ph01[8], ph23[8];
#pragma unroll
        for (int j = 0; j < 8; ++j) {
            const float p0 = __expf(sc[j][0] - mn0);
            const float p1 = __expf(sc[j][1] - mn0);
            const float p2 = __expf(sc[j][2] - mn1);
            const float p3 = __expf(sc[j][3] - mn1);
            sum0 += p0 + p1; sum1 += p2 + p3;
            ph01[j] = f2_to_h2u(p0, p1);
            ph23[j] = f2_to_h2u(p2, p3);
        }
        sum0 += __shfl_xor_sync(0xffffffffu, sum0, 1);
        sum0 += __shfl_xor_sync(0xffffffffu, sum0, 2);
        sum1 += __shfl_xor_sync(0xffffffffu, sum1, 1);
        sum1 += __shfl_xor_sync(0xffffffffu, sum1, 2);

        l0 = sum0 * co0 + sum0;   // BUG preserved from reference
        l1 = sum1 * co1 + sum1;

#pragma unroll
        for (int j = 0; j < 8; ++j) {
            acc[j][0] *= co0; acc[j][1] *= co0;
            acc[j][2] *= co1; acc[j][3] *= co1;
        }

#pragma unroll
        for (int s = 0; s < 4; ++s) {
            const uint32_t aP[4] = {ph01[2 * s], ph23[2 * s],
                                    ph01[2 * s + 1], ph23[2 * s + 1]};
#pragma unroll
            for (int dp = 0; dp < 4; ++dp) {
                uint32_t vf[4];
                ldsm4t(sVst + (uint32_t)(16 * s + kg8 + kq) * 144
                            + (uint32_t)(16 * dp + kg16) * 2, vf);
                mma_fp(acc[2 * dp],     aP, &vf[0]);
                mma_fp(acc[2 * dp + 1], aP, &vf[2]);
            }
        }
        __syncthreads();
    }

    // ---- epilogue: O = acc / l, written as fp16 hi/lo split ----
    const float inv0 = 1.f / l0;
    const float inv1 = 1.f / l1;
    const int row0 = q0 + 16 * w + (lane >> 2);
    const int colb = h * HDv + 2 * (lane & 3);
    __half* Ohb = Oh + (size_t)b * Sv * Ev;
    __half* Olb = Ol + (size_t)b * Sv * Ev;
#pragma unroll
    for (int j = 0; j < 8; ++j) {
        const int col = colb + 8 * j;
        const float o00 = acc[j][0] * inv0, o01 = acc[j][1] * inv0;
        const float o10 = acc[j][2] * inv1, o11 = acc[j][3] * inv1;
        const __half h00 = __float2half_rn(o00), h01 = __float2half_rn(o01);
        const __half h10 = __float2half_rn(o10), h11 = __float2half_rn(o11);
        const size_t i0 = (size_t)row0 * Ev + col;
        const size_t i1 = (size_t)(row0 + 8) * Ev + col;
        *reinterpret_cast<uint32_t*>(&Ohb[i0]) = f2_to_h2u(o00, o01);
        *reinterpret_cast<uint32_t*>(&Ohb[i1]) = f2_to_h2u(o10, o11);
        *reinterpret_cast<uint32_t*>(&Olb[i0]) =
            f2_to_h2u(o00 - __half2float(h00), o01 - __half2float(h01));
        *reinterpret_cast<uint32_t*>(&Olb[i1]) =
            f2_to_h2u(o10 - __half2float(h10), o11 - __half2float(h11));
    }
}

// ========================= launch ==========================================
extern "C" void kernel_launch(void* const* d_in, const int* in_sizes, int n_in,
                              void* d_out, int out_size)
{
    const float* x  = (const float*)d_in[0];
    const float* ws[4] = {(const float*)d_in[1], (const float*)d_in[2],
                          (const float*)d_in[3], (const float*)d_in[4]};
    const float* ob = (const float*)d_in[5];
    float* out = (float*)d_out;

    __half *Qh, *Kh, *Vh, *xh, *xl, *oh, *ol, *wf;
    cudaGetSymbolAddress((void**)&Qh, g_Qh);
    cudaGetSymbolAddress((void**)&Kh, g_Kh);
    cudaGetSymbolAddress((void**)&Vh, g_Vh);
    cudaGetSymbolAddress((void**)&xh, g_xh);
    cudaGetSymbolAddress((void**)&xl, g_xl);
    cudaGetSymbolAddress((void**)&oh, g_oh);
    cudaGetSymbolAddress((void**)&ol, g_ol);
    cudaGetSymbolAddress((void**)&wf, g_wf);

    const int M = Bv * Sv;
    const int nX4 = M * Ev / 4;
    const int nW4 = Ev * Ev / 4;

    split_h_kernel<<<nX4 / 256, 256>>>(x, xh, xl, nX4);
    for (int i = 0; i < 4; ++i)
        cvt_h_kernel<<<nW4 / 256, 256>>>(ws[i], wf + (size_t)i * Ev * Ev, nW4);

    cudaFuncSetAttribute(gemm_mma_kernel,
                         cudaFuncAttributeMaxDynamicSharedMemorySize, GEMM_SMEM);
    const dim3 ggrid(Ev / 128, M / 128);

    gemm_mma_kernel<<<ggrid, 256, GEMM_SMEM>>>(xh, xl, wf + 0 * (size_t)Ev * Ev,
        nullptr, nullptr, Qh, ATT_SCALE);
    gemm_mma_kernel<<<ggrid, 256, GEMM_SMEM>>>(xh, xl, wf + 1 * (size_t)Ev * Ev,
        nullptr, nullptr, Kh, 1.0f);
    gemm_mma_kernel<<<ggrid, 256, GEMM_SMEM>>>(xh, xl, wf + 2 * (size_t)Ev * Ev,
        nullptr, nullptr, Vh, 1.0f);

    cudaFuncSetAttribute(attn_tc_kernel,
                         cudaFuncAttributeMaxDynamicSharedMemorySize, ATT_SMEM);
    attn_tc_kernel<<<dim3(Bv * Hv, Sv / 128), 256, ATT_SMEM>>>(Qh, Kh, Vh, oh, ol);

    gemm_mma_kernel<<<ggrid, 256, GEMM_SMEM>>>(oh, ol, wf + 3 * (size_t)Ev * Ev,
        ob, out, nullptr, 1.0f);
}

// round 8
// speedup vs baseline: 6.2120x; 1.3996x over previous
#include <cuda_runtime.h>
#include <cuda_fp16.h>
#include <math_constants.h>
#include <cstdint>

// Problem constants
#define Bv 4
#define Sv 2048
#define Ev 1024
#define Hv 16
#define HDv 64
#define NKB (Sv / 64)
#define ATT_SCALE 0.125f

// ========================= PTX helpers =====================================
__device__ __forceinline__ uint32_t smem_u32(const void* p) {
    uint32_t a;
    asm("{ .reg .u64 t; cvta.to.shared.u64 t, %1; cvt.u32.u64 %0, t; }"
        : "=r"(a) : "l"(p));
    return a;
}
#define CP_ASYNC16(sa, ga) \
    asm volatile("cp.async.cg.shared.global [%0], [%1], 16;" :: "r"(sa), "l"(ga))
#define CP_COMMIT()  asm volatile("cp.async.commit_group;" ::: "memory")
#define CP_WAIT(n)   asm volatile("cp.async.wait_group %0;" :: "n"(n) : "memory")

__device__ __forceinline__ void ldsm4(uint32_t addr, uint32_t r[4]) {
    asm volatile("ldmatrix.sync.aligned.m8n8.x4.shared.b16 {%0,%1,%2,%3}, [%4];"
                 : "=r"(r[0]), "=r"(r[1]), "=r"(r[2]), "=r"(r[3]) : "r"(addr));
}
__device__ __forceinline__ void ldsm4t(uint32_t addr, uint32_t r[4]) {
    asm volatile("ldmatrix.sync.aligned.m8n8.x4.trans.shared.b16 {%0,%1,%2,%3}, [%4];"
                 : "=r"(r[0]), "=r"(r[1]), "=r"(r[2]), "=r"(r[3]) : "r"(addr));
}
// fp16 mma, fp32 accum
__device__ __forceinline__ void mma_fp(float c[4], const uint32_t a[4],
                                       const uint32_t b[2]) {
    asm volatile(
        "mma.sync.aligned.m16n8k16.row.col.f32.f16.f16.f32 "
        "{%0,%1,%2,%3}, {%4,%5,%6,%7}, {%8,%9}, {%0,%1,%2,%3};"
        : "+f"(c[0]), "+f"(c[1]), "+f"(c[2]), "+f"(c[3])
        : "r"(a[0]), "r"(a[1]), "r"(a[2]), "r"(a[3]), "r"(b[0]), "r"(b[1]));
}
// pack two floats -> fp16x2 in a u32 register
__device__ __forceinline__ uint32_t f2_to_h2u(float lo, float hi) {
    uint32_t r;
    asm("cvt.rn.f16x2.f32 %0, %1, %2;" : "=r"(r) : "f"(hi), "f"(lo));
    return r;
}

// ========================= static device scratch ===========================
__device__ __half g_Qh[(size_t)Bv * Sv * Ev];
__device__ __half g_Kh[(size_t)Bv * Sv * Ev];
__device__ __half g_Vh[(size_t)Bv * Sv * Ev];
__device__ __half g_xf[(size_t)Bv * Sv * Ev];
__device__ __half g_oh[(size_t)Bv * Sv * Ev];
__device__ __half g_ol[(size_t)Bv * Sv * Ev];
__device__ __half g_wf[4][(size_t)Ev * Ev];

// ========================= fp32 -> fp16 converts ===========================
__global__ void cvt_h_kernel(const float* __restrict__ src,
                             __half* __restrict__ dst, int n4)
{
    int i = blockIdx.x * blockDim.x + threadIdx.x;
    if (i >= n4) return;
    float4 v = reinterpret_cast<const float4*>(src)[i];
    uint32_t* dp = reinterpret_cast<uint32_t*>(dst) + 2 * i;
    dp[0] = f2_to_h2u(v.x, v.y);
    dp[1] = f2_to_h2u(v.z, v.w);
}

__global__ void cvt4_kernel(const float* __restrict__ w0,
                            const float* __restrict__ w1,
                            const float* __restrict__ w2,
                            const float* __restrict__ w3,
                            __half* __restrict__ dst, int n4)
{
    const float* srcs[4] = {w0, w1, w2, w3};
    const float* s = srcs[blockIdx.y];
    __half* d = dst + (size_t)blockIdx.y * Ev * Ev;
    int i = blockIdx.x * blockDim.x + threadIdx.x;
    if (i >= n4) return;
    float4 v = reinterpret_cast<const float4*>(s)[i];
    uint32_t* dp = reinterpret_cast<uint32_t*>(d) + 2 * i;
    dp[0] = f2_to_h2u(v.x, v.y);
    dp[1] = f2_to_h2u(v.z, v.w);
}

// ========================= shared GEMM config ==============================
#define BK 32
#define ROWB 80
#define TILE_BYTES (128 * ROWB)
#define NCHW (Ev / BK)

// ========================= fused QKV GEMM (single-product fp16) ============
// z = blockIdx.z selects weight slab + output + premul.
#define STAGE_S (2 * TILE_BYTES)     // A, B
#define QKV_SMEM (2 * STAGE_S)       // 40960

__device__ __forceinline__ void load_stage_s(
    uint32_t sbase, int stage, int kc,
    const __half* A, const __half* B, int m0, int n0, int tid)
{
    const uint32_t st = sbase + stage * STAGE_S;
    const __half* srcs[2] = {A, B};
    const int row0[2] = {m0, n0};
#pragma unroll
    for (int t = 0; t < 2; ++t) {
#pragma unroll
        for (int p = 0; p < 2; ++p) {
            const int i = p * 256 + tid;
            const int r = i >> 2;
            const int c = i & 3;
            const __half* g =
                srcs[t] + (size_t)(row0[t] + r) * Ev + kc * BK + c * 8;
            CP_ASYNC16(st + t * TILE_BYTES + r * ROWB + c * 16, g);
        }
    }
}

__global__ __launch_bounds__(256, 2)
void gemm_qkv_kernel(const __half* __restrict__ A, const __half* __restrict__ W,
                     __half* __restrict__ Qo, __half* __restrict__ Ko,
                     __half* __restrict__ Vo)
{
    extern __shared__ __align__(128) char smem[];
    const uint32_t sb = smem_u32(smem);
    const int tid = threadIdx.x;
    const int wid = tid >> 5, lane = tid & 31;
    const int warp_m = wid & 3, warp_n = wid >> 2;
    const int m0 = blockIdx.y << 7;
    const int n0 = blockIdx.x << 7;
    const int z  = blockIdx.z;

    const __half* B = W + (size_t)z * Ev * Ev;
    __half* Out = (z == 0) ? Qo : ((z == 1) ? Ko : Vo);
    const float premul = (z == 0) ? ATT_SCALE : 1.0f;

    float acc[2][8][4];
#pragma unroll
    for (int mt = 0; mt < 2; ++mt)
#pragma unroll
        for (int nt = 0; nt < 8; ++nt)
#pragma unroll
            for (int q = 0; q < 4; ++q) acc[mt][nt][q] = 0.f;

    load_stage_s(sb, 0, 0, A, B, m0, n0, tid);
    CP_COMMIT();

    const int arow = warp_m * 32 + (lane & 15);
    const uint32_t acol16 = (uint32_t)((lane >> 4) << 4);
    const int nrow = warp_n * 64 + (((lane >> 4) & 1) << 3) + (lane & 7);
    const uint32_t bcol16 = (uint32_t)(((lane >> 3) & 1) << 4);

    for (int c = 0; c < NCHW; ++c) {
        const int s = c & 1;
        if (c + 1 < NCHW) {
            load_stage_s(sb, s ^ 1, c + 1, A, B, m0, n0, tid);
            CP_COMMIT();
            CP_WAIT(1);
        } else {
            CP_WAIT(0);
        }
        __syncthreads();

        const uint32_t stA = sb + s * STAGE_S;
        const uint32_t stB = stA + TILE_BYTES;

#pragma unroll
        for (int ks = 0; ks < 2; ++ks) {
            const uint32_t kofs = ks * 32;
            uint32_t a[2][4], b[4][4];
#pragma unroll
            for (int p = 0; p < 4; ++p)
                ldsm4(stB + (uint32_t)(nrow + p * 16) * ROWB + kofs + bcol16, b[p]);
            ldsm4(stA + (uint32_t)arow * ROWB + kofs + acol16, a[0]);
            ldsm4(stA + (uint32_t)(arow + 16) * ROWB + kofs + acol16, a[1]);
#pragma unroll
            for (int mt = 0; mt < 2; ++mt)
#pragma unroll
                for (int nt = 0; nt < 8; ++nt)
                    mma_fp(acc[mt][nt], a[mt], &b[nt >> 1][(nt & 1) * 2]);
        }
        __syncthreads();
    }

    const int tr = lane >> 2;
    const int tc = (lane & 3) * 2;
    const int mb = m0 + warp_m * 32;
    const int nb = n0 + warp_n * 64;
#pragma unroll
    for (int mt = 0; mt < 2; ++mt) {
#pragma unroll
        for (int nt = 0; nt < 8; ++nt) {
            const int col = nb + nt * 8 + tc;
            const size_t r0 = (size_t)(mb + mt * 16 + tr) * Ev + col;
            const size_t r1 = (size_t)(mb + mt * 16 + tr + 8) * Ev + col;
            *reinterpret_cast<uint32_t*>(&Out[r0]) =
                f2_to_h2u(acc[mt][nt][0] * premul, acc[mt][nt][1] * premul);
            *reinterpret_cast<uint32_t*>(&Out[r1]) =
                f2_to_h2u(acc[mt][nt][2] * premul, acc[mt][nt][3] * premul);
        }
    }
}

// ========================= out-proj GEMM (fp16 2-product, A split) =========
#define STAGE_BYTES (3 * TILE_BYTES)     // Ah, Al, B
#define GEMM_SMEM (2 * STAGE_BYTES)      // 61440

__device__ __forceinline__ void load_stage(
    uint32_t sbase, int stage, int kc,
    const __half* Ah, const __half* Al, const __half* B,
    int m0, int n0, int tid)
{
    const uint32_t st = sbase + stage * STAGE_BYTES;
    const __half* srcs[3] = {Ah, Al, B};
    const int row0[3] = {m0, m0, n0};
#pragma unroll
    for (int t = 0; t < 3; ++t) {
#pragma unroll
        for (int p = 0; p < 2; ++p) {
            const int i = p * 256 + tid;
            const int r = i >> 2;
            const int c = i & 3;
            const __half* g =
                srcs[t] + (size_t)(row0[t] + r) * Ev + kc * BK + c * 8;
            CP_ASYNC16(st + t * TILE_BYTES + r * ROWB + c * 16, g);
        }
    }
}

__global__ __launch_bounds__(256, 1)
void gemm_mma_kernel(const __half* __restrict__ Ah,
                     const __half* __restrict__ Al,
                     const __half* __restrict__ B,
                     const float* __restrict__ bias,
                     float* __restrict__ C)
{
    extern __shared__ __align__(128) char smem[];
    const uint32_t sb = smem_u32(smem);
    const int tid = threadIdx.x;
    const int wid = tid >> 5, lane = tid & 31;
    const int warp_m = wid & 3, warp_n = wid >> 2;
    const int m0 = blockIdx.y << 7;
    const int n0 = blockIdx.x << 7;

    float acc[2][8][4];
#pragma unroll
    for (int mt = 0; mt < 2; ++mt)
#pragma unroll
        for (int nt = 0; nt < 8; ++nt)
#pragma unroll
            for (int q = 0; q < 4; ++q) acc[mt][nt][q] = 0.f;

    load_stage(sb, 0, 0, Ah, Al, B, m0, n0, tid);
    CP_COMMIT();

    const int arow = warp_m * 32 + (lane & 15);
    const uint32_t acol16 = (uint32_t)((lane >> 4) << 4);
    const int nrow = warp_n * 64 + (((lane >> 4) & 1) << 3) + (lane & 7);
    const uint32_t bcol16 = (uint32_t)(((lane >> 3) & 1) << 4);

    for (int c = 0; c < NCHW; ++c) {
        const int s = c & 1;
        if (c + 1 < NCHW) {
            load_stage(sb, s ^ 1, c + 1, Ah, Al, B, m0, n0, tid);
            CP_COMMIT();
            CP_WAIT(1);
        } else {
            CP_WAIT(0);
        }
        __syncthreads();

        const uint32_t stAh = sb + s * STAGE_BYTES;
        const uint32_t stAl = stAh + TILE_BYTES;
        const uint32_t stB  = stAh + 2 * TILE_BYTES;

#pragma unroll
        for (int ks = 0; ks < 2; ++ks) {
            const uint32_t kofs = ks * 32;
            uint32_t a[2][4], a2[2][4], b[4][4];
#pragma unroll
            for (int p = 0; p < 4; ++p)
                ldsm4(stB + (uint32_t)(nrow + p * 16) * ROWB + kofs + bcol16, b[p]);
            ldsm4(stAh + (uint32_t)arow * ROWB + kofs + acol16, a[0]);
            ldsm4(stAh + (uint32_t)(arow + 16) * ROWB + kofs + acol16, a[1]);
#pragma unroll
            for (int mt = 0; mt < 2; ++mt)
#pragma unroll
                for (int nt = 0; nt < 8; ++nt)
                    mma_fp(acc[mt][nt], a[mt], &b[nt >> 1][(nt & 1) * 2]);

            ldsm4(stAl + (uint32_t)arow * ROWB + kofs + acol16, a2[0]);
            ldsm4(stAl + (uint32_t)(arow + 16) * ROWB + kofs + acol16, a2[1]);
#pragma unroll
            for (int mt = 0; mt < 2; ++mt)
#pragma unroll
                for (int nt = 0; nt < 8; ++nt)
                    mma_fp(acc[mt][nt], a2[mt], &b[nt >> 1][(nt & 1) * 2]);
        }
        __syncthreads();
    }

    const int tr = lane >> 2;
    const int tc = (lane & 3) * 2;
    const int mb = m0 + warp_m * 32;
    const int nb = n0 + warp_n * 64;
#pragma unroll
    for (int mt = 0; mt < 2; ++mt) {
#pragma unroll
        for (int nt = 0; nt < 8; ++nt) {
            const int col = nb + nt * 8 + tc;
            const float b0 = bias[col], b1 = bias[col + 1];
            const size_t r0 = (size_t)(mb + mt * 16 + tr) * Ev + col;
            const size_t r1 = (size_t)(mb + mt * 16 + tr + 8) * Ev + col;
            float2 v0 = {acc[mt][nt][0] + b0, acc[mt][nt][1] + b1};
            float2 v1 = {acc[mt][nt][2] + b0, acc[mt][nt][3] + b1};
            *reinterpret_cast<float2*>(&C[r0]) = v0;
            *reinterpret_cast<float2*>(&C[r1]) = v1;
        }
    }
}

// ========================= tensor-core flash attention =====================
// fp16 single-product. Q pre-scaled by 0.125 (exact). Buggy l preserved.
// Epilogue writes O as fp16 hi/lo split directly (error 2^-22).
#define AROW 72
#define ATT_SMEM ((128 + 2*64 + 2*64) * AROW * 2)   // 55296 B

__global__ __launch_bounds__(256, 2)
void attn_tc_kernel(const __half* __restrict__ Q, const __half* __restrict__ K,
                    const __half* __restrict__ V,
                    __half* __restrict__ Oh, __half* __restrict__ Ol)
{
    extern __shared__ __align__(128) char smem[];
    const uint32_t sb = smem_u32(smem);
    const uint32_t sQ = sb;
    const uint32_t sK = sQ + 128 * AROW * 2;
    const uint32_t sV = sK + 2 * 64 * AROW * 2;

    const int tid = threadIdx.x;
    const int w = tid >> 5, lane = tid & 31;
    const int b  = blockIdx.x >> 4;
    const int h  = blockIdx.x & 15;
    const int q0 = blockIdx.y << 7;

    const __half* Qg = Q + ((size_t)b * Sv + q0) * Ev + h * HDv;
    const __half* Kg = K + (size_t)b * Sv * Ev + h * HDv;
    const __half* Vg = V + (size_t)b * Sv * Ev + h * HDv;

    for (int i = tid; i < 1024; i += 256) {
        const int r = i >> 3, c = i & 7;
        CP_ASYNC16(sQ + r * 144 + c * 16, Qg + (size_t)r * Ev + c * 8);
    }
    for (int i = tid; i < 512; i += 256) {
        const int r = i >> 3, c = i & 7;
        CP_ASYNC16(sK + r * 144 + c * 16, Kg + (size_t)r * Ev + c * 8);
        CP_ASYNC16(sV + r * 144 + c * 16, Vg + (size_t)r * Ev + c * 8);
    }
    CP_COMMIT();

    float acc[8][4];
#pragma unroll
    for (int j = 0; j < 8; ++j)
#pragma unroll
        for (int q = 0; q < 4; ++q) acc[j][q] = 0.f;
    float m0 = -CUDART_INF_F, m1 = -CUDART_INF_F;
    float l0 = 0.f, l1 = 0.f;

    uint32_t aQ[4][4];
    bool qLoaded = false;

    const uint32_t q_addr0 = sQ + (uint32_t)(16 * w + (lane & 15)) * 144
                                + ((lane >> 4) << 4);
    const int kq = lane & 7;
    const int kg16 = (lane >> 4) << 3;
    const int kg8  = ((lane >> 3) & 1) << 3;

    for (int kb = 0; kb < NKB; ++kb) {
        const int st = kb & 1;
        if (kb + 1 < NKB) {
            const int sn = st ^ 1;
            const __half* Kp = Kg + (size_t)((kb + 1) * 64) * Ev;
            const __half* Vp = Vg + (size_t)((kb + 1) * 64) * Ev;
            for (int i = tid; i < 512; i += 256) {
                const int r = i >> 3, c = i & 7;
                CP_ASYNC16(sK + (sn * 64 + r) * 144 + c * 16, Kp + (size_t)r * Ev + c * 8);
                CP_ASYNC16(sV + (sn * 64 + r) * 144 + c * 16, Vp + (size_t)r * Ev + c * 8);
            }
            CP_COMMIT();
            CP_WAIT(1);
        } else {
            CP_WAIT(0);
        }
        __syncthreads();

        if (!qLoaded) {
#pragma unroll
            for (int s = 0; s < 4; ++s) ldsm4(q_addr0 + s * 32, aQ[s]);
            qLoaded = true;
        }

        const uint32_t sKst = sK + (uint32_t)st * 64 * 144;
        const uint32_t sVst = sV + (uint32_t)st * 64 * 144;

        float sc[8][4];
#pragma unroll
        for (int j = 0; j < 8; ++j)
#pragma unroll
            for (int q = 0; q < 4; ++q) sc[j][q] = 0.f;

#pragma unroll
        for (int p = 0; p < 4; ++p) {
#pragma unroll
            for (int s = 0; s < 4; ++s) {
                uint32_t kf[4];
                ldsm4(sKst + (uint32_t)(16 * p + kg16 + kq) * 144
                           + (uint32_t)(16 * s + kg8) * 2, kf);
                mma_fp(sc[2 * p],     aQ[s], &kf[0]);
                mma_fp(sc[2 * p + 1], aQ[s], &kf[2]);
            }
        }

        float mx0 = -CUDART_INF_F, mx1 = -CUDART_INF_F;
#pragma unroll
        for (int j = 0; j < 8; ++j) {
            mx0 = fmaxf(mx0, fmaxf(sc[j][0], sc[j][1]));
            mx1 = fmaxf(mx1, fmaxf(sc[j][2], sc[j][3]));
        }
        mx0 = fmaxf(mx0, __shfl_xor_sync(0xffffffffu, mx0, 1));
        mx0 = fmaxf(mx0, __shfl_xor_sync(0xffffffffu, mx0, 2));
        mx1 = fmaxf(mx1, __shfl_xor_sync(0xffffffffu, mx1, 1));
        mx1 = fmaxf(mx1, __shfl_xor_sync(0xffffffffu, mx1, 2));

        const float mn0 = fmaxf(m0, mx0);
        const float mn1 = fmaxf(m1, mx1);
        const float co0 = __expf(m0 - mn0);
        const float co1 = __expf(m1 - mn1);
        m0 = mn0; m1 = mn1;

        float sum0 = 0.f, sum1 = 0.f;
        uint32_t ph01[8], ph23[8];
#pragma unroll
        for (int j = 0; j < 8; ++j) {
            const float p0 = __expf(sc[j][0] - mn0);
            const float p1 = __expf(sc[j][1] - mn0);
            const float p2 = __expf(sc[j][2] - mn1);
            const float p3 = __expf(sc[j][3] - mn1);
            sum0 += p0 + p1; sum1 += p2 + p3;
            ph01[j] = f2_to_h2u(p0, p1);
            ph23[j] = f2_to_h2u(p2, p3);
        }
        sum0 += __shfl_xor_sync(0xffffffffu, sum0, 1);
        sum0 += __shfl_xor_sync(0xffffffffu, sum0, 2);
        sum1 += __shfl_xor_sync(0xffffffffu, sum1, 1);
        sum1 += __shfl_xor_sync(0xffffffffu, sum1, 2);

        l0 = sum0 * co0 + sum0;   // BUG preserved from reference
        l1 = sum1 * co1 + sum1;

#pragma unroll
        for (int j = 0; j < 8; ++j) {
            acc[j][0] *= co0; acc[j][1] *= co0;
            acc[j][2] *= co1; acc[j][3] *= co1;
        }

#pragma unroll
        for (int s = 0; s < 4; ++s) {
            const uint32_t aP[4] = {ph01[2 * s], ph23[2 * s],
                                    ph01[2 * s + 1], ph23[2 * s + 1]};
#pragma unroll
            for (int dp = 0; dp < 4; ++dp) {
                uint32_t vf[4];
                ldsm4t(sVst + (uint32_t)(16 * s + kg8 + kq) * 144
                            + (uint32_t)(16 * dp + kg16) * 2, vf);
                mma_fp(acc[2 * dp],     aP, &vf[0]);
                mma_fp(acc[2 * dp + 1], aP, &vf[2]);
            }
        }
        __syncthreads();
    }

    // ---- epilogue: O = acc / l, written as fp16 hi/lo split ----
    const float inv0 = 1.f / l0;
    const float inv1 = 1.f / l1;
    const int row0 = q0 + 16 * w + (lane >> 2);
    const int colb = h * HDv + 2 * (lane & 3);
    __half* Ohb = Oh + (size_t)b * Sv * Ev;
    __half* Olb = Ol + (size_t)b * Sv * Ev;
#pragma unroll
    for (int j = 0; j < 8; ++j) {
        const int col = colb + 8 * j;
        const float o00 = acc[j][0] * inv0, o01 = acc[j][1] * inv0;
        const float o10 = acc[j][2] * inv1, o11 = acc[j][3] * inv1;
        const __half h00 = __float2half_rn(o00), h01 = __float2half_rn(o01);
        const __half h10 = __float2half_rn(o10), h11 = __float2half_rn(o11);
        const size_t i0 = (size_t)row0 * Ev + col;
        const size_t i1 = (size_t)(row0 + 8) * Ev + col;
        *reinterpret_cast<uint32_t*>(&Ohb[i0]) = f2_to_h2u(o00, o01);
        *reinterpret_cast<uint32_t*>(&Ohb[i1]) = f2_to_h2u(o10, o11);
        *reinterpret_cast<uint32_t*>(&Olb[i0]) =
            f2_to_h2u(o00 - __half2float(h00), o01 - __half2float(h01));
        *reinterpret_cast<uint32_t*>(&Olb[i1]) =
            f2_to_h2u(o10 - __half2float(h10), o11 - __half2float(h11));
    }
}

// ========================= launch ==========================================
extern "C" void kernel_launch(void* const* d_in, const int* in_sizes, int n_in,
                              void* d_out, int out_size)
{
    const float* x  = (const float*)d_in[0];
    const float* qw = (const float*)d_in[1];
    const float* kw = (const float*)d_in[2];
    const float* vw = (const float*)d_in[3];
    const float* ow = (const float*)d_in[4];
    const float* ob = (const float*)d_in[5];
    float* out = (float*)d_out;

    __half *Qh, *Kh, *Vh, *xf, *oh, *ol, *wf;
    cudaGetSymbolAddress((void**)&Qh, g_Qh);
    cudaGetSymbolAddress((void**)&Kh, g_Kh);
    cudaGetSymbolAddress((void**)&Vh, g_Vh);
    cudaGetSymbolAddress((void**)&xf, g_xf);
    cudaGetSymbolAddress((void**)&oh, g_oh);
    cudaGetSymbolAddress((void**)&ol, g_ol);
    cudaGetSymbolAddress((void**)&wf, g_wf);

    const int M = Bv * Sv;
    const int nX4 = M * Ev / 4;
    const int nW4 = Ev * Ev / 4;

    cvt_h_kernel<<<nX4 / 256, 256>>>(x, xf, nX4);
    cvt4_kernel<<<dim3(nW4 / 256, 4), 256>>>(qw, kw, vw, ow, wf, nW4);

    cudaFuncSetAttribute(gemm_qkv_kernel,
                         cudaFuncAttributeMaxDynamicSharedMemorySize, QKV_SMEM);
    cudaFuncSetAttribute(gemm_mma_kernel,
                         cudaFuncAttributeMaxDynamicSharedMemorySize, GEMM_SMEM);

    gemm_qkv_kernel<<<dim3(Ev / 128, M / 128, 3), 256, QKV_SMEM>>>(
        xf, wf, Qh, Kh, Vh);

    cudaFuncSetAttribute(attn_tc_kernel,
                         cudaFuncAttributeMaxDynamicSharedMemorySize, ATT_SMEM);
    attn_tc_kernel<<<dim3(Bv * Hv, Sv / 128), 256, ATT_SMEM>>>(Qh, Kh, Vh, oh, ol);

    gemm_mma_kernel<<<dim3(Ev / 128, M / 128), 256, GEMM_SMEM>>>(
        oh, ol, wf + 3 * (size_t)Ev * Ev, ob, out);
}

// round 9
// speedup vs baseline: 7.3455x; 1.1825x over previous
#include <cuda_runtime.h>
#include <cuda_fp16.h>
#include <math_constants.h>
#include <cstdint>

// Problem constants
#define Bv 4
#define Sv 2048
#define Ev 1024
#define Hv 16
#define HDv 64
#define NKB (Sv / 64)
#define ATT_SCALE 0.125f

// ========================= PTX helpers =====================================
__device__ __forceinline__ uint32_t smem_u32(const void* p) {
    uint32_t a;
    asm("{ .reg .u64 t; cvta.to.shared.u64 t, %1; cvt.u32.u64 %0, t; }"
        : "=r"(a) : "l"(p));
    return a;
}
#define CP_ASYNC16(sa, ga) \
    asm volatile("cp.async.cg.shared.global [%0], [%1], 16;" :: "r"(sa), "l"(ga))
#define CP_COMMIT()  asm volatile("cp.async.commit_group;" ::: "memory")
#define CP_WAIT(n)   asm volatile("cp.async.wait_group %0;" :: "n"(n) : "memory")

#define MBAR_INIT(addr, cnt) \
    asm volatile("mbarrier.init.shared.b64 [%0], %1;" :: "r"(addr), "r"((uint32_t)(cnt)) : "memory")
#define MBAR_ARRIVE(addr) \
    asm volatile("mbarrier.arrive.shared.b64 _, [%0];" :: "r"(addr) : "memory")
// arrive on mbar when ALL prior cp.asyncs of this thread complete
#define CPA_ARRIVE(addr) \
    asm volatile("cp.async.mbarrier.arrive.noinc.shared.b64 [%0];" :: "r"(addr) : "memory")
#define MBAR_WAIT(addr, ph) \
    asm volatile("{\n\t.reg .pred P;\n" \
                 "WL_%=:\n\t" \
                 "mbarrier.try_wait.parity.acquire.cta.shared::cta.b64 P, [%0], %1;\n\t" \
                 "@!P bra WL_%=;\n\t}" \
                 :: "r"(addr), "r"((uint32_t)(ph)) : "memory")

__device__ __forceinline__ void ldsm4(uint32_t addr, uint32_t r[4]) {
    asm volatile("ldmatrix.sync.aligned.m8n8.x4.shared.b16 {%0,%1,%2,%3}, [%4];"
                 : "=r"(r[0]), "=r"(r[1]), "=r"(r[2]), "=r"(r[3]) : "r"(addr));
}
__device__ __forceinline__ void ldsm4t(uint32_t addr, uint32_t r[4]) {
    asm volatile("ldmatrix.sync.aligned.m8n8.x4.trans.shared.b16 {%0,%1,%2,%3}, [%4];"
                 : "=r"(r[0]), "=r"(r[1]), "=r"(r[2]), "=r"(r[3]) : "r"(addr));
}
__device__ __forceinline__ void mma_fp(float c[4], const uint32_t a[4],
                                       const uint32_t b[2]) {
    asm volatile(
        "mma.sync.aligned.m16n8k16.row.col.f32.f16.f16.f32 "
        "{%0,%1,%2,%3}, {%4,%5,%6,%7}, {%8,%9}, {%0,%1,%2,%3};"
        : "+f"(c[0]), "+f"(c[1]), "+f"(c[2]), "+f"(c[3])
        : "r"(a[0]), "r"(a[1]), "r"(a[2]), "r"(a[3]), "r"(b[0]), "r"(b[1]));
}
__device__ __forceinline__ uint32_t f2_to_h2u(float lo, float hi) {
    uint32_t r;
    asm("cvt.rn.f16x2.f32 %0, %1, %2;" : "=r"(r) : "f"(hi), "f"(lo));
    return r;
}

// ========================= static device scratch ===========================
__device__ __half g_Qh[(size_t)Bv * Sv * Ev];
__device__ __half g_Kh[(size_t)Bv * Sv * Ev];
__device__ __half g_Vh[(size_t)Bv * Sv * Ev];
__device__ __half g_xf[(size_t)Bv * Sv * Ev];
__device__ __half g_of[(size_t)Bv * Sv * Ev];
__device__ __half g_wf[4][(size_t)Ev * Ev];

// ========================= fp32 -> fp16 converts ===========================
__global__ void cvt_h_kernel(const float* __restrict__ src,
                             __half* __restrict__ dst, int n4)
{
    int i = blockIdx.x * blockDim.x + threadIdx.x;
    if (i >= n4) return;
    float4 v = reinterpret_cast<const float4*>(src)[i];
    uint32_t* dp = reinterpret_cast<uint32_t*>(dst) + 2 * i;
    dp[0] = f2_to_h2u(v.x, v.y);
    dp[1] = f2_to_h2u(v.z, v.w);
}

__global__ void cvt4_kernel(const float* __restrict__ w0,
                            const float* __restrict__ w1,
                            const float* __restrict__ w2,
                            const float* __restrict__ w3,
                            __half* __restrict__ dst, int n4)
{
    const float* srcs[4] = {w0, w1, w2, w3};
    const float* s = srcs[blockIdx.y];
    __half* d = dst + (size_t)blockIdx.y * Ev * Ev;
    int i = blockIdx.x * blockDim.x + threadIdx.x;
    if (i >= n4) return;
    float4 v = reinterpret_cast<const float4*>(s)[i];
    uint32_t* dp = reinterpret_cast<uint32_t*>(d) + 2 * i;
    dp[0] = f2_to_h2u(v.x, v.y);
    dp[1] = f2_to_h2u(v.z, v.w);
}

// ========================= shared GEMM config ==============================
#define BK 32
#define ROWB 80
#define TILE_BYTES (128 * ROWB)
#define NCHW (Ev / BK)
#define STAGE_S (2 * TILE_BYTES)
#define GEMM_SMEM (2 * STAGE_S)     // 40960

__device__ __forceinline__ void load_stage_s(
    uint32_t sbase, int stage, int kc,
    const __half* A, const __half* B, int m0, int n0, int tid)
{
    const uint32_t st = sbase + stage * STAGE_S;
    const __half* srcs[2] = {A, B};
    const int row0[2] = {m0, n0};
#pragma unroll
    for (int t = 0; t < 2; ++t) {
#pragma unroll
        for (int p = 0; p < 2; ++p) {
            const int i = p * 256 + tid;
            const int r = i >> 2;
            const int c = i & 3;
            const __half* g =
                srcs[t] + (size_t)(row0[t] + r) * Ev + kc * BK + c * 8;
            CP_ASYNC16(st + t * TILE_BYTES + r * ROWB + c * 16, g);
        }
    }
}

// ========================= fused QKV GEMM (single-product fp16) ============
__global__ __launch_bounds__(256, 2)
void gemm_qkv_kernel(const __half* __restrict__ A, const __half* __restrict__ W,
                     __half* __restrict__ Qo, __half* __restrict__ Ko,
                     __half* __restrict__ Vo)
{
    extern __shared__ __align__(128) char smem[];
    const uint32_t sb = smem_u32(smem);
    const int tid = threadIdx.x;
    const int wid = tid >> 5, lane = tid & 31;
    const int warp_m = wid & 3, warp_n = wid >> 2;
    const int m0 = blockIdx.y << 7;
    const int n0 = blockIdx.x << 7;
    const int z  = blockIdx.z;

    const __half* B = W + (size_t)z * Ev * Ev;
    __half* Out = (z == 0) ? Qo : ((z == 1) ? Ko : Vo);
    const float premul = (z == 0) ? ATT_SCALE : 1.0f;

    float acc[2][8][4];
#pragma unroll
    for (int mt = 0; mt < 2; ++mt)
#pragma unroll
        for (int nt = 0; nt < 8; ++nt)
#pragma unroll
            for (int q = 0; q < 4; ++q) acc[mt][nt][q] = 0.f;

    load_stage_s(sb, 0, 0, A, B, m0, n0, tid);
    CP_COMMIT();

    const int arow = warp_m * 32 + (lane & 15);
    const uint32_t acol16 = (uint32_t)((lane >> 4) << 4);
    const int nrow = warp_n * 64 + (((lane >> 4) & 1) << 3) + (lane & 7);
    const uint32_t bcol16 = (uint32_t)(((lane >> 3) & 1) << 4);

    for (int c = 0; c < NCHW; ++c) {
        const int s = c & 1;
        if (c + 1 < NCHW) {
            load_stage_s(sb, s ^ 1, c + 1, A, B, m0, n0, tid);
            CP_COMMIT();
            CP_WAIT(1);
        } else {
            CP_WAIT(0);
        }
        __syncthreads();

        const uint32_t stA = sb + s * STAGE_S;
        const uint32_t stB = stA + TILE_BYTES;

#pragma unroll
        for (int ks = 0; ks < 2; ++ks) {
            const uint32_t kofs = ks * 32;
            uint32_t a[2][4], b[4][4];
#pragma unroll
            for (int p = 0; p < 4; ++p)
                ldsm4(stB + (uint32_t)(nrow + p * 16) * ROWB + kofs + bcol16, b[p]);
            ldsm4(stA + (uint32_t)arow * ROWB + kofs + acol16, a[0]);
            ldsm4(stA + (uint32_t)(arow + 16) * ROWB + kofs + acol16, a[1]);
#pragma unroll
            for (int mt = 0; mt < 2; ++mt)
#pragma unroll
                for (int nt = 0; nt < 8; ++nt)
                    mma_fp(acc[mt][nt], a[mt], &b[nt >> 1][(nt & 1) * 2]);
        }
        __syncthreads();
    }

    const int tr = lane >> 2;
    const int tc = (lane & 3) * 2;
    const int mb = m0 + warp_m * 32;
    const int nb = n0 + warp_n * 64;
#pragma unroll
    for (int mt = 0; mt < 2; ++mt) {
#pragma unroll
        for (int nt = 0; nt < 8; ++nt) {
            const int col = nb + nt * 8 + tc;
            const size_t r0 = (size_t)(mb + mt * 16 + tr) * Ev + col;
            const size_t r1 = (size_t)(mb + mt * 16 + tr + 8) * Ev + col;
            *reinterpret_cast<uint32_t*>(&Out[r0]) =
                f2_to_h2u(acc[mt][nt][0] * premul, acc[mt][nt][1] * premul);
            *reinterpret_cast<uint32_t*>(&Out[r1]) =
                f2_to_h2u(acc[mt][nt][2] * premul, acc[mt][nt][3] * premul);
        }
    }
}

// ========================= out-proj GEMM (single-product, fp32+bias) =======
__global__ __launch_bounds__(256, 2)
void gemm_out_kernel(const __half* __restrict__ A, const __half* __restrict__ B,
                     const float* __restrict__ bias, float* __restrict__ C)
{
    extern __shared__ __align__(128) char smem[];
    const uint32_t sb = smem_u32(smem);
    const int tid = threadIdx.x;
    const int wid = tid >> 5, lane = tid & 31;
    const int warp_m = wid & 3, warp_n = wid >> 2;
    const int m0 = blockIdx.y << 7;
    const int n0 = blockIdx.x << 7;

    float acc[2][8][4];
#pragma unroll
    for (int mt = 0; mt < 2; ++mt)
#pragma unroll
        for (int nt = 0; nt < 8; ++nt)
#pragma unroll
            for (int q = 0; q < 4; ++q) acc[mt][nt][q] = 0.f;

    load_stage_s(sb, 0, 0, A, B, m0, n0, tid);
    CP_COMMIT();

    const int arow = warp_m * 32 + (lane & 15);
    const uint32_t acol16 = (uint32_t)((lane >> 4) << 4);
    const int nrow = warp_n * 64 + (((lane >> 4) & 1) << 3) + (lane & 7);
    const uint32_t bcol16 = (uint32_t)(((lane >> 3) & 1) << 4);

    for (int c = 0; c < NCHW; ++c) {
        const int s = c & 1;
        if (c + 1 < NCHW) {
            load_stage_s(sb, s ^ 1, c + 1, A, B, m0, n0, tid);
            CP_COMMIT();
            CP_WAIT(1);
        } else {
            CP_WAIT(0);
        }
        __syncthreads();

        const uint32_t stA = sb + s * STAGE_S;
        const uint32_t stB = stA + TILE_BYTES;

#pragma unroll
        for (int ks = 0; ks < 2; ++ks) {
            const uint32_t kofs = ks * 32;
            uint32_t a[2][4], b[4][4];
#pragma unroll
            for (int p = 0; p < 4; ++p)
                ldsm4(stB + (uint32_t)(nrow + p * 16) * ROWB + kofs + bcol16, b[p]);
            ldsm4(stA + (uint32_t)arow * ROWB + kofs + acol16, a[0]);
            ldsm4(stA + (uint32_t)(arow + 16) * ROWB + kofs + acol16, a[1]);
#pragma unroll
            for (int mt = 0; mt < 2; ++mt)
#pragma unroll
                for (int nt = 0; nt < 8; ++nt)
                    mma_fp(acc[mt][nt], a[mt], &b[nt >> 1][(nt & 1) * 2]);
        }
        __syncthreads();
    }

    const int tr = lane >> 2;
    const int tc = (lane & 3) * 2;
    const int mb = m0 + warp_m * 32;
    const int nb = n0 + warp_n * 64;
#pragma unroll
    for (int mt = 0; mt < 2; ++mt) {
#pragma unroll
        for (int nt = 0; nt < 8; ++nt) {
            const int col = nb + nt * 8 + tc;
            const float b0 = bias[col], b1 = bias[col + 1];
            const size_t r0 = (size_t)(mb + mt * 16 + tr) * Ev + col;
            const size_t r1 = (size_t)(mb + mt * 16 + tr + 8) * Ev + col;
            float2 v0 = {acc[mt][nt][0] + b0, acc[mt][nt][1] + b1};
            float2 v1 = {acc[mt][nt][2] + b0, acc[mt][nt][3] + b1};
            *reinterpret_cast<float2*>(&C[r0]) = v0;
            *reinterpret_cast<float2*>(&C[r1]) = v1;
        }
    }
}

// ========================= tensor-core flash attention =====================
// fp16 single-product, mbarrier 3-stage K/V pipeline (no per-iter syncthreads)
// Q pre-scaled by 0.125 (exact). Buggy l preserved. Output fp16.
#define NSTG 3
#define KVSTG (2 * 64 * 144)                         // 18432 B per stage
#define ATT_SMEM (64 + 128 * 144 + NSTG * KVSTG)     // 73792 B

__global__ __launch_bounds__(256, 2)
void attn_tc_kernel(const __half* __restrict__ Q, const __half* __restrict__ K,
                    const __half* __restrict__ V, __half* __restrict__ Of)
{
    extern __shared__ __align__(128) char smem[];
    const uint32_t sb = smem_u32(smem);
    // full[s] = sb + 8*s ; empty[s] = sb + 24 + 8*s
    const uint32_t sQ  = sb + 64;
    const uint32_t sKV = sQ + 128 * 144;

    const int tid = threadIdx.x;
    const int w = tid >> 5, lane = tid & 31;
    const int b  = blockIdx.x >> 4;
    const int h  = blockIdx.x & 15;
    const int q0 = blockIdx.y << 7;

    const __half* Qg = Q + ((size_t)b * Sv + q0) * Ev + h * HDv;
    const __half* Kg = K + (size_t)b * Sv * Ev + h * HDv;
    const __half* Vg = V + (size_t)b * Sv * Ev + h * HDv;

    if (tid == 0) {
#pragma unroll
        for (int s = 0; s < NSTG; ++s) {
            MBAR_INIT(sb + 8 * s, 256);
            MBAR_INIT(sb + 24 + 8 * s, 256);
        }
    }
    __syncthreads();

    // prologue: Q + stage 0 (covered by full[0] arrive), stage 1
    for (int i = tid; i < 1024; i += 256) {
        const int r = i >> 3, c = i & 7;
        CP_ASYNC16(sQ + r * 144 + c * 16, Qg + (size_t)r * Ev + c * 8);
    }
    {
        const uint32_t st0 = sKV;
        for (int i = tid; i < 512; i += 256) {
            const int r = i >> 3, c = i & 7;
            CP_ASYNC16(st0 + r * 144 + c * 16, Kg + (size_t)r * Ev + c * 8);
            CP_ASYNC16(st0 + 64 * 144 + r * 144 + c * 16, Vg + (size_t)r * Ev + c * 8);
        }
        CPA_ARRIVE(sb + 0);
        const uint32_t st1 = sKV + KVSTG;
        const __half* Kp = Kg + (size_t)64 * Ev;
        const __half* Vp = Vg + (size_t)64 * Ev;
        for (int i = tid; i < 512; i += 256) {
            const int r = i >> 3, c = i & 7;
            CP_ASYNC16(st1 + r * 144 + c * 16, Kp + (size_t)r * Ev + c * 8);
            CP_ASYNC16(st1 + 64 * 144 + r * 144 + c * 16, Vp + (size_t)r * Ev + c * 8);
        }
        CPA_ARRIVE(sb + 8);
    }

    float acc[8][4];
#pragma unroll
    for (int j = 0; j < 8; ++j)
#pragma unroll
        for (int q = 0; q < 4; ++q) acc[j][q] = 0.f;
    float m0 = -CUDART_INF_F, m1 = -CUDART_INF_F;
    float l0 = 0.f, l1 = 0.f;

    uint32_t aQ[4][4];
    bool qLoaded = false;

    const uint32_t q_addr0 = sQ + (uint32_t)(16 * w + (lane & 15)) * 144
                                + ((lane >> 4) << 4);
    const int kq = lane & 7;
    const int kg16 = (lane >> 4) << 3;
    const int kg8  = ((lane >> 3) & 1) << 3;

    for (int kb = 0; kb < NKB; ++kb) {
        const int cur = kb % NSTG;
        MBAR_WAIT(sb + 8 * cur, (kb / NSTG) & 1);

        if (!qLoaded) {
#pragma unroll
            for (int s = 0; s < 4; ++s) ldsm4(q_addr0 + s * 32, aQ[s]);
            qLoaded = true;
        }

        const uint32_t sKst = sKV + (uint32_t)cur * KVSTG;
        const uint32_t sVst = sKst + 64 * 144;

        // ---- scores: S[16][64] = Qw @ K^T (HMMAs in flight during produce) --
        float sc[8][4];
#pragma unroll
        for (int j = 0; j < 8; ++j)
#pragma unroll
            for (int q = 0; q < 4; ++q) sc[j][q] = 0.f;

#pragma unroll
        for (int p = 0; p < 4; ++p) {
#pragma unroll
            for (int s = 0; s < 4; ++s) {
                uint32_t kf[4];
                ldsm4(sKst + (uint32_t)(16 * p + kg16 + kq) * 144
                           + (uint32_t)(16 * s + kg8) * 2, kf);
                mma_fp(sc[2 * p],     aQ[s], &kf[0]);
                mma_fp(sc[2 * p + 1], aQ[s], &kf[2]);
            }
        }

        // ---- produce stage for kb+2 ----
        if (kb + 2 < NKB) {
            const int kl = kb + 2;
            const int s2 = kl % NSTG;
            const int m = kl / NSTG;
            MBAR_WAIT(sb + 24 + 8 * s2, (m + 1) & 1);
            const uint32_t st = sKV + (uint32_t)s2 * KVSTG;
            const __half* Kp = Kg + (size_t)(kl * 64) * Ev;
            const __half* Vp = Vg + (size_t)(kl * 64) * Ev;
            for (int i = tid; i < 512; i += 256) {
                const int r = i >> 3, c = i & 7;
                CP_ASYNC16(st + r * 144 + c * 16, Kp + (size_t)r * Ev + c * 8);
                CP_ASYNC16(st + 64 * 144 + r * 144 + c * 16, Vp + (size_t)r * Ev + c * 8);
            }
            CPA_ARRIVE(sb + 8 * s2);
        }

        // ---- online softmax (buggy l preserved) ----
        float mx0 = -CUDART_INF_F, mx1 = -CUDART_INF_F;
#pragma unroll
        for (int j = 0; j < 8; ++j) {
            mx0 = fmaxf(mx0, fmaxf(sc[j][0], sc[j][1]));
            mx1 = fmaxf(mx1, fmaxf(sc[j][2], sc[j][3]));
        }
        mx0 = fmaxf(mx0, __shfl_xor_sync(0xffffffffu, mx0, 1));
        mx0 = fmaxf(mx0, __shfl_xor_sync(0xffffffffu, mx0, 2));
        mx1 = fmaxf(mx1, __shfl_xor_sync(0xffffffffu, mx1, 1));
        mx1 = fmaxf(mx1, __shfl_xor_sync(0xffffffffu, mx1, 2));

        const float mn0 = fmaxf(m0, mx0);
        const float mn1 = fmaxf(m1, mx1);
        const float co0 = __expf(m0 - mn0);
        const float co1 = __expf(m1 - mn1);
        m0 = mn0; m1 = mn1;

        float sum0 = 0.f, sum1 = 0.f;
        uint32_t ph01[8], ph23[8];
#pragma unroll
        for (int j = 0; j < 8; ++j) {
            const float p0 = __expf(sc[j][0] - mn0);
            const float p1 = __expf(sc[j][1] - mn0);
            const float p2 = __expf(sc[j][2] - mn1);
            const float p3 = __expf(sc[j][3] - mn1);
            sum0 += p0 + p1; sum1 += p2 + p3;
            ph01[j] = f2_to_h2u(p0, p1);
            ph23[j] = f2_to_h2u(p2, p3);
        }
        sum0 += __shfl_xor_sync(0xffffffffu, sum0, 1);
        sum0 += __shfl_xor_sync(0xffffffffu, sum0, 2);
        sum1 += __shfl_xor_sync(0xffffffffu, sum1, 1);
        sum1 += __shfl_xor_sync(0xffffffffu, sum1, 2);

        l0 = sum0 * co0 + sum0;   // BUG preserved from reference
        l1 = sum1 * co1 + sum1;

#pragma unroll
        for (int j = 0; j < 8; ++j) {
            acc[j][0] *= co0; acc[j][1] *= co0;
            acc[j][2] *= co1; acc[j][3] *= co1;
        }

        // ---- PV: acc += P @ V ----
#pragma unroll
        for (int s = 0; s < 4; ++s) {
            const uint32_t aP[4] = {ph01[2 * s], ph23[2 * s],
                                    ph01[2 * s + 1], ph23[2 * s + 1]};
#pragma unroll
            for (int dp = 0; dp < 4; ++dp) {
                uint32_t vf[4];
                ldsm4t(sVst + (uint32_t)(16 * s + kg8 + kq) * 144
                            + (uint32_t)(16 * dp + kg16) * 2, vf);
                mma_fp(acc[2 * dp],     aP, &vf[0]);
                mma_fp(acc[2 * dp + 1], aP, &vf[2]);
            }
        }

        MBAR_ARRIVE(sb + 24 + 8 * cur);   // stage consumed
    }

    // ---- epilogue: O = acc / l, fp16 output ----
    const float inv0 = 1.f / l0;
    const float inv1 = 1.f / l1;
    const int row0 = q0 + 16 * w + (lane >> 2);
    const int colb = h * HDv + 2 * (lane & 3);
    __half* Ob = Of + (size_t)b * Sv * Ev;
#pragma unroll
    for (int j = 0; j < 8; ++j) {
        const int col = colb + 8 * j;
        const size_t i0 = (size_t)row0 * Ev + col;
        const size_t i1 = (size_t)(row0 + 8) * Ev + col;
        *reinterpret_cast<uint32_t*>(&Ob[i0]) =
            f2_to_h2u(acc[j][0] * inv0, acc[j][1] * inv0);
        *reinterpret_cast<uint32_t*>(&Ob[i1]) =
            f2_to_h2u(acc[j][2] * inv1, acc[j][3] * inv1);
    }
}

// ========================= launch ==========================================
extern "C" void kernel_launch(void* const* d_in, const int* in_sizes, int n_in,
                              void* d_out, int out_size)
{
    const float* x  = (const float*)d_in[0];
    const float* qw = (const float*)d_in[1];
    const float* kw = (const float*)d_in[2];
    const float* vw = (const float*)d_in[3];
    const float* ow = (const float*)d_in[4];
    const float* ob = (const float*)d_in[5];
    float* out = (float*)d_out;

    __half *Qh, *Kh, *Vh, *xf, *of, *wf;
    cudaGetSymbolAddress((void**)&Qh, g_Qh);
    cudaGetSymbolAddress((void**)&Kh, g_Kh);
    cudaGetSymbolAddress((void**)&Vh, g_Vh);
    cudaGetSymbolAddress((void**)&xf, g_xf);
    cudaGetSymbolAddress((void**)&of, g_of);
    cudaGetSymbolAddress((void**)&wf, g_wf);

    const int M = Bv * Sv;
    const int nX4 = M * Ev / 4;
    const int nW4 = Ev * Ev / 4;

    cvt_h_kernel<<<nX4 / 256, 256>>>(x, xf, nX4);
    cvt4_kernel<<<dim3(nW4 / 256, 4), 256>>>(qw, kw, vw, ow, wf, nW4);

    cudaFuncSetAttribute(gemm_qkv_kernel,
                         cudaFuncAttributeMaxDynamicSharedMemorySize, GEMM_SMEM);
    cudaFuncSetAttribute(gemm_out_kernel,
                         cudaFuncAttributeMaxDynamicSharedMemorySize, GEMM_SMEM);
    cudaFuncSetAttribute(attn_tc_kernel,
                         cudaFuncAttributeMaxDynamicSharedMemorySize, ATT_SMEM);

    gemm_qkv_kernel<<<dim3(Ev / 128, M / 128, 3), 256, GEMM_SMEM>>>(
        xf, wf, Qh, Kh, Vh);

    attn_tc_kernel<<<dim3(Bv * Hv, Sv / 128), 256, ATT_SMEM>>>(Qh, Kh, Vh, of);

    gemm_out_kernel<<<dim3(Ev / 128, M / 128), 256, GEMM_SMEM>>>(
        of, wf + 3 * (size_t)Ev * Ev, ob, out);
}

// round 10
// speedup vs baseline: 7.7408x; 1.0538x over previous
#include <cuda_runtime.h>
#include <cuda_fp16.h>
#include <math_constants.h>
#include <cstdint>

// Problem constants
#define Bv 4
#define Sv 2048
#define Ev 1024
#define Hv 16
#define HDv 64
#define NKB (Sv / 64)
#define ATT_SCALE 0.125f
#define LOG2E 1.4426950408889634f

// ========================= PTX helpers =====================================
__device__ __forceinline__ uint32_t smem_u32(const void* p) {
    uint32_t a;
    asm("{ .reg .u64 t; cvta.to.shared.u64 t, %1; cvt.u32.u64 %0, t; }"
        : "=r"(a) : "l"(p));
    return a;
}
#define CP_ASYNC16(sa, ga) \
    asm volatile("cp.async.cg.shared.global [%0], [%1], 16;" :: "r"(sa), "l"(ga))
#define CP_COMMIT()  asm volatile("cp.async.commit_group;" ::: "memory")
#define CP_WAIT(n)   asm volatile("cp.async.wait_group %0;" :: "n"(n) : "memory")

#define MBAR_INIT(addr, cnt) \
    asm volatile("mbarrier.init.shared.b64 [%0], %1;" :: "r"(addr), "r"((uint32_t)(cnt)) : "memory")
#define MBAR_ARRIVE(addr) \
    asm volatile("mbarrier.arrive.shared.b64 _, [%0];" :: "r"(addr) : "memory")
#define CPA_ARRIVE(addr) \
    asm volatile("cp.async.mbarrier.arrive.noinc.shared.b64 [%0];" :: "r"(addr) : "memory")
#define MBAR_WAIT(addr, ph) \
    asm volatile("{\n\t.reg .pred P;\n" \
                 "WL_%=:\n\t" \
                 "mbarrier.try_wait.parity.acquire.cta.shared::cta.b64 P, [%0], %1;\n\t" \
                 "@!P bra WL_%=;\n\t}" \
                 :: "r"(addr), "r"((uint32_t)(ph)) : "memory")

__device__ __forceinline__ void ldsm4(uint32_t addr, uint32_t r[4]) {
    asm volatile("ldmatrix.sync.aligned.m8n8.x4.shared.b16 {%0,%1,%2,%3}, [%4];"
                 : "=r"(r[0]), "=r"(r[1]), "=r"(r[2]), "=r"(r[3]) : "r"(addr));
}
__device__ __forceinline__ void ldsm4t(uint32_t addr, uint32_t r[4]) {
    asm volatile("ldmatrix.sync.aligned.m8n8.x4.trans.shared.b16 {%0,%1,%2,%3}, [%4];"
                 : "=r"(r[0]), "=r"(r[1]), "=r"(r[2]), "=r"(r[3]) : "r"(addr));
}
__device__ __forceinline__ void mma_fp(float c[4], const uint32_t a[4],
                                       const uint32_t b[2]) {
    asm volatile(
        "mma.sync.aligned.m16n8k16.row.col.f32.f16.f16.f32 "
        "{%0,%1,%2,%3}, {%4,%5,%6,%7}, {%8,%9}, {%0,%1,%2,%3};"
        : "+f"(c[0]), "+f"(c[1]), "+f"(c[2]), "+f"(c[3])
        : "r"(a[0]), "r"(a[1]), "r"(a[2]), "r"(a[3]), "r"(b[0]), "r"(b[1]));
}
__device__ __forceinline__ uint32_t f2_to_h2u(float lo, float hi) {
    uint32_t r;
    asm("cvt.rn.f16x2.f32 %0, %1, %2;" : "=r"(r) : "f"(hi), "f"(lo));
    return r;
}
__device__ __forceinline__ float ex2f(float x) {
    float r; asm("ex2.approx.f32 %0, %1;" : "=f"(r) : "f"(x)); return r;
}
__device__ __forceinline__ uint32_t h2ex2(uint32_t a) {
    uint32_t r; asm("ex2.approx.f16x2 %0, %1;" : "=r"(r) : "r"(a)); return r;
}

// ========================= static device scratch ===========================
__device__ __half g_Qh[(size_t)Bv * Sv * Ev];
__device__ __half g_Kh[(size_t)Bv * Sv * Ev];
__device__ __half g_Vh[(size_t)Bv * Sv * Ev];
__device__ __half g_xf[(size_t)Bv * Sv * Ev];
__device__ __half g_of[(size_t)Bv * Sv * Ev];
__device__ __half g_wf[4][(size_t)Ev * Ev];

// ========================= fused fp32 -> fp16 convert ======================
// blocks [0,8192): x (2M f4); blocks [8192,12288): 4 weight slabs (256K f4 each)
__global__ void cvt_all_kernel(const float* __restrict__ x,
                               const float* __restrict__ w0,
                               const float* __restrict__ w1,
                               const float* __restrict__ w2,
                               const float* __restrict__ w3,
                               __half* __restrict__ xf, __half* __restrict__ wf)
{
    const int bid = blockIdx.x;
    const float* src;
    __half* dst;
    int i;
    if (bid < 8192) {
        src = x; dst = xf;
        i = bid * 256 + threadIdx.x;
    } else {
        const int wb = bid - 8192;
        const int wi = wb >> 10;                  // 1024 blocks per weight
        const float* ws[4] = {w0, w1, w2, w3};
        src = ws[wi];
        dst = wf + (size_t)wi * Ev * Ev;
        i = (wb & 1023) * 256 + threadIdx.x;
    }
    float4 v = reinterpret_cast<const float4*>(src)[i];
    uint32_t* dp = reinterpret_cast<uint32_t*>(dst) + 2 * i;
    dp[0] = f2_to_h2u(v.x, v.y);
    dp[1] = f2_to_h2u(v.z, v.w);
}

// ========================= shared GEMM config ==============================
#define BK 32
#define ROWB 80
#define TILE_BYTES (128 * ROWB)
#define NCHW (Ev / BK)
#define STAGE_S (2 * TILE_BYTES)
#define GEMM_SMEM (2 * STAGE_S)     // 40960

__device__ __forceinline__ void load_stage_s(
    uint32_t sbase, int stage, int kc,
    const __half* A, const __half* B, int m0, int n0, int tid)
{
    const uint32_t st = sbase + stage * STAGE_S;
    const __half* srcs[2] = {A, B};
    const int row0[2] = {m0, n0};
#pragma unroll
    for (int t = 0; t < 2; ++t) {
#pragma unroll
        for (int p = 0; p < 2; ++p) {
            const int i = p * 256 + tid;
            const int r = i >> 2;
            const int c = i & 3;
            const __half* g =
                srcs[t] + (size_t)(row0[t] + r) * Ev + kc * BK + c * 8;
            CP_ASYNC16(st + t * TILE_BYTES + r * ROWB + c * 16, g);
        }
    }
}

// ========================= fused QKV GEMM (single-product fp16) ============
__global__ __launch_bounds__(256, 2)
void gemm_qkv_kernel(const __half* __restrict__ A, const __half* __restrict__ W,
                     __half* __restrict__ Qo, __half* __restrict__ Ko,
                     __half* __restrict__ Vo)
{
    extern __shared__ __align__(128) char smem[];
    const uint32_t sb = smem_u32(smem);
    const int tid = threadIdx.x;
    const int wid = tid >> 5, lane = tid & 31;
    const int warp_m = wid & 3, warp_n = wid >> 2;
    const int m0 = blockIdx.y << 7;
    const int n0 = blockIdx.x << 7;
    const int z  = blockIdx.z;

    const __half* B = W + (size_t)z * Ev * Ev;
    __half* Out = (z == 0) ? Qo : ((z == 1) ? Ko : Vo);
    // Q premul: ATT_SCALE * log2(e) -> scores in log2 domain
    const float premul = (z == 0) ? (ATT_SCALE * LOG2E) : 1.0f;

    float acc[2][8][4];
#pragma unroll
    for (int mt = 0; mt < 2; ++mt)
#pragma unroll
        for (int nt = 0; nt < 8; ++nt)
#pragma unroll
            for (int q = 0; q < 4; ++q) acc[mt][nt][q] = 0.f;

    load_stage_s(sb, 0, 0, A, B, m0, n0, tid);
    CP_COMMIT();

    const int arow = warp_m * 32 + (lane & 15);
    const uint32_t acol16 = (uint32_t)((lane >> 4) << 4);
    const int nrow = warp_n * 64 + (((lane >> 4) & 1) << 3) + (lane & 7);
    const uint32_t bcol16 = (uint32_t)(((lane >> 3) & 1) << 4);

    for (int c = 0; c < NCHW; ++c) {
        const int s = c & 1;
        if (c + 1 < NCHW) {
            load_stage_s(sb, s ^ 1, c + 1, A, B, m0, n0, tid);
            CP_COMMIT();
            CP_WAIT(1);
        } else {
            CP_WAIT(0);
        }
        __syncthreads();

        const uint32_t stA = sb + s * STAGE_S;
        const uint32_t stB = stA + TILE_BYTES;

#pragma unroll
        for (int ks = 0; ks < 2; ++ks) {
            const uint32_t kofs = ks * 32;
            uint32_t a[2][4], b[4][4];
#pragma unroll
            for (int p = 0; p < 4; ++p)
                ldsm4(stB + (uint32_t)(nrow + p * 16) * ROWB + kofs + bcol16, b[p]);
            ldsm4(stA + (uint32_t)arow * ROWB + kofs + acol16, a[0]);
            ldsm4(stA + (uint32_t)(arow + 16) * ROWB + kofs + acol16, a[1]);
#pragma unroll
            for (int mt = 0; mt < 2; ++mt)
#pragma unroll
                for (int nt = 0; nt < 8; ++nt)
                    mma_fp(acc[mt][nt], a[mt], &b[nt >> 1][(nt & 1) * 2]);
        }
        __syncthreads();
    }

    const int tr = lane >> 2;
    const int tc = (lane & 3) * 2;
    const int mb = m0 + warp_m * 32;
    const int nb = n0 + warp_n * 64;
#pragma unroll
    for (int mt = 0; mt < 2; ++mt) {
#pragma unroll
        for (int nt = 0; nt < 8; ++nt) {
            const int col = nb + nt * 8 + tc;
            const size_t r0 = (size_t)(mb + mt * 16 + tr) * Ev + col;
            const size_t r1 = (size_t)(mb + mt * 16 + tr + 8) * Ev + col;
            *reinterpret_cast<uint32_t*>(&Out[r0]) =
                f2_to_h2u(acc[mt][nt][0] * premul, acc[mt][nt][1] * premul);
            *reinterpret_cast<uint32_t*>(&Out[r1]) =
                f2_to_h2u(acc[mt][nt][2] * premul, acc[mt][nt][3] * premul);
        }
    }
}

// ========================= out-proj GEMM (single-product, fp32+bias) =======
__global__ __launch_bounds__(256, 2)
void gemm_out_kernel(const __half* __restrict__ A, const __half* __restrict__ B,
                     const float* __restrict__ bias, float* __restrict__ C)
{
    extern __shared__ __align__(128) char smem[];
    const uint32_t sb = smem_u32(smem);
    const int tid = threadIdx.x;
    const int wid = tid >> 5, lane = tid & 31;
    const int warp_m = wid & 3, warp_n = wid >> 2;
    const int m0 = blockIdx.y << 7;
    const int n0 = blockIdx.x << 7;

    float acc[2][8][4];
#pragma unroll
    for (int mt = 0; mt < 2; ++mt)
#pragma unroll
        for (int nt = 0; nt < 8; ++nt)
#pragma unroll
            for (int q = 0; q < 4; ++q) acc[mt][nt][q] = 0.f;

    load_stage_s(sb, 0, 0, A, B, m0, n0, tid);
    CP_COMMIT();

    const int arow = warp_m * 32 + (lane & 15);
    const uint32_t acol16 = (uint32_t)((lane >> 4) << 4);
    const int nrow = warp_n * 64 + (((lane >> 4) & 1) << 3) + (lane & 7);
    const uint32_t bcol16 = (uint32_t)(((lane >> 3) & 1) << 4);

    for (int c = 0; c < NCHW; ++c) {
        const int s = c & 1;
        if (c + 1 < NCHW) {
            load_stage_s(sb, s ^ 1, c + 1, A, B, m0, n0, tid);
            CP_COMMIT();
            CP_WAIT(1);
        } else {
            CP_WAIT(0);
        }
        __syncthreads();

        const uint32_t stA = sb + s * STAGE_S;
        const uint32_t stB = stA + TILE_BYTES;

#pragma unroll
        for (int ks = 0; ks < 2; ++ks) {
            const uint32_t kofs = ks * 32;
            uint32_t a[2][4], b[4][4];
#pragma unroll
            for (int p = 0; p < 4; ++p)
                ldsm4(stB + (uint32_t)(nrow + p * 16) * ROWB + kofs + bcol16, b[p]);
            ldsm4(stA + (uint32_t)arow * ROWB + kofs + acol16, a[0]);
            ldsm4(stA + (uint32_t)(arow + 16) * ROWB + kofs + acol16, a[1]);
#pragma unroll
            for (int mt = 0; mt < 2; ++mt)
#pragma unroll
                for (int nt = 0; nt < 8; ++nt)
                    mma_fp(acc[mt][nt], a[mt], &b[nt >> 1][(nt & 1) * 2]);
        }
        __syncthreads();
    }

    const int tr = lane >> 2;
    const int tc = (lane & 3) * 2;
    const int mb = m0 + warp_m * 32;
    const int nb = n0 + warp_n * 64;
#pragma unroll
    for (int mt = 0; mt < 2; ++mt) {
#pragma unroll
        for (int nt = 0; nt < 8; ++nt) {
            const int col = nb + nt * 8 + tc;
            const float b0 = bias[col], b1 = bias[col + 1];
            const size_t r0 = (size_t)(mb + mt * 16 + tr) * Ev + col;
            const size_t r1 = (size_t)(mb + mt * 16 + tr + 8) * Ev + col;
            float2 v0 = {acc[mt][nt][0] + b0, acc[mt][nt][1] + b1};
            float2 v1 = {acc[mt][nt][2] + b0, acc[mt][nt][3] + b1};
            *reinterpret_cast<float2*>(&C[r0]) = v0;
            *reinterpret_cast<float2*>(&C[r1]) = v1;
        }
    }
}

// ========================= tensor-core flash attention =====================
// fp16, log2-domain scores (Q premul folds scale*log2e). ex2.approx.f16x2 for
// P, row-sum via all-ones n8 MMA column (fp32 accum). Buggy l preserved.
// 3-stage mbarrier K/V pipeline. Output fp16.
#define NSTG 3
#define KVSTG (2 * 64 * 144)
#define ATT_SMEM (64 + 128 * 144 + NSTG * KVSTG)     // 73792 B
#define H2_ONES 0x3C003C00u

__global__ __launch_bounds__(256, 2)
void attn_tc_kernel(const __half* __restrict__ Q, const __half* __restrict__ K,
                    const __half* __restrict__ V, __half* __restrict__ Of)
{
    extern __shared__ __align__(128) char smem[];
    const uint32_t sb = smem_u32(smem);
    const uint32_t sQ  = sb + 64;
    const uint32_t sKV = sQ + 128 * 144;

    const int tid = threadIdx.x;
    const int w = tid >> 5, lane = tid & 31;
    const int b  = blockIdx.x >> 4;
    const int h  = blockIdx.x & 15;
    const int q0 = blockIdx.y << 7;

    const __half* Qg = Q + ((size_t)b * Sv + q0) * Ev + h * HDv;
    const __half* Kg = K + (size_t)b * Sv * Ev + h * HDv;
    const __half* Vg = V + (size_t)b * Sv * Ev + h * HDv;

    if (tid == 0) {
#pragma unroll
        for (int s = 0; s < NSTG; ++s) {
            MBAR_INIT(sb + 8 * s, 256);
            MBAR_INIT(sb + 24 + 8 * s, 256);
        }
    }
    __syncthreads();

    for (int i = tid; i < 1024; i += 256) {
        const int r = i >> 3, c = i & 7;
        CP_ASYNC16(sQ + r * 144 + c * 16, Qg + (size_t)r * Ev + c * 8);
    }
    {
        const uint32_t st0 = sKV;
        for (int i = tid; i < 512; i += 256) {
            const int r = i >> 3, c = i & 7;
            CP_ASYNC16(st0 + r * 144 + c * 16, Kg + (size_t)r * Ev + c * 8);
            CP_ASYNC16(st0 + 64 * 144 + r * 144 + c * 16, Vg + (size_t)r * Ev + c * 8);
        }
        CPA_ARRIVE(sb + 0);
        const uint32_t st1 = sKV + KVSTG;
        const __half* Kp = Kg + (size_t)64 * Ev;
        const __half* Vp = Vg + (size_t)64 * Ev;
        for (int i = tid; i < 512; i += 256) {
            const int r = i >> 3, c = i & 7;
            CP_ASYNC16(st1 + r * 144 + c * 16, Kp + (size_t)r * Ev + c * 8);
            CP_ASYNC16(st1 + 64 * 144 + r * 144 + c * 16, Vp + (size_t)r * Ev + c * 8);
        }
        CPA_ARRIVE(sb + 8);
    }

    float acc[8][4];
#pragma unroll
    for (int j = 0; j < 8; ++j)
#pragma unroll
        for (int q = 0; q < 4; ++q) acc[j][q] = 0.f;
    float m0 = -CUDART_INF_F, m1 = -CUDART_INF_F;   // log2-domain running max
    float l0 = 0.f, l1 = 0.f;

    uint32_t aQ[4][4];
    bool qLoaded = false;

    const uint32_t q_addr0 = sQ + (uint32_t)(16 * w + (lane & 15)) * 144
                                + ((lane >> 4) << 4);
    const int kq = lane & 7;
    const int kg16 = (lane >> 4) << 3;
    const int kg8  = ((lane >> 3) & 1) << 3;
    const uint32_t onesB[2] = {H2_ONES, H2_ONES};

    for (int kb = 0; kb < NKB; ++kb) {
        const int cur = kb % NSTG;
        MBAR_WAIT(sb + 8 * cur, (kb / NSTG) & 1);

        if (!qLoaded) {
#pragma unroll
            for (int s = 0; s < 4; ++s) ldsm4(q_addr0 + s * 32, aQ[s]);
            qLoaded = true;
        }

        const uint32_t sKst = sKV + (uint32_t)cur * KVSTG;
        const uint32_t sVst = sKst + 64 * 144;

        // ---- scores (log2-domain): S[16][64] = Qw @ K^T ----
        float sc[8][4];
#pragma unroll
        for (int j = 0; j < 8; ++j)
#pragma unroll
            for (int q = 0; q < 4; ++q) sc[j][q] = 0.f;

#pragma unroll
        for (int p = 0; p < 4; ++p) {
#pragma unroll
            for (int s = 0; s < 4; ++s) {
                uint32_t kf[4];
                ldsm4(sKst + (uint32_t)(16 * p + kg16 + kq) * 144
                           + (uint32_t)(16 * s + kg8) * 2, kf);
                mma_fp(sc[2 * p],     aQ[s], &kf[0]);
                mma_fp(sc[2 * p + 1], aQ[s], &kf[2]);
            }
        }

        // ---- produce stage for kb+2 ----
        if (kb + 2 < NKB) {
            const int kl = kb + 2;
            const int s2 = kl % NSTG;
            const int m = kl / NSTG;
            MBAR_WAIT(sb + 24 + 8 * s2, (m + 1) & 1);
            const uint32_t st = sKV + (uint32_t)s2 * KVSTG;
            const __half* Kp = Kg + (size_t)(kl * 64) * Ev;
            const __half* Vp = Vg + (size_t)(kl * 64) * Ev;
            for (int i = tid; i < 512; i += 256) {
                const int r = i >> 3, c = i & 7;
                CP_ASYNC16(st + r * 144 + c * 16, Kp + (size_t)r * Ev + c * 8);
                CP_ASYNC16(st + 64 * 144 + r * 144 + c * 16, Vp + (size_t)r * Ev + c * 8);
            }
            CPA_ARRIVE(sb + 8 * s2);
        }

        // ---- online softmax (log2 domain, buggy l preserved) ----
        float mx0 = -CUDART_INF_F, mx1 = -CUDART_INF_F;
#pragma unroll
        for (int j = 0; j < 8; ++j) {
            mx0 = fmaxf(mx0, fmaxf(sc[j][0], sc[j][1]));
            mx1 = fmaxf(mx1, fmaxf(sc[j][2], sc[j][3]));
        }
        mx0 = fmaxf(mx0, __shfl_xor_sync(0xffffffffu, mx0, 1));
        mx0 = fmaxf(mx0, __shfl_xor_sync(0xffffffffu, mx0, 2));
        mx1 = fmaxf(mx1, __shfl_xor_sync(0xffffffffu, mx1, 1));
        mx1 = fmaxf(mx1, __shfl_xor_sync(0xffffffffu, mx1, 2));

        const float mn0 = fmaxf(m0, mx0);
        const float mn1 = fmaxf(m1, mx1);
        const float co0 = ex2f(m0 - mn0);
        const float co1 = ex2f(m1 - mn1);
        m0 = mn0; m1 = mn1;

        // P = exp2(sc - mn) via ex2.approx.f16x2 (args packed in fp16x2)
        uint32_t ph01[8], ph23[8];
#pragma unroll
        for (int j = 0; j < 8; ++j) {
            ph01[j] = h2ex2(f2_to_h2u(sc[j][0] - mn0, sc[j][1] - mn0));
            ph23[j] = h2ex2(f2_to_h2u(sc[j][2] - mn1, sc[j][3] - mn1));
        }

#pragma unroll
        for (int j = 0; j < 8; ++j) {
            acc[j][0] *= co0; acc[j][1] *= co0;
            acc[j][2] *= co1; acc[j][3] *= co1;
        }

        // ---- PV + ones-column row-sum ----
        float sl[4] = {0.f, 0.f, 0.f, 0.f};
#pragma unroll
        for (int s = 0; s < 4; ++s) {
            const uint32_t aP[4] = {ph01[2 * s], ph23[2 * s],
                                    ph01[2 * s + 1], ph23[2 * s + 1]};
#pragma unroll
            for (int dp = 0; dp < 4; ++dp) {
                uint32_t vf[4];
                ldsm4t(sVst + (uint32_t)(16 * s + kg8 + kq) * 144
                            + (uint32_t)(16 * dp + kg16) * 2, vf);
                mma_fp(acc[2 * dp],     aP, &vf[0]);
                mma_fp(acc[2 * dp + 1], aP, &vf[2]);
            }
            mma_fp(sl, aP, onesB);     // row sums (all-ones B fragment)
        }
        // l = cs*corr + cs (BUG preserved from reference)
        l0 = fmaf(sl[0], co0, sl[0]);
        l1 = fmaf(sl[2], co1, sl[2]);

        MBAR_ARRIVE(sb + 24 + 8 * cur);
    }

    // ---- epilogue: O = acc / l, fp16 output ----
    const float inv0 = 1.f / l0;
    const float inv1 = 1.f / l1;
    const int row0 = q0 + 16 * w + (lane >> 2);
    const int colb = h * HDv + 2 * (lane & 3);
    __half* Ob = Of + (size_t)b * Sv * Ev;
#pragma unroll
    for (int j = 0; j < 8; ++j) {
        const int col = colb + 8 * j;
        const size_t i0 = (size_t)row0 * Ev + col;
        const size_t i1 = (size_t)(row0 + 8) * Ev + col;
        *reinterpret_cast<uint32_t*>(&Ob[i0]) =
            f2_to_h2u(acc[j][0] * inv0, acc[j][1] * inv0);
        *reinterpret_cast<uint32_t*>(&Ob[i1]) =
            f2_to_h2u(acc[j][2] * inv1, acc[j][3] * inv1);
    }
}

// ========================= launch ==========================================
extern "C" void kernel_launch(void* const* d_in, const int* in_sizes, int n_in,
                              void* d_out, int out_size)
{
    const float* x  = (const float*)d_in[0];
    const float* qw = (const float*)d_in[1];
    const float* kw = (const float*)d_in[2];
    const float* vw = (const float*)d_in[3];
    const float* ow = (const float*)d_in[4];
    const float* ob = (const float*)d_in[5];
    float* out = (float*)d_out;

    __half *Qh, *Kh, *Vh, *xf, *of, *wf;
    cudaGetSymbolAddress((void**)&Qh, g_Qh);
    cudaGetSymbolAddress((void**)&Kh, g_Kh);
    cudaGetSymbolAddress((void**)&Vh, g_Vh);
    cudaGetSymbolAddress((void**)&xf, g_xf);
    cudaGetSymbolAddress((void**)&of, g_of);
    cudaGetSymbolAddress((void**)&wf, g_wf);

    const int M = Bv * Sv;

    cvt_all_kernel<<<8192 + 4096, 256>>>(x, qw, kw, vw, ow, xf, wf);

    cudaFuncSetAttribute(gemm_qkv_kernel,
                         cudaFuncAttributeMaxDynamicSharedMemorySize, GEMM_SMEM);
    cudaFuncSetAttribute(gemm_out_kernel,
                         cudaFuncAttributeMaxDynamicSharedMemorySize, GEMM_SMEM);
    cudaFuncSetAttribute(attn_tc_kernel,
                         cudaFuncAttributeMaxDynamicSharedMemorySize, ATT_SMEM);

    gemm_qkv_kernel<<<dim3(Ev / 128, M / 128, 3), 256, GEMM_SMEM>>>(
        xf, wf, Qh, Kh, Vh);

    attn_tc_kernel<<<dim3(Bv * Hv, Sv / 128), 256, ATT_SMEM>>>(Qh, Kh, Vh, of);

    gemm_out_kernel<<<dim3(Ev / 128, M / 128), 256, GEMM_SMEM>>>(
        of, wf + 3 * (size_t)Ev * Ev, ob, out);
}

// round 11
// speedup vs baseline: 8.0334x; 1.0378x over previous
#include <cuda_runtime.h>
#include <cuda_fp16.h>
#include <math_constants.h>
#include <cstdint>

// Problem constants
#define Bv 4
#define Sv 2048
#define Ev 1024
#define Hv 16
#define HDv 64
#define NKB (Sv / 64)
#define ATT_SCALE 0.125f
#define LOG2E 1.4426950408889634f

// ========================= PTX helpers =====================================
__device__ __forceinline__ uint32_t smem_u32(const void* p) {
    uint32_t a;
    asm("{ .reg .u64 t; cvta.to.shared.u64 t, %1; cvt.u32.u64 %0, t; }"
        : "=r"(a) : "l"(p));
    return a;
}
#define CP_ASYNC16(sa, ga) \
    asm volatile("cp.async.cg.shared.global [%0], [%1], 16;" :: "r"(sa), "l"(ga))
#define CP_COMMIT()  asm volatile("cp.async.commit_group;" ::: "memory")
#define CP_WAIT(n)   asm volatile("cp.async.wait_group %0;" :: "n"(n) : "memory")

#define MBAR_INIT(addr, cnt) \
    asm volatile("mbarrier.init.shared.b64 [%0], %1;" :: "r"(addr), "r"((uint32_t)(cnt)) : "memory")
#define MBAR_ARRIVE(addr) \
    asm volatile("mbarrier.arrive.shared.b64 _, [%0];" :: "r"(addr) : "memory")
#define CPA_ARRIVE(addr) \
    asm volatile("cp.async.mbarrier.arrive.noinc.shared.b64 [%0];" :: "r"(addr) : "memory")
#define MBAR_WAIT(addr, ph) \
    asm volatile("{\n\t.reg .pred P;\n" \
                 "WL_%=:\n\t" \
                 "mbarrier.try_wait.parity.acquire.cta.shared::cta.b64 P, [%0], %1;\n\t" \
                 "@!P bra WL_%=;\n\t}" \
                 :: "r"(addr), "r"((uint32_t)(ph)) : "memory")

__device__ __forceinline__ void ldsm4(uint32_t addr, uint32_t r[4]) {
    asm volatile("ldmatrix.sync.aligned.m8n8.x4.shared.b16 {%0,%1,%2,%3}, [%4];"
                 : "=r"(r[0]), "=r"(r[1]), "=r"(r[2]), "=r"(r[3]) : "r"(addr));
}
__device__ __forceinline__ void ldsm4t(uint32_t addr, uint32_t r[4]) {
    asm volatile("ldmatrix.sync.aligned.m8n8.x4.trans.shared.b16 {%0,%1,%2,%3}, [%4];"
                 : "=r"(r[0]), "=r"(r[1]), "=r"(r[2]), "=r"(r[3]) : "r"(addr));
}
__device__ __forceinline__ void mma_fp(float c[4], const uint32_t a[4],
                                       const uint32_t b[2]) {
    asm volatile(
        "mma.sync.aligned.m16n8k16.row.col.f32.f16.f16.f32 "
        "{%0,%1,%2,%3}, {%4,%5,%6,%7}, {%8,%9}, {%0,%1,%2,%3};"
        : "+f"(c[0]), "+f"(c[1]), "+f"(c[2]), "+f"(c[3])
        : "r"(a[0]), "r"(a[1]), "r"(a[2]), "r"(a[3]), "r"(b[0]), "r"(b[1]));
}
__device__ __forceinline__ uint32_t f2_to_h2u(float lo, float hi) {
    uint32_t r;
    asm("cvt.rn.f16x2.f32 %0, %1, %2;" : "=r"(r) : "f"(hi), "f"(lo));
    return r;
}
__device__ __forceinline__ float ex2f(float x) {
    float r; asm("ex2.approx.f32 %0, %1;" : "=f"(r) : "f"(x)); return r;
}
__device__ __forceinline__ uint32_t h2ex2(uint32_t a) {
    uint32_t r; asm("ex2.approx.f16x2 %0, %1;" : "=r"(r) : "r"(a)); return r;
}

// ========================= static device scratch ===========================
__device__ __half g_Qh[(size_t)Bv * Sv * Ev];
__device__ __half g_Kh[(size_t)Bv * Sv * Ev];
__device__ __half g_Vh[(size_t)Bv * Sv * Ev];
__device__ __half g_xf[(size_t)Bv * Sv * Ev];
__device__ __half g_of[(size_t)Bv * Sv * Ev];
__device__ __half g_wf[4][(size_t)Ev * Ev];

// ========================= fused fp32 -> fp16 convert ======================
__global__ void cvt_all_kernel(const float* __restrict__ x,
                               const float* __restrict__ w0,
                               const float* __restrict__ w1,
                               const float* __restrict__ w2,
                               const float* __restrict__ w3,
                               __half* __restrict__ xf, __half* __restrict__ wf)
{
    const int bid = blockIdx.x;
    const float* src;
    __half* dst;
    int i;
    if (bid < 8192) {
        src = x; dst = xf;
        i = bid * 256 + threadIdx.x;
    } else {
        const int wb = bid - 8192;
        const int wi = wb >> 10;
        const float* ws[4] = {w0, w1, w2, w3};
        src = ws[wi];
        dst = wf + (size_t)wi * Ev * Ev;
        i = (wb & 1023) * 256 + threadIdx.x;
    }
    float4 v = reinterpret_cast<const float4*>(src)[i];
    uint32_t* dp = reinterpret_cast<uint32_t*>(dst) + 2 * i;
    dp[0] = f2_to_h2u(v.x, v.y);
    dp[1] = f2_to_h2u(v.z, v.w);
}

// ========================= shared GEMM config ==============================
#define BK 32
#define ROWB 80
#define TILE_BYTES (128 * ROWB)
#define NCHW (Ev / BK)
#define STAGE_S (2 * TILE_BYTES)      // A, B
#define NGSTG 4
#define GEMM_SMEM (NGSTG * STAGE_S)   // 81920

__device__ __forceinline__ void load_stage_s(
    uint32_t sbase, int stage, int kc,
    const __half* A, const __half* B, int m0, int n0, int tid)
{
    const uint32_t st = sbase + stage * STAGE_S;
    const __half* srcs[2] = {A, B};
    const int row0[2] = {m0, n0};
#pragma unroll
    for (int t = 0; t < 2; ++t) {
#pragma unroll
        for (int p = 0; p < 2; ++p) {
            const int i = p * 256 + tid;
            const int r = i >> 2;
            const int c = i & 3;
            const __half* g =
                srcs[t] + (size_t)(row0[t] + r) * Ev + kc * BK + c * 8;
            CP_ASYNC16(st + t * TILE_BYTES + r * ROWB + c * 16, g);
        }
    }
}

// shared mainloop body (4-stage, 1 barrier/chunk, CUTLASS multistage order)
#define GEMM_MAINLOOP(A_, B_)                                              \
    load_stage_s(sb, 0, 0, A_, B_, m0, n0, tid); CP_COMMIT();              \
    load_stage_s(sb, 1, 1, A_, B_, m0, n0, tid); CP_COMMIT();              \
    load_stage_s(sb, 2, 2, A_, B_, m0, n0, tid); CP_COMMIT();              \
    CP_WAIT(2);                                                            \
    __syncthreads();                                                       \
    for (int c = 0; c < NCHW; ++c) {                                       \
        const int s = c & 3;                                               \
        if (c + 3 < NCHW) {                                                \
            load_stage_s(sb, (c + 3) & 3, c + 3, A_, B_, m0, n0, tid);     \
            CP_COMMIT();                                                   \
        } else { CP_COMMIT(); }                                            \
        const uint32_t stA = sb + s * STAGE_S;                             \
        const uint32_t stB = stA + TILE_BYTES;                             \
        _Pragma("unroll")                                                  \
        for (int ks = 0; ks < 2; ++ks) {                                   \
            const uint32_t kofs = ks * 32;                                 \
            uint32_t a[2][4], b[4][4];                                     \
            _Pragma("unroll")                                              \
            for (int p = 0; p < 4; ++p)                                    \
                ldsm4(stB + (uint32_t)(nrow + p * 16) * ROWB + kofs + bcol16, b[p]); \
            ldsm4(stA + (uint32_t)arow * ROWB + kofs + acol16, a[0]);      \
            ldsm4(stA + (uint32_t)(arow + 16) * ROWB + kofs + acol16, a[1]); \
            _Pragma("unroll")                                              \
            for (int mt = 0; mt < 2; ++mt)                                 \
                _Pragma("unroll")                                          \
                for (int nt = 0; nt < 8; ++nt)                             \
                    mma_fp(acc[mt][nt], a[mt], &b[nt >> 1][(nt & 1) * 2]); \
        }                                                                  \
        CP_WAIT(2);                                                        \
        __syncthreads();                                                   \
    }

// ========================= fused QKV GEMM (single-product fp16) ============
__global__ __launch_bounds__(256, 2)
void gemm_qkv_kernel(const __half* __restrict__ A, const __half* __restrict__ W,
                     __half* __restrict__ Qo, __half* __restrict__ Ko,
                     __half* __restrict__ Vo)
{
    extern __shared__ __align__(128) char smem[];
    const uint32_t sb = smem_u32(smem);
    const int tid = threadIdx.x;
    const int wid = tid >> 5, lane = tid & 31;
    const int warp_m = wid & 3, warp_n = wid >> 2;
    const int m0 = blockIdx.y << 7;
    const int n0 = blockIdx.x << 7;
    const int z  = blockIdx.z;

    const __half* B = W + (size_t)z * Ev * Ev;
    __half* Out = (z == 0) ? Qo : ((z == 1) ? Ko : Vo);
    const float premul = (z == 0) ? (ATT_SCALE * LOG2E) : 1.0f;

    float acc[2][8][4];
#pragma unroll
    for (int mt = 0; mt < 2; ++mt)
#pragma unroll
        for (int nt = 0; nt < 8; ++nt)
#pragma unroll
            for (int q = 0; q < 4; ++q) acc[mt][nt][q] = 0.f;

    const int arow = warp_m * 32 + (lane & 15);
    const uint32_t acol16 = (uint32_t)((lane >> 4) << 4);
    const int nrow = warp_n * 64 + (((lane >> 4) & 1) << 3) + (lane & 7);
    const uint32_t bcol16 = (uint32_t)(((lane >> 3) & 1) << 4);

    GEMM_MAINLOOP(A, B)

    const int tr = lane >> 2;
    const int tc = (lane & 3) * 2;
    const int mb = m0 + warp_m * 32;
    const int nb = n0 + warp_n * 64;
#pragma unroll
    for (int mt = 0; mt < 2; ++mt) {
#pragma unroll
        for (int nt = 0; nt < 8; ++nt) {
            const int col = nb + nt * 8 + tc;
            const size_t r0 = (size_t)(mb + mt * 16 + tr) * Ev + col;
            const size_t r1 = (size_t)(mb + mt * 16 + tr + 8) * Ev + col;
            *reinterpret_cast<uint32_t*>(&Out[r0]) =
                f2_to_h2u(acc[mt][nt][0] * premul, acc[mt][nt][1] * premul);
            *reinterpret_cast<uint32_t*>(&Out[r1]) =
                f2_to_h2u(acc[mt][nt][2] * premul, acc[mt][nt][3] * premul);
        }
    }
}

// ========================= out-proj GEMM (single-product, fp32+bias) =======
__global__ __launch_bounds__(256, 2)
void gemm_out_kernel(const __half* __restrict__ A, const __half* __restrict__ B,
                     const float* __restrict__ bias, float* __restrict__ C)
{
    extern __shared__ __align__(128) char smem[];
    const uint32_t sb = smem_u32(smem);
    const int tid = threadIdx.x;
    const int wid = tid >> 5, lane = tid & 31;
    const int warp_m = wid & 3, warp_n = wid >> 2;
    const int m0 = blockIdx.y << 7;
    const int n0 = blockIdx.x << 7;

    float acc[2][8][4];
#pragma unroll
    for (int mt = 0; mt < 2; ++mt)
#pragma unroll
        for (int nt = 0; nt < 8; ++nt)
#pragma unroll
            for (int q = 0; q < 4; ++q) acc[mt][nt][q] = 0.f;

    const int arow = warp_m * 32 + (lane & 15);
    const uint32_t acol16 = (uint32_t)((lane >> 4) << 4);
    const int nrow = warp_n * 64 + (((lane >> 4) & 1) << 3) + (lane & 7);
    const uint32_t bcol16 = (uint32_t)(((lane >> 3) & 1) << 4);

    GEMM_MAINLOOP(A, B)

    const int tr = lane >> 2;
    const int tc = (lane & 3) * 2;
    const int mb = m0 + warp_m * 32;
    const int nb = n0 + warp_n * 64;
#pragma unroll
    for (int mt = 0; mt < 2; ++mt) {
#pragma unroll
        for (int nt = 0; nt < 8; ++nt) {
            const int col = nb + nt * 8 + tc;
            const float b0 = bias[col], b1 = bias[col + 1];
            const size_t r0 = (size_t)(mb + mt * 16 + tr) * Ev + col;
            const size_t r1 = (size_t)(mb + mt * 16 + tr + 8) * Ev + col;
            float2 v0 = {acc[mt][nt][0] + b0, acc[mt][nt][1] + b1};
            float2 v1 = {acc[mt][nt][2] + b0, acc[mt][nt][3] + b1};
            *reinterpret_cast<float2*>(&C[r0]) = v0;
            *reinterpret_cast<float2*>(&C[r1]) = v1;
        }
    }
}

// ========================= tensor-core flash attention =====================
// fp16, log2-domain scores. ex2.approx.f16x2 P, ones-column row-sum MMA.
// Buggy l preserved. 3-stage mbarrier K/V pipeline. Output fp16.
#define NSTG 3
#define KVSTG (2 * 64 * 144)
#define ATT_SMEM (64 + 128 * 144 + NSTG * KVSTG)
#define H2_ONES 0x3C003C00u

__global__ __launch_bounds__(256, 2)
void attn_tc_kernel(const __half* __restrict__ Q, const __half* __restrict__ K,
                    const __half* __restrict__ V, __half* __restrict__ Of)
{
    extern __shared__ __align__(128) char smem[];
    const uint32_t sb = smem_u32(smem);
    const uint32_t sQ  = sb + 64;
    const uint32_t sKV = sQ + 128 * 144;

    const int tid = threadIdx.x;
    const int w = tid >> 5, lane = tid & 31;
    const int b  = blockIdx.x >> 4;
    const int h  = blockIdx.x & 15;
    const int q0 = blockIdx.y << 7;

    const __half* Qg = Q + ((size_t)b * Sv + q0) * Ev + h * HDv;
    const __half* Kg = K + (size_t)b * Sv * Ev + h * HDv;
    const __half* Vg = V + (size_t)b * Sv * Ev + h * HDv;

    if (tid == 0) {
#pragma unroll
        for (int s = 0; s < NSTG; ++s) {
            MBAR_INIT(sb + 8 * s, 256);
            MBAR_INIT(sb + 24 + 8 * s, 256);
        }
    }
    __syncthreads();

    for (int i = tid; i < 1024; i += 256) {
        const int r = i >> 3, c = i & 7;
        CP_ASYNC16(sQ + r * 144 + c * 16, Qg + (size_t)r * Ev + c * 8);
    }
    {
        const uint32_t st0 = sKV;
        for (int i = tid; i < 512; i += 256) {
            const int r = i >> 3, c = i & 7;
            CP_ASYNC16(st0 + r * 144 + c * 16, Kg + (size_t)r * Ev + c * 8);
            CP_ASYNC16(st0 + 64 * 144 + r * 144 + c * 16, Vg + (size_t)r * Ev + c * 8);
        }
        CPA_ARRIVE(sb + 0);
        const uint32_t st1 = sKV + KVSTG;
        const __half* Kp = Kg + (size_t)64 * Ev;
        const __half* Vp = Vg + (size_t)64 * Ev;
        for (int i = tid; i < 512; i += 256) {
            const int r = i >> 3, c = i & 7;
            CP_ASYNC16(st1 + r * 144 + c * 16, Kp + (size_t)r * Ev + c * 8);
            CP_ASYNC16(st1 + 64 * 144 + r * 144 + c * 16, Vp + (size_t)r * Ev + c * 8);
        }
        CPA_ARRIVE(sb + 8);
    }

    float acc[8][4];
#pragma unroll
    for (int j = 0; j < 8; ++j)
#pragma unroll
        for (int q = 0; q < 4; ++q) acc[j][q] = 0.f;
    float m0 = -CUDART_INF_F, m1 = -CUDART_INF_F;
    float l0 = 0.f, l1 = 0.f;

    uint32_t aQ[4][4];
    bool qLoaded = false;

    const uint32_t q_addr0 = sQ + (uint32_t)(16 * w + (lane & 15)) * 144
                                + ((lane >> 4) << 4);
    const int kq = lane & 7;
    const int kg16 = (lane >> 4) << 3;
    const int kg8  = ((lane >> 3) & 1) << 3;
    const uint32_t onesB[2] = {H2_ONES, H2_ONES};

    for (int kb = 0; kb < NKB; ++kb) {
        const int cur = kb % NSTG;
        MBAR_WAIT(sb + 8 * cur, (kb / NSTG) & 1);

        if (!qLoaded) {
#pragma unroll
            for (int s = 0; s < 4; ++s) ldsm4(q_addr0 + s * 32, aQ[s]);
            qLoaded = true;
        }

        const uint32_t sKst = sKV + (uint32_t)cur * KVSTG;
        const uint32_t sVst = sKst + 64 * 144;

        float sc[8][4];
#pragma unroll
        for (int j = 0; j < 8; ++j)
#pragma unroll
            for (int q = 0; q < 4; ++q) sc[j][q] = 0.f;

#pragma unroll
        for (int p = 0; p < 4; ++p) {
#pragma unroll
            for (int s = 0; s < 4; ++s) {
                uint32_t kf[4];
                ldsm4(sKst + (uint32_t)(16 * p + kg16 + kq) * 144
                           + (uint32_t)(16 * s + kg8) * 2, kf);
                mma_fp(sc[2 * p],     aQ[s], &kf[0]);
                mma_fp(sc[2 * p + 1], aQ[s], &kf[2]);
            }
        }

        if (kb + 2 < NKB) {
            const int kl = kb + 2;
            const int s2 = kl % NSTG;
            const int m = kl / NSTG;
            MBAR_WAIT(sb + 24 + 8 * s2, (m + 1) & 1);
            const uint32_t st = sKV + (uint32_t)s2 * KVSTG;
            const __half* Kp = Kg + (size_t)(kl * 64) * Ev;
            const __half* Vp = Vg + (size_t)(kl * 64) * Ev;
            for (int i = tid; i < 512; i += 256) {
                const int r = i >> 3, c = i & 7;
                CP_ASYNC16(st + r * 144 + c * 16, Kp + (size_t)r * Ev + c * 8);
                CP_ASYNC16(st + 64 * 144 + r * 144 + c * 16, Vp + (size_t)r * Ev + c * 8);
            }
            CPA_ARRIVE(sb + 8 * s2);
        }

        float mx0 = -CUDART_INF_F, mx1 = -CUDART_INF_F;
#pragma unroll
        for (int j = 0; j < 8; ++j) {
            mx0 = fmaxf(mx0, fmaxf(sc[j][0], sc[j][1]));
            mx1 = fmaxf(mx1, fmaxf(sc[j][2], sc[j][3]));
        }
        mx0 = fmaxf(mx0, __shfl_xor_sync(0xffffffffu, mx0, 1));
        mx0 = fmaxf(mx0, __shfl_xor_sync(0xffffffffu, mx0, 2));
        mx1 = fmaxf(mx1, __shfl_xor_sync(0xffffffffu, mx1, 1));
        mx1 = fmaxf(mx1, __shfl_xor_sync(0xffffffffu, mx1, 2));

        const float mn0 = fmaxf(m0, mx0);
        const float mn1 = fmaxf(m1, mx1);
        const float co0 = ex2f(m0 - mn0);
        const float co1 = ex2f(m1 - mn1);
        m0 = mn0; m1 = mn1;

        uint32_t ph01[8], ph23[8];
#pragma unroll
        for (int j = 0; j < 8; ++j) {
            ph01[j] = h2ex2(f2_to_h2u(sc[j][0] - mn0, sc[j][1] - mn0));
            ph23[j] = h2ex2(f2_to_h2u(sc[j][2] - mn1, sc[j][3] - mn1));
        }

#pragma unroll
        for (int j = 0; j < 8; ++j) {
            acc[j][0] *= co0; acc[j][1] *= co0;
            acc[j][2] *= co1; acc[j][3] *= co1;
        }

        float sl[4] = {0.f, 0.f, 0.f, 0.f};
#pragma unroll
        for (int s = 0; s < 4; ++s) {
            const uint32_t aP[4] = {ph01[2 * s], ph23[2 * s],
                                    ph01[2 * s + 1], ph23[2 * s + 1]};
#pragma unroll
            for (int dp = 0; dp < 4; ++dp) {
                uint32_t vf[4];
                ldsm4t(sVst + (uint32_t)(16 * s + kg8 + kq) * 144
                            + (uint32_t)(16 * dp + kg16) * 2, vf);
                mma_fp(acc[2 * dp],     aP, &vf[0]);
                mma_fp(acc[2 * dp + 1], aP, &vf[2]);
            }
            mma_fp(sl, aP, onesB);
        }
        l0 = fmaf(sl[0], co0, sl[0]);
        l1 = fmaf(sl[2], co1, sl[2]);

        MBAR_ARRIVE(sb + 24 + 8 * cur);
    }

    const float inv0 = 1.f / l0;
    const float inv1 = 1.f / l1;
    const int row0 = q0 + 16 * w + (lane >> 2);
    const int colb = h * HDv + 2 * (lane & 3);
    __half* Ob = Of + (size_t)b * Sv * Ev;
#pragma unroll
    for (int j = 0; j < 8; ++j) {
        const int col = colb + 8 * j;
        const size_t i0 = (size_t)row0 * Ev + col;
        const size_t i1 = (size_t)(row0 + 8) * Ev + col;
        *reinterpret_cast<uint32_t*>(&Ob[i0]) =
            f2_to_h2u(acc[j][0] * inv0, acc[j][1] * inv0);
        *reinterpret_cast<uint32_t*>(&Ob[i1]) =
            f2_to_h2u(acc[j][2] * inv1, acc[j][3] * inv1);
    }
}

// ========================= launch ==========================================
extern "C" void kernel_launch(void* const* d_in, const int* in_sizes, int n_in,
                              void* d_out, int out_size)
{
    const float* x  = (const float*)d_in[0];
    const float* qw = (const float*)d_in[1];
    const float* kw = (const float*)d_in[2];
    const float* vw = (const float*)d_in[3];
    const float* ow = (const float*)d_in[4];
    const float* ob = (const float*)d_in[5];
    float* out = (float*)d_out;

    __half *Qh, *Kh, *Vh, *xf, *of, *wf;
    cudaGetSymbolAddress((void**)&Qh, g_Qh);
    cudaGetSymbolAddress((void**)&Kh, g_Kh);
    cudaGetSymbolAddress((void**)&Vh, g_Vh);
    cudaGetSymbolAddress((void**)&xf, g_xf);
    cudaGetSymbolAddress((void**)&of, g_of);
    cudaGetSymbolAddress((void**)&wf, g_wf);

    const int M = Bv * Sv;

    cvt_all_kernel<<<8192 + 4096, 256>>>(x, qw, kw, vw, ow, xf, wf);

    cudaFuncSetAttribute(gemm_qkv_kernel,
                         cudaFuncAttributeMaxDynamicSharedMemorySize, GEMM_SMEM);
    cudaFuncSetAttribute(gemm_out_kernel,
                         cudaFuncAttributeMaxDynamicSharedMemorySize, GEMM_SMEM);
    cudaFuncSetAttribute(attn_tc_kernel,
                         cudaFuncAttributeMaxDynamicSharedMemorySize, ATT_SMEM);

    gemm_qkv_kernel<<<dim3(Ev / 128, M / 128, 3), 256, GEMM_SMEM>>>(
        xf, wf, Qh, Kh, Vh);

    attn_tc_kernel<<<dim3(Bv * Hv, Sv / 128), 256, ATT_SMEM>>>(Qh, Kh, Vh, of);

    gemm_out_kernel<<<dim3(Ev / 128, M / 128), 256, GEMM_SMEM>>>(
        of, wf + 3 * (size_t)Ev * Ev, ob, out);
}

// round 12
// speedup vs baseline: 8.4846x; 1.0562x over previous
#include <cuda_runtime.h>
#include <cuda_fp16.h>
#include <math_constants.h>
#include <cstdint>

// Problem constants
#define Bv 4
#define Sv 2048
#define Ev 1024
#define Hv 16
#define HDv 64
#define NKB (Sv / 64)
#define ATT_SCALE 0.125f
#define LOG2E 1.4426950408889634f

// ========================= PTX helpers =====================================
__device__ __forceinline__ uint32_t smem_u32(const void* p) {
    uint32_t a;
    asm("{ .reg .u64 t; cvta.to.shared.u64 t, %1; cvt.u32.u64 %0, t; }"
        : "=r"(a) : "l"(p));
    return a;
}
#define CP_ASYNC16(sa, ga) \
    asm volatile("cp.async.cg.shared.global [%0], [%1], 16;" :: "r"(sa), "l"(ga))
#define CP_COMMIT()  asm volatile("cp.async.commit_group;" ::: "memory")
#define CP_WAIT(n)   asm volatile("cp.async.wait_group %0;" :: "n"(n) : "memory")

#define MBAR_INIT(addr, cnt) \
    asm volatile("mbarrier.init.shared.b64 [%0], %1;" :: "r"(addr), "r"((uint32_t)(cnt)) : "memory")
#define MBAR_ARRIVE(addr) \
    asm volatile("mbarrier.arrive.shared.b64 _, [%0];" :: "r"(addr) : "memory")
#define CPA_ARRIVE(addr) \
    asm volatile("cp.async.mbarrier.arrive.noinc.shared.b64 [%0];" :: "r"(addr) : "memory")
#define MBAR_WAIT(addr, ph) \
    asm volatile("{\n\t.reg .pred P;\n" \
                 "WL_%=:\n\t" \
                 "mbarrier.try_wait.parity.acquire.cta.shared::cta.b64 P, [%0], %1;\n\t" \
                 "@!P bra WL_%=;\n\t}" \
                 :: "r"(addr), "r"((uint32_t)(ph)) : "memory")

__device__ __forceinline__ void ldsm4(uint32_t addr, uint32_t r[4]) {
    asm volatile("ldmatrix.sync.aligned.m8n8.x4.shared.b16 {%0,%1,%2,%3}, [%4];"
                 : "=r"(r[0]), "=r"(r[1]), "=r"(r[2]), "=r"(r[3]) : "r"(addr));
}
__device__ __forceinline__ void ldsm4t(uint32_t addr, uint32_t r[4]) {
    asm volatile("ldmatrix.sync.aligned.m8n8.x4.trans.shared.b16 {%0,%1,%2,%3}, [%4];"
                 : "=r"(r[0]), "=r"(r[1]), "=r"(r[2]), "=r"(r[3]) : "r"(addr));
}
__device__ __forceinline__ void mma_fp(float c[4], const uint32_t a[4],
                                       const uint32_t b[2]) {
    asm volatile(
        "mma.sync.aligned.m16n8k16.row.col.f32.f16.f16.f32 "
        "{%0,%1,%2,%3}, {%4,%5,%6,%7}, {%8,%9}, {%0,%1,%2,%3};"
        : "+f"(c[0]), "+f"(c[1]), "+f"(c[2]), "+f"(c[3])
        : "r"(a[0]), "r"(a[1]), "r"(a[2]), "r"(a[3]), "r"(b[0]), "r"(b[1]));
}
__device__ __forceinline__ uint32_t f2_to_h2u(float lo, float hi) {
    uint32_t r;
    asm("cvt.rn.f16x2.f32 %0, %1, %2;" : "=r"(r) : "f"(hi), "f"(lo));
    return r;
}
__device__ __forceinline__ float ex2f(float x) {
    float r; asm("ex2.approx.f32 %0, %1;" : "=f"(r) : "f"(x)); return r;
}
__device__ __forceinline__ uint32_t h2ex2(uint32_t a) {
    uint32_t r; asm("ex2.approx.f16x2 %0, %1;" : "=r"(r) : "r"(a)); return r;
}

// ========================= static device scratch ===========================
__device__ __half g_Qh[(size_t)Bv * Sv * Ev];
__device__ __half g_Kh[(size_t)Bv * Sv * Ev];
__device__ __half g_Vh[(size_t)Bv * Sv * Ev];
__device__ __half g_xf[(size_t)Bv * Sv * Ev];
__device__ __half g_of[(size_t)Bv * Sv * Ev];
__device__ __half g_wf[4][(size_t)Ev * Ev];

// ========================= fused fp32 -> fp16 convert ======================
__global__ void cvt_all_kernel(const float* __restrict__ x,
                               const float* __restrict__ w0,
                               const float* __restrict__ w1,
                               const float* __restrict__ w2,
                               const float* __restrict__ w3,
                               __half* __restrict__ xf, __half* __restrict__ wf)
{
    const int bid = blockIdx.x;
    const float* src;
    __half* dst;
    int i;
    if (bid < 8192) {
        src = x; dst = xf;
        i = bid * 256 + threadIdx.x;
    } else {
        const int wb = bid - 8192;
        const int wi = wb >> 10;
        const float* ws[4] = {w0, w1, w2, w3};
        src = ws[wi];
        dst = wf + (size_t)wi * Ev * Ev;
        i = (wb & 1023) * 256 + threadIdx.x;
    }
    float4 v = reinterpret_cast<const float4*>(src)[i];
    uint32_t* dp = reinterpret_cast<uint32_t*>(dst) + 2 * i;
    dp[0] = f2_to_h2u(v.x, v.y);
    dp[1] = f2_to_h2u(v.z, v.w);
}

// ========================= shared GEMM config ==============================
// 128x128 CTA tile, 4 warps of 64x64, 128 threads. 4-stage cp.async pipeline.
#define BK 32
#define ROWB 80
#define TILE_BYTES (128 * ROWB)
#define NCHW (Ev / BK)
#define STAGE_S (2 * TILE_BYTES)      // A, B
#define NGSTG 4
#define GEMM_SMEM (NGSTG * STAGE_S)   // 81920
#define GTHREADS 128

__device__ __forceinline__ void load_stage_s(
    uint32_t sbase, int stage, int kc,
    const __half* A, const __half* B, int m0, int n0, int tid)
{
    const uint32_t st = sbase + stage * STAGE_S;
    const __half* srcs[2] = {A, B};
    const int row0[2] = {m0, n0};
#pragma unroll
    for (int t = 0; t < 2; ++t) {
#pragma unroll
        for (int p = 0; p < 4; ++p) {
            const int i = p * GTHREADS + tid;     // 0..511
            const int r = i >> 2;
            const int c = i & 3;
            const __half* g =
                srcs[t] + (size_t)(row0[t] + r) * Ev + kc * BK + c * 8;
            CP_ASYNC16(st + t * TILE_BYTES + r * ROWB + c * 16, g);
        }
    }
}

// 4-stage mainloop, 64x64 warp tiles: per ks 8 ldsm feed 32 MMA.
#define GEMM_MAINLOOP(A_, B_)                                              \
    load_stage_s(sb, 0, 0, A_, B_, m0, n0, tid); CP_COMMIT();              \
    load_stage_s(sb, 1, 1, A_, B_, m0, n0, tid); CP_COMMIT();              \
    load_stage_s(sb, 2, 2, A_, B_, m0, n0, tid); CP_COMMIT();              \
    CP_WAIT(2);                                                            \
    __syncthreads();                                                       \
    for (int c = 0; c < NCHW; ++c) {                                       \
        const int s = c & 3;                                               \
        if (c + 3 < NCHW) {                                                \
            load_stage_s(sb, (c + 3) & 3, c + 3, A_, B_, m0, n0, tid);     \
            CP_COMMIT();                                                   \
        } else { CP_COMMIT(); }                                            \
        const uint32_t stA = sb + s * STAGE_S;                             \
        const uint32_t stB = stA + TILE_BYTES;                             \
        _Pragma("unroll")                                                  \
        for (int ks = 0; ks < 2; ++ks) {                                   \
            const uint32_t kofs = ks * 32;                                 \
            uint32_t a[4][4], b[4][4];                                     \
            _Pragma("unroll")                                              \
            for (int p = 0; p < 4; ++p)                                    \
                ldsm4(stA + (uint32_t)(arow + p * 16) * ROWB + kofs + acol16, a[p]); \
            _Pragma("unroll")                                              \
            for (int p = 0; p < 4; ++p)                                    \
                ldsm4(stB + (uint32_t)(nrow + p * 16) * ROWB + kofs + bcol16, b[p]); \
            _Pragma("unroll")                                              \
            for (int mt = 0; mt < 4; ++mt)                                 \
                _Pragma("unroll")                                          \
                for (int nt = 0; nt < 8; ++nt)                             \
                    mma_fp(acc[mt][nt], a[mt], &b[nt >> 1][(nt & 1) * 2]); \
        }                                                                  \
        CP_WAIT(2);                                                        \
        __syncthreads();                                                   \
    }

// ========================= fused QKV GEMM (single-product fp16) ============
__global__ __launch_bounds__(GTHREADS, 2)
void gemm_qkv_kernel(const __half* __restrict__ A, const __half* __restrict__ W,
                     __half* __restrict__ Qo, __half* __restrict__ Ko,
                     __half* __restrict__ Vo)
{
    extern __shared__ __align__(128) char smem[];
    const uint32_t sb = smem_u32(smem);
    const int tid = threadIdx.x;
    const int wid = tid >> 5, lane = tid & 31;
    const int warp_m = wid & 1, warp_n = wid >> 1;
    const int m0 = blockIdx.y << 7;
    const int n0 = blockIdx.x << 7;
    const int z  = blockIdx.z;

    const __half* B = W + (size_t)z * Ev * Ev;
    __half* Out = (z == 0) ? Qo : ((z == 1) ? Ko : Vo);
    const float premul = (z == 0) ? (ATT_SCALE * LOG2E) : 1.0f;

    float acc[4][8][4];
#pragma unroll
    for (int mt = 0; mt < 4; ++mt)
#pragma unroll
        for (int nt = 0; nt < 8; ++nt)
#pragma unroll
            for (int q = 0; q < 4; ++q) acc[mt][nt][q] = 0.f;

    const int arow = warp_m * 64 + (lane & 15);
    const uint32_t acol16 = (uint32_t)((lane >> 4) << 4);
    const int nrow = warp_n * 64 + (((lane >> 4) & 1) << 3) + (lane & 7);
    const uint32_t bcol16 = (uint32_t)(((lane >> 3) & 1) << 4);

    GEMM_MAINLOOP(A, B)

    const int tr = lane >> 2;
    const int tc = (lane & 3) * 2;
    const int mb = m0 + warp_m * 64;
    const int nb = n0 + warp_n * 64;
#pragma unroll
    for (int mt = 0; mt < 4; ++mt) {
#pragma unroll
        for (int nt = 0; nt < 8; ++nt) {
            const int col = nb + nt * 8 + tc;
            const size_t r0 = (size_t)(mb + mt * 16 + tr) * Ev + col;
            const size_t r1 = (size_t)(mb + mt * 16 + tr + 8) * Ev + col;
            *reinterpret_cast<uint32_t*>(&Out[r0]) =
                f2_to_h2u(acc[mt][nt][0] * premul, acc[mt][nt][1] * premul);
            *reinterpret_cast<uint32_t*>(&Out[r1]) =
                f2_to_h2u(acc[mt][nt][2] * premul, acc[mt][nt][3] * premul);
        }
    }
}

// ========================= out-proj GEMM (single-product, fp32+bias) =======
__global__ __launch_bounds__(GTHREADS, 2)
void gemm_out_kernel(const __half* __restrict__ A, const __half* __restrict__ B,
                     const float* __restrict__ bias, float* __restrict__ C)
{
    extern __shared__ __align__(128) char smem[];
    const uint32_t sb = smem_u32(smem);
    const int tid = threadIdx.x;
    const int wid = tid >> 5, lane = tid & 31;
    const int warp_m = wid & 1, warp_n = wid >> 1;
    const int m0 = blockIdx.y << 7;
    const int n0 = blockIdx.x << 7;

    float acc[4][8][4];
#pragma unroll
    for (int mt = 0; mt < 4; ++mt)
#pragma unroll
        for (int nt = 0; nt < 8; ++nt)
#pragma unroll
            for (int q = 0; q < 4; ++q) acc[mt][nt][q] = 0.f;

    const int arow = warp_m * 64 + (lane & 15);
    const uint32_t acol16 = (uint32_t)((lane >> 4) << 4);
    const int nrow = warp_n * 64 + (((lane >> 4) & 1) << 3) + (lane & 7);
    const uint32_t bcol16 = (uint32_t)(((lane >> 3) & 1) << 4);

    GEMM_MAINLOOP(A, B)

    const int tr = lane >> 2;
    const int tc = (lane & 3) * 2;
    const int mb = m0 + warp_m * 64;
    const int nb = n0 + warp_n * 64;
#pragma unroll
    for (int mt = 0; mt < 4; ++mt) {
#pragma unroll
        for (int nt = 0; nt < 8; ++nt) {
            const int col = nb + nt * 8 + tc;
            const float b0 = bias[col], b1 = bias[col + 1];
            const size_t r0 = (size_t)(mb + mt * 16 + tr) * Ev + col;
            const size_t r1 = (size_t)(mb + mt * 16 + tr + 8) * Ev + col;
            float2 v0 = {acc[mt][nt][0] + b0, acc[mt][nt][1] + b1};
            float2 v1 = {acc[mt][nt][2] + b0, acc[mt][nt][3] + b1};
            *reinterpret_cast<float2*>(&C[r0]) = v0;
            *reinterpret_cast<float2*>(&C[r1]) = v1;
        }
    }
}

// ========================= tensor-core flash attention =====================
// fp16, log2-domain scores. ex2.approx.f16x2 P, ones-column row-sum MMA.
// Buggy l preserved. 3-stage mbarrier K/V pipeline. Output fp16.
#define NSTG 3
#define KVSTG (2 * 64 * 144)
#define ATT_SMEM (64 + 128 * 144 + NSTG * KVSTG)
#define H2_ONES 0x3C003C00u

__global__ __launch_bounds__(256, 2)
void attn_tc_kernel(const __half* __restrict__ Q, const __half* __restrict__ K,
                    const __half* __restrict__ V, __half* __restrict__ Of)
{
    extern __shared__ __align__(128) char smem[];
    const uint32_t sb = smem_u32(smem);
    const uint32_t sQ  = sb + 64;
    const uint32_t sKV = sQ + 128 * 144;

    const int tid = threadIdx.x;
    const int w = tid >> 5, lane = tid & 31;
    const int b  = blockIdx.x >> 4;
    const int h  = blockIdx.x & 15;
    const int q0 = blockIdx.y << 7;

    const __half* Qg = Q + ((size_t)b * Sv + q0) * Ev + h * HDv;
    const __half* Kg = K + (size_t)b * Sv * Ev + h * HDv;
    const __half* Vg = V + (size_t)b * Sv * Ev + h * HDv;

    if (tid == 0) {
#pragma unroll
        for (int s = 0; s < NSTG; ++s) {
            MBAR_INIT(sb + 8 * s, 256);
            MBAR_INIT(sb + 24 + 8 * s, 256);
        }
    }
    __syncthreads();

    for (int i = tid; i < 1024; i += 256) {
        const int r = i >> 3, c = i & 7;
        CP_ASYNC16(sQ + r * 144 + c * 16, Qg + (size_t)r * Ev + c * 8);
    }
    {
        const uint32_t st0 = sKV;
        for (int i = tid; i < 512; i += 256) {
            const int r = i >> 3, c = i & 7;
            CP_ASYNC16(st0 + r * 144 + c * 16, Kg + (size_t)r * Ev + c * 8);
            CP_ASYNC16(st0 + 64 * 144 + r * 144 + c * 16, Vg + (size_t)r * Ev + c * 8);
        }
        CPA_ARRIVE(sb + 0);
        const uint32_t st1 = sKV + KVSTG;
        const __half* Kp = Kg + (size_t)64 * Ev;
        const __half* Vp = Vg + (size_t)64 * Ev;
        for (int i = tid; i < 512; i += 256) {
            const int r = i >> 3, c = i & 7;
            CP_ASYNC16(st1 + r * 144 + c * 16, Kp + (size_t)r * Ev + c * 8);
            CP_ASYNC16(st1 + 64 * 144 + r * 144 + c * 16, Vp + (size_t)r * Ev + c * 8);
        }
        CPA_ARRIVE(sb + 8);
    }

    float acc[8][4];
#pragma unroll
    for (int j = 0; j < 8; ++j)
#pragma unroll
        for (int q = 0; q < 4; ++q) acc[j][q] = 0.f;
    float m0 = -CUDART_INF_F, m1 = -CUDART_INF_F;
    float l0 = 0.f, l1 = 0.f;

    uint32_t aQ[4][4];
    bool qLoaded = false;

    const uint32_t q_addr0 = sQ + (uint32_t)(16 * w + (lane & 15)) * 144
                                + ((lane >> 4) << 4);
    const int kq = lane & 7;
    const int kg16 = (lane >> 4) << 3;
    const int kg8  = ((lane >> 3) & 1) << 3;
    const uint32_t onesB[2] = {H2_ONES, H2_ONES};

    for (int kb = 0; kb < NKB; ++kb) {
        const int cur = kb % NSTG;
        MBAR_WAIT(sb + 8 * cur, (kb / NSTG) & 1);

        if (!qLoaded) {
#pragma unroll
            for (int s = 0; s < 4; ++s) ldsm4(q_addr0 + s * 32, aQ[s]);
            qLoaded = true;
        }

        const uint32_t sKst = sKV + (uint32_t)cur * KVSTG;
        const uint32_t sVst = sKst + 64 * 144;

        float sc[8][4];
#pragma unroll
        for (int j = 0; j < 8; ++j)
#pragma unroll
            for (int q = 0; q < 4; ++q) sc[j][q] = 0.f;

#pragma unroll
        for (int p = 0; p < 4; ++p) {
#pragma unroll
            for (int s = 0; s < 4; ++s) {
                uint32_t kf[4];
                ldsm4(sKst + (uint32_t)(16 * p + kg16 + kq) * 144
                           + (uint32_t)(16 * s + kg8) * 2, kf);
                mma_fp(sc[2 * p],     aQ[s], &kf[0]);
                mma_fp(sc[2 * p + 1], aQ[s], &kf[2]);
            }
        }

        if (kb + 2 < NKB) {
            const int kl = kb + 2;
            const int s2 = kl % NSTG;
            const int m = kl / NSTG;
            MBAR_WAIT(sb + 24 + 8 * s2, (m + 1) & 1);
            const uint32_t st = sKV + (uint32_t)s2 * KVSTG;
            const __half* Kp = Kg + (size_t)(kl * 64) * Ev;
            const __half* Vp = Vg + (size_t)(kl * 64) * Ev;
            for (int i = tid; i < 512; i += 256) {
                const int r = i >> 3, c = i & 7;
                CP_ASYNC16(st + r * 144 + c * 16, Kp + (size_t)r * Ev + c * 8);
                CP_ASYNC16(st + 64 * 144 + r * 144 + c * 16, Vp + (size_t)r * Ev + c * 8);
            }
            CPA_ARRIVE(sb + 8 * s2);
        }

        float mx0 = -CUDART_INF_F, mx1 = -CUDART_INF_F;
#pragma unroll
        for (int j = 0; j < 8; ++j) {
            mx0 = fmaxf(mx0, fmaxf(sc[j][0], sc[j][1]));
            mx1 = fmaxf(mx1, fmaxf(sc[j][2], sc[j][3]));
        }
        mx0 = fmaxf(mx0, __shfl_xor_sync(0xffffffffu, mx0, 1));
        mx0 = fmaxf(mx0, __shfl_xor_sync(0xffffffffu, mx0, 2));
        mx1 = fmaxf(mx1, __shfl_xor_sync(0xffffffffu, mx1, 1));
        mx1 = fmaxf(mx1, __shfl_xor_sync(0xffffffffu, mx1, 2));

        const float mn0 = fmaxf(m0, mx0);
        const float mn1 = fmaxf(m1, mx1);
        const float co0 = ex2f(m0 - mn0);
        const float co1 = ex2f(m1 - mn1);
        m0 = mn0; m1 = mn1;

        uint32_t ph01[8], ph23[8];
#pragma unroll
        for (int j = 0; j < 8; ++j) {
            ph01[j] = h2ex2(f2_to_h2u(sc[j][0] - mn0, sc[j][1] - mn0));
            ph23[j] = h2ex2(f2_to_h2u(sc[j][2] - mn1, sc[j][3] - mn1));
        }

#pragma unroll
        for (int j = 0; j < 8; ++j) {
            acc[j][0] *= co0; acc[j][1] *= co0;
            acc[j][2] *= co1; acc[j][3] *= co1;
        }

        float sl[4] = {0.f, 0.f, 0.f, 0.f};
#pragma unroll
        for (int s = 0; s < 4; ++s) {
            const uint32_t aP[4] = {ph01[2 * s], ph23[2 * s],
                                    ph01[2 * s + 1], ph23[2 * s + 1]};
#pragma unroll
            for (int dp = 0; dp < 4; ++dp) {
                uint32_t vf[4];
                ldsm4t(sVst + (uint32_t)(16 * s + kg8 + kq) * 144
                            + (uint32_t)(16 * dp + kg16) * 2, vf);
                mma_fp(acc[2 * dp],     aP, &vf[0]);
                mma_fp(acc[2 * dp + 1], aP, &vf[2]);
            }
            mma_fp(sl, aP, onesB);
        }
        l0 = fmaf(sl[0], co0, sl[0]);
        l1 = fmaf(sl[2], co1, sl[2]);

        MBAR_ARRIVE(sb + 24 + 8 * cur);
    }

    const float inv0 = 1.f / l0;
    const float inv1 = 1.f / l1;
    const int row0 = q0 + 16 * w + (lane >> 2);
    const int colb = h * HDv + 2 * (lane & 3);
    __half* Ob = Of + (size_t)b * Sv * Ev;
#pragma unroll
    for (int j = 0; j < 8; ++j) {
        const int col = colb + 8 * j;
        const size_t i0 = (size_t)row0 * Ev + col;
        const size_t i1 = (size_t)(row0 + 8) * Ev + col;
        *reinterpret_cast<uint32_t*>(&Ob[i0]) =
            f2_to_h2u(acc[j][0] * inv0, acc[j][1] * inv0);
        *reinterpret_cast<uint32_t*>(&Ob[i1]) =
            f2_to_h2u(acc[j][2] * inv1, acc[j][3] * inv1);
    }
}

// ========================= launch ==========================================
extern "C" void kernel_launch(void* const* d_in, const int* in_sizes, int n_in,
                              void* d_out, int out_size)
{
    const float* x  = (const float*)d_in[0];
    const float* qw = (const float*)d_in[1];
    const float* kw = (const float*)d_in[2];
    const float* vw = (const float*)d_in[3];
    const float* ow = (const float*)d_in[4];
    const float* ob = (const float*)d_in[5];
    float* out = (float*)d_out;

    __half *Qh, *Kh, *Vh, *xf, *of, *wf;
    cudaGetSymbolAddress((void**)&Qh, g_Qh);
    cudaGetSymbolAddress((void**)&Kh, g_Kh);
    cudaGetSymbolAddress((void**)&Vh, g_Vh);
    cudaGetSymbolAddress((void**)&xf, g_xf);
    cudaGetSymbolAddress((void**)&of, g_of);
    cudaGetSymbolAddress((void**)&wf, g_wf);

    const int M = Bv * Sv;

    cvt_all_kernel<<<8192 + 4096, 256>>>(x, qw, kw, vw, ow, xf, wf);

    cudaFuncSetAttribute(gemm_qkv_kernel,
                         cudaFuncAttributeMaxDynamicSharedMemorySize, GEMM_SMEM);
    cudaFuncSetAttribute(gemm_out_kernel,
                         cudaFuncAttributeMaxDynamicSharedMemorySize, GEMM_SMEM);
    cudaFuncSetAttribute(attn_tc_kernel,
                         cudaFuncAttributeMaxDynamicSharedMemorySize, ATT_SMEM);

    gemm_qkv_kernel<<<dim3(Ev / 128, M / 128, 3), GTHREADS, GEMM_SMEM>>>(
        xf, wf, Qh, Kh, Vh);

    attn_tc_kernel<<<dim3(Bv * Hv, Sv / 128), 256, ATT_SMEM>>>(Qh, Kh, Vh, of);

    gemm_out_kernel<<<dim3(Ev / 128, M / 128), GTHREADS, GEMM_SMEM>>>(
        of, wf + 3 * (size_t)Ev * Ev, ob, out);
}

// round 13
// speedup vs baseline: 8.6056x; 1.0143x over previous
#include <cuda_runtime.h>
#include <cuda_fp16.h>
#include <math_constants.h>
#include <cstdint>

// Problem constants
#define Bv 4
#define Sv 2048
#define Ev 1024
#define Hv 16
#define HDv 64
#define NKB (Sv / 64)
#define ATT_SCALE 0.125f
#define LOG2E 1.4426950408889634f

// ========================= PTX helpers =====================================
__device__ __forceinline__ uint32_t smem_u32(const void* p) {
    uint32_t a;
    asm("{ .reg .u64 t; cvta.to.shared.u64 t, %1; cvt.u32.u64 %0, t; }"
        : "=r"(a) : "l"(p));
    return a;
}
#define CP_ASYNC16(sa, ga) \
    asm volatile("cp.async.cg.shared.global [%0], [%1], 16;" :: "r"(sa), "l"(ga))
#define CP_COMMIT()  asm volatile("cp.async.commit_group;" ::: "memory")
#define CP_WAIT(n)   asm volatile("cp.async.wait_group %0;" :: "n"(n) : "memory")

#define MBAR_INIT(addr, cnt) \
    asm volatile("mbarrier.init.shared.b64 [%0], %1;" :: "r"(addr), "r"((uint32_t)(cnt)) : "memory")
#define MBAR_ARRIVE(addr) \
    asm volatile("mbarrier.arrive.shared.b64 _, [%0];" :: "r"(addr) : "memory")
#define CPA_ARRIVE(addr) \
    asm volatile("cp.async.mbarrier.arrive.noinc.shared.b64 [%0];" :: "r"(addr) : "memory")
#define MBAR_WAIT(addr, ph) \
    asm volatile("{\n\t.reg .pred P;\n" \
                 "WL_%=:\n\t" \
                 "mbarrier.try_wait.parity.acquire.cta.shared::cta.b64 P, [%0], %1;\n\t" \
                 "@!P bra WL_%=;\n\t}" \
                 :: "r"(addr), "r"((uint32_t)(ph)) : "memory")

__device__ __forceinline__ void ldsm4(uint32_t addr, uint32_t r[4]) {
    asm volatile("ldmatrix.sync.aligned.m8n8.x4.shared.b16 {%0,%1,%2,%3}, [%4];"
                 : "=r"(r[0]), "=r"(r[1]), "=r"(r[2]), "=r"(r[3]) : "r"(addr));
}
__device__ __forceinline__ void ldsm4t(uint32_t addr, uint32_t r[4]) {
    asm volatile("ldmatrix.sync.aligned.m8n8.x4.trans.shared.b16 {%0,%1,%2,%3}, [%4];"
                 : "=r"(r[0]), "=r"(r[1]), "=r"(r[2]), "=r"(r[3]) : "r"(addr));
}
__device__ __forceinline__ void mma_fp(float c[4], const uint32_t a[4],
                                       const uint32_t b[2]) {
    asm volatile(
        "mma.sync.aligned.m16n8k16.row.col.f32.f16.f16.f32 "
        "{%0,%1,%2,%3}, {%4,%5,%6,%7}, {%8,%9}, {%0,%1,%2,%3};"
        : "+f"(c[0]), "+f"(c[1]), "+f"(c[2]), "+f"(c[3])
        : "r"(a[0]), "r"(a[1]), "r"(a[2]), "r"(a[3]), "r"(b[0]), "r"(b[1]));
}
__device__ __forceinline__ uint32_t f2_to_h2u(float lo, float hi) {
    uint32_t r;
    asm("cvt.rn.f16x2.f32 %0, %1, %2;" : "=r"(r) : "f"(hi), "f"(lo));
    return r;
}
__device__ __forceinline__ float ex2f(float x) {
    float r; asm("ex2.approx.f32 %0, %1;" : "=f"(r) : "f"(x)); return r;
}
__device__ __forceinline__ uint32_t h2ex2(uint32_t a) {
    uint32_t r; asm("ex2.approx.f16x2 %0, %1;" : "=r"(r) : "r"(a)); return r;
}

// ========================= static device scratch ===========================
__device__ __half g_Qh[(size_t)Bv * Sv * Ev];
__device__ __half g_Kh[(size_t)Bv * Sv * Ev];
__device__ __half g_Vh[(size_t)Bv * Sv * Ev];
__device__ __half g_xf[(size_t)Bv * Sv * Ev];
__device__ __half g_of[(size_t)Bv * Sv * Ev];
__device__ __half g_wf[4][(size_t)Ev * Ev];

// ========================= fused fp32 -> fp16 convert ======================
__global__ void cvt_all_kernel(const float* __restrict__ x,
                               const float* __restrict__ w0,
                               const float* __restrict__ w1,
                               const float* __restrict__ w2,
                               const float* __restrict__ w3,
                               __half* __restrict__ xf, __half* __restrict__ wf)
{
    const int bid = blockIdx.x;
    const float* src;
    __half* dst;
    int i;
    if (bid < 8192) {
        src = x; dst = xf;
        i = bid * 256 + threadIdx.x;
    } else {
        const int wb = bid - 8192;
        const int wi = wb >> 10;
        const float* ws[4] = {w0, w1, w2, w3};
        src = ws[wi];
        dst = wf + (size_t)wi * Ev * Ev;
        i = (wb & 1023) * 256 + threadIdx.x;
    }
    float4 v = reinterpret_cast<const float4*>(src)[i];
    uint32_t* dp = reinterpret_cast<uint32_t*>(dst) + 2 * i;
    dp[0] = f2_to_h2u(v.x, v.y);
    dp[1] = f2_to_h2u(v.z, v.w);
}

// ========================= shared GEMM config ==============================
// 128x128 CTA tile, 4 warps of 64x64, 128 threads. BK=64, 3-stage pipeline.
#define BK 64
#define ROWB 144                      // 128 data bytes + 16 pad
#define TILE_BYTES (128 * ROWB)       // 18432
#define NCHW (Ev / BK)                // 16
#define STAGE_S (2 * TILE_BYTES)      // 36864
#define NGSTG 3
#define GEMM_SMEM (NGSTG * STAGE_S)   // 110592
#define GTHREADS 128

__device__ __forceinline__ void load_stage_s(
    uint32_t sbase, int stage, int kc,
    const __half* A, const __half* B, int m0, int n0, int tid)
{
    const uint32_t st = sbase + stage * STAGE_S;
    const __half* srcs[2] = {A, B};
    const int row0[2] = {m0, n0};
#pragma unroll
    for (int t = 0; t < 2; ++t) {
#pragma unroll
        for (int p = 0; p < 8; ++p) {
            const int i = p * GTHREADS + tid;     // 0..1023
            const int r = i >> 3;
            const int c = i & 7;
            const __half* g =
                srcs[t] + (size_t)(row0[t] + r) * Ev + kc * BK + c * 8;
            CP_ASYNC16(st + t * TILE_BYTES + r * ROWB + c * 16, g);
        }
    }
}

// 3-stage mainloop, BK=64, 64x64 warp tiles: per ks 8 ldsm feed 32 MMA.
#define GEMM_MAINLOOP(A_, B_)                                              \
    load_stage_s(sb, 0, 0, A_, B_, m0, n0, tid); CP_COMMIT();              \
    load_stage_s(sb, 1, 1, A_, B_, m0, n0, tid); CP_COMMIT();              \
    CP_WAIT(1);                                                            \
    __syncthreads();                                                       \
    for (int c = 0; c < NCHW; ++c) {                                       \
        const int s = (c % NGSTG);                                         \
        if (c + 2 < NCHW) {                                                \
            load_stage_s(sb, (c + 2) % NGSTG, c + 2, A_, B_, m0, n0, tid); \
            CP_COMMIT();                                                   \
        } else { CP_COMMIT(); }                                            \
        const uint32_t stA = sb + s * STAGE_S;                             \
        const uint32_t stB = stA + TILE_BYTES;                             \
        _Pragma("unroll")                                                  \
        for (int ks = 0; ks < 4; ++ks) {                                   \
            const uint32_t kofs = ks * 32;                                 \
            uint32_t a[4][4], b[4][4];                                     \
            _Pragma("unroll")                                              \
            for (int p = 0; p < 4; ++p)                                    \
                ldsm4(stA + (uint32_t)(arow + p * 16) * ROWB + kofs + acol16, a[p]); \
            _Pragma("unroll")                                              \
            for (int p = 0; p < 4; ++p)                                    \
                ldsm4(stB + (uint32_t)(nrow + p * 16) * ROWB + kofs + bcol16, b[p]); \
            _Pragma("unroll")                                              \
            for (int mt = 0; mt < 4; ++mt)                                 \
                _Pragma("unroll")                                          \
                for (int nt = 0; nt < 8; ++nt)                             \
                    mma_fp(acc[mt][nt], a[mt], &b[nt >> 1][(nt & 1) * 2]); \
        }                                                                  \
        CP_WAIT(1);                                                        \
        __syncthreads();                                                   \
    }

// ========================= fused QKV GEMM (single-product fp16) ============
__global__ __launch_bounds__(GTHREADS, 2)
void gemm_qkv_kernel(const __half* __restrict__ A, const __half* __restrict__ W,
                     __half* __restrict__ Qo, __half* __restrict__ Ko,
                     __half* __restrict__ Vo)
{
    extern __shared__ __align__(128) char smem[];
    const uint32_t sb = smem_u32(smem);
    const int tid = threadIdx.x;
    const int wid = tid >> 5, lane = tid & 31;
    const int warp_m = wid & 1, warp_n = wid >> 1;
    const int m0 = blockIdx.y << 7;
    const int n0 = blockIdx.x << 7;
    const int z  = blockIdx.z;

    const __half* B = W + (size_t)z * Ev * Ev;
    __half* Out = (z == 0) ? Qo : ((z == 1) ? Ko : Vo);
    const float premul = (z == 0) ? (ATT_SCALE * LOG2E) : 1.0f;

    float acc[4][8][4];
#pragma unroll
    for (int mt = 0; mt < 4; ++mt)
#pragma unroll
        for (int nt = 0; nt < 8; ++nt)
#pragma unroll
            for (int q = 0; q < 4; ++q) acc[mt][nt][q] = 0.f;

    const int arow = warp_m * 64 + (lane & 15);
    const uint32_t acol16 = (uint32_t)((lane >> 4) << 4);
    const int nrow = warp_n * 64 + (((lane >> 4) & 1) << 3) + (lane & 7);
    const uint32_t bcol16 = (uint32_t)(((lane >> 3) & 1) << 4);

    GEMM_MAINLOOP(A, B)

    const int tr = lane >> 2;
    const int tc = (lane & 3) * 2;
    const int mb = m0 + warp_m * 64;
    const int nb = n0 + warp_n * 64;
#pragma unroll
    for (int mt = 0; mt < 4; ++mt) {
#pragma unroll
        for (int nt = 0; nt < 8; ++nt) {
            const int col = nb + nt * 8 + tc;
            const size_t r0 = (size_t)(mb + mt * 16 + tr) * Ev + col;
            const size_t r1 = (size_t)(mb + mt * 16 + tr + 8) * Ev + col;
            *reinterpret_cast<uint32_t*>(&Out[r0]) =
                f2_to_h2u(acc[mt][nt][0] * premul, acc[mt][nt][1] * premul);
            *reinterpret_cast<uint32_t*>(&Out[r1]) =
                f2_to_h2u(acc[mt][nt][2] * premul, acc[mt][nt][3] * premul);
        }
    }
}

// ========================= out-proj GEMM (single-product, fp32+bias) =======
__global__ __launch_bounds__(GTHREADS, 2)
void gemm_out_kernel(const __half* __restrict__ A, const __half* __restrict__ B,
                     const float* __restrict__ bias, float* __restrict__ C)
{
    extern __shared__ __align__(128) char smem[];
    const uint32_t sb = smem_u32(smem);
    const int tid = threadIdx.x;
    const int wid = tid >> 5, lane = tid & 31;
    const int warp_m = wid & 1, warp_n = wid >> 1;
    const int m0 = blockIdx.y << 7;
    const int n0 = blockIdx.x << 7;

    float acc[4][8][4];
#pragma unroll
    for (int mt = 0; mt < 4; ++mt)
#pragma unroll
        for (int nt = 0; nt < 8; ++nt)
#pragma unroll
            for (int q = 0; q < 4; ++q) acc[mt][nt][q] = 0.f;

    const int arow = warp_m * 64 + (lane & 15);
    const uint32_t acol16 = (uint32_t)((lane >> 4) << 4);
    const int nrow = warp_n * 64 + (((lane >> 4) & 1) << 3) + (lane & 7);
    const uint32_t bcol16 = (uint32_t)(((lane >> 3) & 1) << 4);

    GEMM_MAINLOOP(A, B)

    const int tr = lane >> 2;
    const int tc = (lane & 3) * 2;
    const int mb = m0 + warp_m * 64;
    const int nb = n0 + warp_n * 64;
#pragma unroll
    for (int mt = 0; mt < 4; ++mt) {
#pragma unroll
        for (int nt = 0; nt < 8; ++nt) {
            const int col = nb + nt * 8 + tc;
            const float b0 = bias[col], b1 = bias[col + 1];
            const size_t r0 = (size_t)(mb + mt * 16 + tr) * Ev + col;
            const size_t r1 = (size_t)(mb + mt * 16 + tr + 8) * Ev + col;
            float2 v0 = {acc[mt][nt][0] + b0, acc[mt][nt][1] + b1};
            float2 v1 = {acc[mt][nt][2] + b0, acc[mt][nt][3] + b1};
            *reinterpret_cast<float2*>(&C[r0]) = v0;
            *reinterpret_cast<float2*>(&C[r1]) = v1;
        }
    }
}

// ========================= tensor-core flash attention =====================
// fp16, log2-domain scores. ex2.approx.f16x2 P, ones-column row-sum MMA.
// Skip correction-scale when running max unchanged (exact: corr==1).
// Buggy l preserved. 3-stage mbarrier K/V pipeline. Output fp16.
#define NSTG 3
#define KVSTG (2 * 64 * 144)
#define ATT_SMEM (64 + 128 * 144 + NSTG * KVSTG)
#define H2_ONES 0x3C003C00u

__global__ __launch_bounds__(256, 2)
void attn_tc_kernel(const __half* __restrict__ Q, const __half* __restrict__ K,
                    const __half* __restrict__ V, __half* __restrict__ Of)
{
    extern __shared__ __align__(128) char smem[];
    const uint32_t sb = smem_u32(smem);
    const uint32_t sQ  = sb + 64;
    const uint32_t sKV = sQ + 128 * 144;

    const int tid = threadIdx.x;
    const int w = tid >> 5, lane = tid & 31;
    const int b  = blockIdx.x >> 4;
    const int h  = blockIdx.x & 15;
    const int q0 = blockIdx.y << 7;

    const __half* Qg = Q + ((size_t)b * Sv + q0) * Ev + h * HDv;
    const __half* Kg = K + (size_t)b * Sv * Ev + h * HDv;
    const __half* Vg = V + (size_t)b * Sv * Ev + h * HDv;

    if (tid == 0) {
#pragma unroll
        for (int s = 0; s < NSTG; ++s) {
            MBAR_INIT(sb + 8 * s, 256);
            MBAR_INIT(sb + 24 + 8 * s, 256);
        }
    }
    __syncthreads();

    for (int i = tid; i < 1024; i += 256) {
        const int r = i >> 3, c = i & 7;
        CP_ASYNC16(sQ + r * 144 + c * 16, Qg + (size_t)r * Ev + c * 8);
    }
    {
        const uint32_t st0 = sKV;
        for (int i = tid; i < 512; i += 256) {
            const int r = i >> 3, c = i & 7;
            CP_ASYNC16(st0 + r * 144 + c * 16, Kg + (size_t)r * Ev + c * 8);
            CP_ASYNC16(st0 + 64 * 144 + r * 144 + c * 16, Vg + (size_t)r * Ev + c * 8);
        }
        CPA_ARRIVE(sb + 0);
        const uint32_t st1 = sKV + KVSTG;
        const __half* Kp = Kg + (size_t)64 * Ev;
        const __half* Vp = Vg + (size_t)64 * Ev;
        for (int i = tid; i < 512; i += 256) {
            const int r = i >> 3, c = i & 7;
            CP_ASYNC16(st1 + r * 144 + c * 16, Kp + (size_t)r * Ev + c * 8);
            CP_ASYNC16(st1 + 64 * 144 + r * 144 + c * 16, Vp + (size_t)r * Ev + c * 8);
        }
        CPA_ARRIVE(sb + 8);
    }

    float acc[8][4];
#pragma unroll
    for (int j = 0; j < 8; ++j)
#pragma unroll
        for (int q = 0; q < 4; ++q) acc[j][q] = 0.f;
    float m0 = -CUDART_INF_F, m1 = -CUDART_INF_F;
    float l0 = 0.f, l1 = 0.f;

    uint32_t aQ[4][4];
    bool qLoaded = false;

    const uint32_t q_addr0 = sQ + (uint32_t)(16 * w + (lane & 15)) * 144
                                + ((lane >> 4) << 4);
    const int kq = lane & 7;
    const int kg16 = (lane >> 4) << 3;
    const int kg8  = ((lane >> 3) & 1) << 3;
    const uint32_t onesB[2] = {H2_ONES, H2_ONES};

    for (int kb = 0; kb < NKB; ++kb) {
        const int cur = kb % NSTG;
        MBAR_WAIT(sb + 8 * cur, (kb / NSTG) & 1);

        if (!qLoaded) {
#pragma unroll
            for (int s = 0; s < 4; ++s) ldsm4(q_addr0 + s * 32, aQ[s]);
            qLoaded = true;
        }

        const uint32_t sKst = sKV + (uint32_t)cur * KVSTG;
        const uint32_t sVst = sKst + 64 * 144;

        float sc[8][4];
#pragma unroll
        for (int j = 0; j < 8; ++j)
#pragma unroll
            for (int q = 0; q < 4; ++q) sc[j][q] = 0.f;

#pragma unroll
        for (int p = 0; p < 4; ++p) {
#pragma unroll
            for (int s = 0; s < 4; ++s) {
                uint32_t kf[4];
                ldsm4(sKst + (uint32_t)(16 * p + kg16 + kq) * 144
                           + (uint32_t)(16 * s + kg8) * 2, kf);
                mma_fp(sc[2 * p],     aQ[s], &kf[0]);
                mma_fp(sc[2 * p + 1], aQ[s], &kf[2]);
            }
        }

        if (kb + 2 < NKB) {
            const int kl = kb + 2;
            const int s2 = kl % NSTG;
            const int m = kl / NSTG;
            MBAR_WAIT(sb + 24 + 8 * s2, (m + 1) & 1);
            const uint32_t st = sKV + (uint32_t)s2 * KVSTG;
            const __half* Kp = Kg + (size_t)(kl * 64) * Ev;
            const __half* Vp = Vg + (size_t)(kl * 64) * Ev;
            for (int i = tid; i < 512; i += 256) {
                const int r = i >> 3, c = i & 7;
                CP_ASYNC16(st + r * 144 + c * 16, Kp + (size_t)r * Ev + c * 8);
                CP_ASYNC16(st + 64 * 144 + r * 144 + c * 16, Vp + (size_t)r * Ev + c * 8);
            }
            CPA_ARRIVE(sb + 8 * s2);
        }

        float mx0 = -CUDART_INF_F, mx1 = -CUDART_INF_F;
#pragma unroll
        for (int j = 0; j < 8; ++j) {
            mx0 = fmaxf(mx0, fmaxf(sc[j][0], sc[j][1]));
            mx1 = fmaxf(mx1, fmaxf(sc[j][2], sc[j][3]));
        }
        mx0 = fmaxf(mx0, __shfl_xor_sync(0xffffffffu, mx0, 1));
        mx0 = fmaxf(mx0, __shfl_xor_sync(0xffffffffu, mx0, 2));
        mx1 = fmaxf(mx1, __shfl_xor_sync(0xffffffffu, mx1, 1));
        mx1 = fmaxf(mx1, __shfl_xor_sync(0xffffffffu, mx1, 2));

        const float mn0 = fmaxf(m0, mx0);
        const float mn1 = fmaxf(m1, mx1);
        float co0 = 1.f, co1 = 1.f;
        const bool upd = (mn0 > m0) || (mn1 > m1);
        if (upd) {
            co0 = ex2f(m0 - mn0);
            co1 = ex2f(m1 - mn1);
#pragma unroll
            for (int j = 0; j < 8; ++j) {
                acc[j][0] *= co0; acc[j][1] *= co0;
                acc[j][2] *= co1; acc[j][3] *= co1;
            }
        }
        m0 = mn0; m1 = mn1;

        uint32_t ph01[8], ph23[8];
#pragma unroll
        for (int j = 0; j < 8; ++j) {
            ph01[j] = h2ex2(f2_to_h2u(sc[j][0] - mn0, sc[j][1] - mn0));
            ph23[j] = h2ex2(f2_to_h2u(sc[j][2] - mn1, sc[j][3] - mn1));
        }

        float sl[4] = {0.f, 0.f, 0.f, 0.f};
#pragma unroll
        for (int s = 0; s < 4; ++s) {
            const uint32_t aP[4] = {ph01[2 * s], ph23[2 * s],
                                    ph01[2 * s + 1], ph23[2 * s + 1]};
#pragma unroll
            for (int dp = 0; dp < 4; ++dp) {
                uint32_t vf[4];
                ldsm4t(sVst + (uint32_t)(16 * s + kg8 + kq) * 144
                            + (uint32_t)(16 * dp + kg16) * 2, vf);
                mma_fp(acc[2 * dp],     aP, &vf[0]);
                mma_fp(acc[2 * dp + 1], aP, &vf[2]);
            }
            mma_fp(sl, aP, onesB);
        }
        l0 = fmaf(sl[0], co0, sl[0]);
        l1 = fmaf(sl[2], co1, sl[2]);

        MBAR_ARRIVE(sb + 24 + 8 * cur);
    }

    const float inv0 = 1.f / l0;
    const float inv1 = 1.f / l1;
    const int row0 = q0 + 16 * w + (lane >> 2);
    const int colb = h * HDv + 2 * (lane & 3);
    __half* Ob = Of + (size_t)b * Sv * Ev;
#pragma unroll
    for (int j = 0; j < 8; ++j) {
        const int col = colb + 8 * j;
        const size_t i0 = (size_t)row0 * Ev + col;
        const size_t i1 = (size_t)(row0 + 8) * Ev + col;
        *reinterpret_cast<uint32_t*>(&Ob[i0]) =
            f2_to_h2u(acc[j][0] * inv0, acc[j][1] * inv0);
        *reinterpret_cast<uint32_t*>(&Ob[i1]) =
            f2_to_h2u(acc[j][2] * inv1, acc[j][3] * inv1);
    }
}

// ========================= launch ==========================================
extern "C" void kernel_launch(void* const* d_in, const int* in_sizes, int n_in,
                              void* d_out, int out_size)
{
    const float* x  = (const float*)d_in[0];
    const float* qw = (const float*)d_in[1];
    const float* kw = (const float*)d_in[2];
    const float* vw = (const float*)d_in[3];
    const float* ow = (const float*)d_in[4];
    const float* ob = (const float*)d_in[5];
    float* out = (float*)d_out;

    __half *Qh, *Kh, *Vh, *xf, *of, *wf;
    cudaGetSymbolAddress((void**)&Qh, g_Qh);
    cudaGetSymbolAddress((void**)&Kh, g_Kh);
    cudaGetSymbolAddress((void**)&Vh, g_Vh);
    cudaGetSymbolAddress((void**)&xf, g_xf);
    cudaGetSymbolAddress((void**)&of, g_of);
    cudaGetSymbolAddress((void**)&wf, g_wf);

    const int M = Bv * Sv;

    cvt_all_kernel<<<8192 + 4096, 256>>>(x, qw, kw, vw, ow, xf, wf);

    cudaFuncSetAttribute(gemm_qkv_kernel,
                         cudaFuncAttributeMaxDynamicSharedMemorySize, GEMM_SMEM);
    cudaFuncSetAttribute(gemm_out_kernel,
                         cudaFuncAttributeMaxDynamicSharedMemorySize, GEMM_SMEM);
    cudaFuncSetAttribute(attn_tc_kernel,
                         cudaFuncAttributeMaxDynamicSharedMemorySize, ATT_SMEM);

    gemm_qkv_kernel<<<dim3(Ev / 128, M / 128, 3), GTHREADS, GEMM_SMEM>>>(
        xf, wf, Qh, Kh, Vh);

    attn_tc_kernel<<<dim3(Bv * Hv, Sv / 128), 256, ATT_SMEM>>>(Qh, Kh, Vh, of);

    gemm_out_kernel<<<dim3(Ev / 128, M / 128), GTHREADS, GEMM_SMEM>>>(
        of, wf + 3 * (size_t)Ev * Ev, ob, out);
}